// round 9
// baseline (speedup 1.0000x reference)
#include <cuda_runtime.h>
#include <math.h>

// ---------------- problem constants ----------------
#define BATCH   2
#define TSEQ    1024
#define DM      1024
#define NHEAD   16
#define HD      64
#define NLAYER  12
#define DFF     2730
#define CAP     128
#define NSLOTS  128
#define TOPK    8
#define NTOK    (BATCH*TSEQ)      // 2048

// ---------------- scratch (device globals; no allocation allowed) ----------------
__device__ float g_x    [NTOK*DM];
__device__ float g_xn   [NTOK*DM];
__device__ float g_qkv  [NTOK*3*DM];
__device__ float g_attn [NTOK*DM];
__device__ float g_ff1  [NTOK*DFF];
__device__ float g_ff2  [NTOK*DFF];
__device__ float g_retr [NTOK*DM];
__device__ float g_retrp[NTOK*DM];
__device__ float g_sim  [NTOK*NSLOTS];
__device__ float g_g1   [NTOK*512];
__device__ float g_h1   [NTOK*2048];
__device__ float g_xs   [BATCH*CAP*DM];
__device__ float g_scores[NTOK];
__device__ int   g_idx  [BATCH*CAP];

// ---------------- helpers ----------------
__device__ __forceinline__ float warpSum(float v){
    #pragma unroll
    for (int o=16;o>0;o>>=1) v += __shfl_xor_sync(0xffffffffu, v, o);
    return v;
}
__device__ __forceinline__ float warpMax(float v){
    #pragma unroll
    for (int o=16;o>0;o>>=1) v = fmaxf(v, __shfl_xor_sync(0xffffffffu, v, o));
    return v;
}
__device__ __forceinline__ float blockSum(float v, float* red){
    int lane = threadIdx.x & 31, w = threadIdx.x >> 5, nw = blockDim.x >> 5;
    v = warpSum(v);
    if (lane == 0) red[w] = v;
    __syncthreads();
    float r = (w == 0 && lane < nw) ? red[lane] : 0.f;
    if (w == 0) r = warpSum(r);
    if (threadIdx.x == 0) red[0] = r;
    __syncthreads();
    float out = red[0];
    __syncthreads();
    return out;
}
__device__ __forceinline__ float blockMax(float v, float* red){
    int lane = threadIdx.x & 31, w = threadIdx.x >> 5, nw = blockDim.x >> 5;
    v = warpMax(v);
    if (lane == 0) red[w] = v;
    __syncthreads();
    float r = (w == 0 && lane < nw) ? red[lane] : -INFINITY;
    if (w == 0) r = warpMax(r);
    if (threadIdx.x == 0) red[0] = r;
    __syncthreads();
    float out = red[0];
    __syncthreads();
    return out;
}
__device__ __forceinline__ float gelu_f(float v){
    return 0.5f * v * (1.f + erff(v * 0.70710678118654752f));
}
__device__ __forceinline__ float silu_f(float v){
    return v / (1.f + expf(-v));
}

// ---------------- tf32 split + mma ----------------
__device__ __forceinline__ void split_tf32(float v, unsigned &hi, unsigned &lo){
    unsigned h;
    asm("cvt.rna.tf32.f32 %0, %1;" : "=r"(h) : "f"(v));
    float lf = v - __uint_as_float(h);
    unsigned l;
    asm("cvt.rna.tf32.f32 %0, %1;" : "=r"(l) : "f"(lf));
    hi = h; lo = l;
}
__device__ __forceinline__ void mma8(float* c, const unsigned* a, const unsigned* b){
    asm volatile(
        "mma.sync.aligned.m16n8k8.row.col.f32.tf32.tf32.f32 "
        "{%0,%1,%2,%3}, {%4,%5,%6,%7}, {%8,%9}, {%0,%1,%2,%3};"
        : "+f"(c[0]), "+f"(c[1]), "+f"(c[2]), "+f"(c[3])
        : "r"(a[0]), "r"(a[1]), "r"(a[2]), "r"(a[3]), "r"(b[0]), "r"(b[1]));
}

// ---------------- tensor-core GEMM: C[M,N] = epilogue(A[M,K] @ B[N,K]^T) ----------------
// 3xTF32: fp32-equivalent accuracy via hi/lo decomposition.
// EP: 0 store, 1 C=res+acc, 2 C=gelu(acc), 3 C=res+acc+bias[n], 4 C=silu(res)*acc
#define EP_STORE    0
#define EP_ADD      1
#define EP_GELU     2
#define EP_ADD_BIAS 3
#define EP_SILU_MUL 4

template<int EP>
__global__ __launch_bounds__(256)
void tgemm_abt(float* __restrict__ C, const float* __restrict__ A,
               const float* __restrict__ B, int M, int N, int K,
               int lda, int ldb, int ldc,
               const float* __restrict__ res, int ldres,
               const float* __restrict__ bias)
{
    // smem stride 136: 136 % 32 == 8 -> fragment LDS conflict-free
    __shared__ float As[16][136];
    __shared__ float Bs[16][136];
    const int bm = blockIdx.y * 128, bn = blockIdx.x * 128;
    const int tid  = threadIdx.x;
    const int warp = tid >> 5, lane = tid & 31;
    const int wm = (warp & 1) * 64;      // 2 warps along M
    const int wn = (warp >> 1) * 32;     // 4 warps along N
    const int g  = lane >> 2, tg = lane & 3;
    // float4 is only legal when the row stride keeps 16B alignment (lda%4==0).
    const bool a4 = ((lda & 3) == 0);
    const bool b4 = ((ldb & 3) == 0);

    float acc[4][4][4];
    #pragma unroll
    for (int mi = 0; mi < 4; mi++)
        #pragma unroll
        for (int ni = 0; ni < 4; ni++)
            #pragma unroll
            for (int cc = 0; cc < 4; cc++) acc[mi][ni][cc] = 0.f;

    for (int k0 = 0; k0 < K; k0 += 16) {
        // global -> smem (128 rows x 16 k per matrix, 4 floats along K per thread)
        #pragma unroll
        for (int i = 0; i < 2; i++) {
            int e = tid + i * 256;             // 0..511
            int row = e >> 2, vq = e & 3;
            int gk = k0 + vq * 4;
            float4 av = make_float4(0.f, 0.f, 0.f, 0.f);
            int gm = bm + row;
            if (gm < M) {
                const float* ap = A + (size_t)gm * lda + gk;
                if (a4 && gk + 3 < K) av = *(const float4*)ap;
                else {
                    if (gk + 0 < K) av.x = ap[0];
                    if (gk + 1 < K) av.y = ap[1];
                    if (gk + 2 < K) av.z = ap[2];
                    if (gk + 3 < K) av.w = ap[3];
                }
            }
            As[vq * 4 + 0][row] = av.x;
            As[vq * 4 + 1][row] = av.y;
            As[vq * 4 + 2][row] = av.z;
            As[vq * 4 + 3][row] = av.w;

            float4 bv = make_float4(0.f, 0.f, 0.f, 0.f);
            int gn = bn + row;
            if (gn < N) {
                const float* bp = B + (size_t)gn * ldb + gk;
                if (b4 && gk + 3 < K) bv = *(const float4*)bp;
                else {
                    if (gk + 0 < K) bv.x = bp[0];
                    if (gk + 1 < K) bv.y = bp[1];
                    if (gk + 2 < K) bv.z = bp[2];
                    if (gk + 3 < K) bv.w = bp[3];
                }
            }
            Bs[vq * 4 + 0][row] = bv.x;
            Bs[vq * 4 + 1][row] = bv.y;
            Bs[vq * 4 + 2][row] = bv.z;
            Bs[vq * 4 + 3][row] = bv.w;
        }
        __syncthreads();

        #pragma unroll
        for (int ks = 0; ks < 16; ks += 8) {
            unsigned bhi[4][2], blo[4][2];
            #pragma unroll
            for (int ni = 0; ni < 4; ni++) {
                int col = wn + ni * 8 + g;
                split_tf32(Bs[ks + tg][col],     bhi[ni][0], blo[ni][0]);
                split_tf32(Bs[ks + tg + 4][col], bhi[ni][1], blo[ni][1]);
            }
            unsigned ahi[4][4], alo[4][4];
            #pragma unroll
            for (int mi = 0; mi < 4; mi++) {
                int r = wm + mi * 16 + g;
                split_tf32(As[ks + tg][r],         ahi[mi][0], alo[mi][0]);
                split_tf32(As[ks + tg][r + 8],     ahi[mi][1], alo[mi][1]);
                split_tf32(As[ks + tg + 4][r],     ahi[mi][2], alo[mi][2]);
                split_tf32(As[ks + tg + 4][r + 8], ahi[mi][3], alo[mi][3]);
            }
            #pragma unroll
            for (int mi = 0; mi < 4; mi++)
                #pragma unroll
                for (int ni = 0; ni < 4; ni++) {
                    mma8(acc[mi][ni], ahi[mi], bhi[ni]);
                    mma8(acc[mi][ni], ahi[mi], blo[ni]);
                    mma8(acc[mi][ni], alo[mi], bhi[ni]);
                }
        }
        __syncthreads();
    }

    // epilogue
    #pragma unroll
    for (int mi = 0; mi < 4; mi++) {
        int row0 = bm + wm + mi * 16 + g;
        #pragma unroll
        for (int ni = 0; ni < 4; ni++) {
            int col0 = bn + wn + ni * 8 + tg * 2;
            #pragma unroll
            for (int cc = 0; cc < 4; cc++) {
                int gm = row0 + (cc >> 1) * 8;
                int gn = col0 + (cc & 1);
                if (gm < M && gn < N) {
                    float v = acc[mi][ni][cc];
                    if (EP == EP_ADD)           v += res[(size_t)gm * ldres + gn];
                    else if (EP == EP_GELU)     v = gelu_f(v);
                    else if (EP == EP_ADD_BIAS) v += res[(size_t)gm * ldres + gn] + bias[gn];
                    else if (EP == EP_SILU_MUL) v *= silu_f(res[(size_t)gm * ldres + gn]);
                    C[(size_t)gm * ldc + gn] = v;
                }
            }
        }
    }
}

// ---------------- embed + positional ----------------
__global__ void embed_kernel(float* __restrict__ x, const int* __restrict__ ids,
                             const float* __restrict__ emb, const float* __restrict__ pos)
{
    int row = blockIdx.x;          // b*T + t
    int t   = row & (TSEQ - 1);
    int id  = ids[row];
    int tid = threadIdx.x;
    #pragma unroll
    for (int i = 0; i < 4; i++) {
        int d = tid + i * 256;
        x[(size_t)row * DM + d] = emb[(size_t)id * DM + d] + pos[(size_t)t * DM + d];
    }
}

// ---------------- rmsnorm ----------------
__global__ void rms_kernel(float* __restrict__ y, const float* __restrict__ x,
                           const float* __restrict__ w)
{
    __shared__ float red[8];
    int row = blockIdx.x, tid = threadIdx.x;
    const float* xr = x + (size_t)row * DM;
    float s = 0.f;
    #pragma unroll
    for (int i = 0; i < 4; i++) { float v = xr[tid + i * 256]; s = fmaf(v, v, s); }
    s = blockSum(s, red);
    float r = rsqrtf(s * (1.f / DM) + 1e-6f);
    #pragma unroll
    for (int i = 0; i < 4; i++) {
        int d = tid + i * 256;
        y[(size_t)row * DM + d] = xr[d] * r * w[d];
    }
}

// ---------------- attention: one block per (query t, head h, batch b) ----------------
__global__ void attn_kernel(const float* __restrict__ qkv, float* __restrict__ out, int S)
{
    const int t = blockIdx.x, h = blockIdx.y, b = blockIdx.z;
    const int tid = threadIdx.x;   // 128 threads
    __shared__ float qsh[HD];
    __shared__ float sc[TSEQ];
    __shared__ float red[8];
    __shared__ float obuf[HD];
    const float* base = qkv + (size_t)b * S * (3 * DM);
    if (tid < HD) qsh[tid] = base[(size_t)t * (3 * DM) + h * HD + tid];
    __syncthreads();

    float lmax = -INFINITY;
    for (int j = tid; j <= t; j += 128) {
        const float* kr = base + (size_t)j * (3 * DM) + DM + h * HD;
        float s = 0.f;
        #pragma unroll
        for (int d = 0; d < HD; d++) s = fmaf(qsh[d], kr[d], s);
        s *= 0.125f;                 // 1/sqrt(64)
        sc[j] = s;
        lmax = fmaxf(lmax, s);
    }
    float m = blockMax(lmax, red);
    float lsum = 0.f;
    for (int j = tid; j <= t; j += 128) {
        float p = expf(sc[j] - m);
        sc[j] = p;
        lsum += p;
    }
    float ssum = blockSum(lsum, red);
    float inv = 1.f / ssum;

    const int d = tid & 63, half = tid >> 6;
    const float* vb = base + 2 * DM + h * HD + d;
    float o = 0.f;
    for (int j = half; j <= t; j += 2)
        o = fmaf(sc[j], vb[(size_t)j * (3 * DM)], o);
    if (half == 1) obuf[d] = o;
    __syncthreads();
    if (half == 0)
        out[((size_t)(b * S + t)) * DM + h * HD + d] = (o + obuf[d]) * inv;
}

// ---------------- MoD: router scores ----------------
__global__ void score_kernel(float* __restrict__ scores, const float* __restrict__ x,
                             const float* __restrict__ r)
{
    __shared__ float red[8];
    int row = blockIdx.x, tid = threadIdx.x;
    const float* xr = x + (size_t)row * DM;
    float s = 0.f;
    #pragma unroll
    for (int i = 0; i < 4; i++) { int d = tid + i * 256; s = fmaf(xr[d], r[d], s); }
    s = blockSum(s, red);
    if (tid == 0) scores[row] = s;
}

// ---------------- MoD: exact top-128 descending (bitonic sort, tie = smaller idx) ----------------
__global__ void topk_sort_kernel(int* __restrict__ idx, const float* __restrict__ scores)
{
    int b = blockIdx.x, tid = threadIdx.x;     // 1024 threads
    __shared__ float s[TSEQ];
    __shared__ int   si[TSEQ];
    s[tid]  = scores[b * TSEQ + tid];
    si[tid] = tid;
    __syncthreads();
    for (int k = 2; k <= TSEQ; k <<= 1) {
        for (int j = k >> 1; j > 0; j >>= 1) {
            int ixj = tid ^ j;
            if (ixj > tid) {
                bool desc = ((tid & k) == 0);
                float s1 = s[tid], s2 = s[ixj];
                int   i1 = si[tid], i2 = si[ixj];
                bool firstBetter = (s1 > s2) || (s1 == s2 && i1 < i2);
                if (desc != firstBetter) {
                    s[tid] = s2; s[ixj] = s1;
                    si[tid] = i2; si[ixj] = i1;
                }
            }
            __syncthreads();
        }
    }
    if (tid < CAP) idx[b * CAP + tid] = si[tid];
}

__global__ void gather_kernel(float* __restrict__ xs, const float* __restrict__ x,
                              const int* __restrict__ idx)
{
    int row = blockIdx.x;            // b*CAP + j
    int b = row >> 7;
    int src = b * TSEQ + idx[row];
    int tid = threadIdx.x;
    #pragma unroll
    for (int i = 0; i < 4; i++) {
        int d = tid + i * 256;
        xs[(size_t)row * DM + d] = x[(size_t)src * DM + d];
    }
}
__global__ void scatter_kernel(float* __restrict__ x, const float* __restrict__ xs,
                               const int* __restrict__ idx)
{
    int row = blockIdx.x;
    int b = row >> 7;
    int dst = b * TSEQ + idx[row];
    int tid = threadIdx.x;
    #pragma unroll
    for (int i = 0; i < 4; i++) {
        int d = tid + i * 256;
        x[(size_t)dst * DM + d] = xs[(size_t)row * DM + d];
    }
}

// ---------------- memory: top-8 + softmax + weighted value gather ----------------
__global__ void memtopk_kernel(float* __restrict__ outp, const float* __restrict__ sim,
                               const float* __restrict__ mem_values)
{
    int row = blockIdx.x, tid = threadIdx.x;   // 128 threads
    __shared__ float sv[NSLOTS];
    __shared__ float av[NSLOTS];
    __shared__ int   ai[NSLOTS];
    __shared__ float wk[TOPK];
    __shared__ int   ik[TOPK];
    sv[tid] = sim[(size_t)row * NSLOTS + tid] * 0.03125f;   // / sqrt(1024)
    __syncthreads();
    for (int k = 0; k < TOPK; k++) {
        av[tid] = sv[tid]; ai[tid] = tid;
        __syncthreads();
        for (int s = 64; s > 0; s >>= 1) {
            if (tid < s) {
                float v2 = av[tid + s]; int i2 = ai[tid + s];
                if (v2 > av[tid] || (v2 == av[tid] && i2 < ai[tid])) { av[tid] = v2; ai[tid] = i2; }
            }
            __syncthreads();
        }
        if (tid == 0) { wk[k] = av[0]; ik[k] = ai[0]; sv[ai[0]] = -INFINITY; }
        __syncthreads();
    }
    if (tid == 0) {
        float mx = wk[0], ssum = 0.f, e[TOPK];
        #pragma unroll
        for (int k = 0; k < TOPK; k++) { e[k] = expf(wk[k] - mx); ssum += e[k]; }
        #pragma unroll
        for (int k = 0; k < TOPK; k++) wk[k] = e[k] / ssum;
    }
    __syncthreads();
    #pragma unroll
    for (int i = 0; i < 8; i++) {
        int d = tid + i * 128;
        float o = 0.f;
        #pragma unroll
        for (int k = 0; k < TOPK; k++)
            o = fmaf(wk[k], mem_values[(size_t)ik[k] * DM + d], o);
        outp[(size_t)row * DM + d] = o;
    }
}

// ---------------- gate: gelu(g1)@w2 + b2 -> sigmoid -> x += gate*retr ----------------
__global__ void gate_kernel(float* __restrict__ x, const float* __restrict__ g1,
                            const float* __restrict__ gw2, const float* __restrict__ gb2,
                            const float* __restrict__ retr)
{
    __shared__ float red[8];
    int row = blockIdx.x, tid = threadIdx.x;   // 256
    float s = 0.f;
    for (int j = tid; j < 512; j += 256) {
        float v = g1[(size_t)row * 512 + j];
        s = fmaf(gelu_f(v), gw2[j], s);
    }
    s = blockSum(s, red);
    float gate = 1.f / (1.f + expf(-(s + gb2[0])));
    #pragma unroll
    for (int i = 0; i < 4; i++) {
        int d = tid + i * 256;
        size_t p = (size_t)row * DM + d;
        x[p] += gate * retr[p];
    }
}

// ---------------- host-side gemm dispatch ----------------
static void gemm(int ep, float* C, const float* A, const float* B,
                 int M, int N, int K, int lda, int ldb, int ldc,
                 const float* res = nullptr, int ldres = 0,
                 const float* bias = nullptr)
{
    dim3 grid((N + 127) / 128, (M + 127) / 128);
    switch (ep) {
    case EP_STORE:    tgemm_abt<EP_STORE>   <<<grid,256>>>(C,A,B,M,N,K,lda,ldb,ldc,res,ldres,bias); break;
    case EP_ADD:      tgemm_abt<EP_ADD>     <<<grid,256>>>(C,A,B,M,N,K,lda,ldb,ldc,res,ldres,bias); break;
    case EP_GELU:     tgemm_abt<EP_GELU>    <<<grid,256>>>(C,A,B,M,N,K,lda,ldb,ldc,res,ldres,bias); break;
    case EP_ADD_BIAS: tgemm_abt<EP_ADD_BIAS><<<grid,256>>>(C,A,B,M,N,K,lda,ldb,ldc,res,ldres,bias); break;
    case EP_SILU_MUL: tgemm_abt<EP_SILU_MUL><<<grid,256>>>(C,A,B,M,N,K,lda,ldb,ldc,res,ldres,bias); break;
    }
}

extern "C" void kernel_launch(void* const* d_in, const int* in_sizes, int n_in,
                              void* d_out, int out_size)
{
    const int*   ids       = (const int*)  d_in[0];
    const float* embed     = (const float*)d_in[1];
    const float* pos       = (const float*)d_in[2];
    const float* n1        = (const float*)d_in[3];
    const float* qkvw      = (const float*)d_in[4];
    const float* outw      = (const float*)d_in[5];
    const float* n2        = (const float*)d_in[6];
    const float* w1        = (const float*)d_in[7];
    const float* w2        = (const float*)d_in[8];
    const float* w3        = (const float*)d_in[9];
    const float* router    = (const float*)d_in[10];
    const float* mem_keys  = (const float*)d_in[11];
    const float* mem_vals  = (const float*)d_in[12];
    const float* mem_q     = (const float*)d_in[13];
    const float* mem_out   = (const float*)d_in[14];
    const float* gate_w1   = (const float*)d_in[15];
    const float* gate_b1   = (const float*)d_in[16];
    const float* gate_w2   = (const float*)d_in[17];
    const float* gate_b2   = (const float*)d_in[18];
    const float* lat_norm  = (const float*)d_in[19];
    const float* lat_w1    = (const float*)d_in[20];
    const float* lat_w2    = (const float*)d_in[21];
    const float* fin_norm  = (const float*)d_in[22];
    const float* lm_head   = (const float*)d_in[23];
    float* out = (float*)d_out;

    float *x,*xn,*qkvb,*attnb,*ff1,*ff2,*retr,*retrp,*sim,*g1,*h1,*xs,*scores;
    int *idxb;
    cudaGetSymbolAddress((void**)&x,     g_x);
    cudaGetSymbolAddress((void**)&xn,    g_xn);
    cudaGetSymbolAddress((void**)&qkvb,  g_qkv);
    cudaGetSymbolAddress((void**)&attnb, g_attn);
    cudaGetSymbolAddress((void**)&ff1,   g_ff1);
    cudaGetSymbolAddress((void**)&ff2,   g_ff2);
    cudaGetSymbolAddress((void**)&retr,  g_retr);
    cudaGetSymbolAddress((void**)&retrp, g_retrp);
    cudaGetSymbolAddress((void**)&sim,   g_sim);
    cudaGetSymbolAddress((void**)&g1,    g_g1);
    cudaGetSymbolAddress((void**)&h1,    g_h1);
    cudaGetSymbolAddress((void**)&xs,    g_xs);
    cudaGetSymbolAddress((void**)&scores,g_scores);
    cudaGetSymbolAddress((void**)&idxb,  g_idx);

    // x = embed[ids] + pos
    embed_kernel<<<NTOK, 256>>>(x, ids, embed, pos);

    // transformer block applied to a contiguous buffer of M rows (S tokens per batch)
    auto run_block = [&](float* buf, int M, int S, int l) {
        const float* Wqkv = qkvw + (size_t)l * 3 * DM * DM;
        const float* Wout = outw + (size_t)l * DM * DM;
        const float* W1   = w1   + (size_t)l * DFF * DM;
        const float* W2   = w2   + (size_t)l * DFF * DM;
        const float* W3   = w3   + (size_t)l * DM * DFF;
        rms_kernel<<<M, 256>>>(xn, buf, n1 + (size_t)l * DM);
        gemm(EP_STORE, qkvb, xn, Wqkv, M, 3 * DM, DM, DM, DM, 3 * DM);
        attn_kernel<<<dim3(S, NHEAD, BATCH), 128>>>(qkvb, attnb, S);
        gemm(EP_ADD, buf, attnb, Wout, M, DM, DM, DM, DM, DM, buf, DM);
        rms_kernel<<<M, 256>>>(xn, buf, n2 + (size_t)l * DM);
        gemm(EP_STORE,    ff1, xn, W1, M, DFF, DM, DM, DM, DFF);
        gemm(EP_SILU_MUL, ff2, xn, W2, M, DFF, DM, DM, DM, DFF, ff1, DFF);
        gemm(EP_ADD,      buf, ff2, W3, M, DM, DFF, DFF, DFF, DM, buf, DM);
    };

    for (int l = 0; l < NLAYER; l++) {
        if (l & 1) {
            // Mixture-of-Depths: route top-CAP tokens (descending score order)
            score_kernel<<<NTOK, 256>>>(scores, x, router + (size_t)l * DM);
            topk_sort_kernel<<<BATCH, TSEQ>>>(idxb, scores);
            gather_kernel<<<BATCH * CAP, 256>>>(xs, x, idxb);
            run_block(xs, BATCH * CAP, CAP, l);
            scatter_kernel<<<BATCH * CAP, 256>>>(x, xs, idxb);
        } else {
            run_block(x, NTOK, TSEQ, l);
        }
    }

    // kNN memory retrieval
    gemm(EP_STORE, xn,  x,  mem_q,    NTOK, DM,     DM, DM, DM, DM);      // q = x @ mem_q^T
    gemm(EP_STORE, sim, xn, mem_keys, NTOK, NSLOTS, DM, DM, DM, NSLOTS);  // sim (unscaled)
    memtopk_kernel<<<NTOK, 128>>>(retrp, sim, mem_vals);
    gemm(EP_STORE, retr, retrp, mem_out, NTOK, DM, DM, DM, DM, DM);
    // gate MLP: g1 = x@W1a^T + retr@W1b^T + b1   (gate_w1 is [512, 2048])
    gemm(EP_STORE,    g1, x,    gate_w1,        NTOK, 512, DM, DM, 2 * DM, 512);
    gemm(EP_ADD_BIAS, g1, retr, gate_w1 + DM,   NTOK, 512, DM, DM, 2 * DM, 512, g1, 512, gate_b1);
    gate_kernel<<<NTOK, 256>>>(x, g1, gate_w2, gate_b2, retr);

    // latent reasoning iterations
    for (int it = 0; it < 4; it++) {
        rms_kernel<<<NTOK, 256>>>(xn, x, lat_norm);
        gemm(EP_GELU, h1, xn, lat_w1, NTOK, 2 * DM, DM, DM, DM, 2 * DM);
        gemm(EP_ADD,  x,  h1, lat_w2, NTOK, DM, 2 * DM, 2 * DM, 2 * DM, DM, x, DM);
    }

    // final norm + LM head
    rms_kernel<<<NTOK, 256>>>(xn, x, fin_norm);
    gemm(EP_STORE, out, xn, lm_head, NTOK, 50257, DM, DM, DM, 50257);
}

// round 10
// speedup vs baseline: 1.1619x; 1.1619x over previous
#include <cuda_runtime.h>
#include <math.h>

// ---------------- problem constants ----------------
#define BATCH   2
#define TSEQ    1024
#define DM      1024
#define NHEAD   16
#define HD      64
#define NLAYER  12
#define DFF     2730
#define CAP     128
#define NSLOTS  128
#define TOPK    8
#define NTOK    (BATCH*TSEQ)      // 2048

// ---------------- scratch (device globals; no allocation allowed) ----------------
__device__ float g_x    [NTOK*DM];
__device__ float g_xn   [NTOK*DM];
__device__ float g_qkv  [NTOK*3*DM];
__device__ float g_attn [NTOK*DM];
__device__ float g_ff1  [NTOK*DFF];
__device__ float g_ff2  [NTOK*DFF];
__device__ float g_retr [NTOK*DM];
__device__ float g_retrp[NTOK*DM];
__device__ float g_sim  [NTOK*NSLOTS];
__device__ float g_g1   [NTOK*512];
__device__ float g_h1   [NTOK*2048];
__device__ float g_xs   [BATCH*CAP*DM];
__device__ float g_scores[NTOK];
__device__ int   g_idx  [BATCH*CAP];

// ---------------- helpers ----------------
__device__ __forceinline__ float warpSum(float v){
    #pragma unroll
    for (int o=16;o>0;o>>=1) v += __shfl_xor_sync(0xffffffffu, v, o);
    return v;
}
__device__ __forceinline__ float warpMax(float v){
    #pragma unroll
    for (int o=16;o>0;o>>=1) v = fmaxf(v, __shfl_xor_sync(0xffffffffu, v, o));
    return v;
}
__device__ __forceinline__ float blockSum(float v, float* red){
    int lane = threadIdx.x & 31, w = threadIdx.x >> 5, nw = blockDim.x >> 5;
    v = warpSum(v);
    if (lane == 0) red[w] = v;
    __syncthreads();
    float r = (w == 0 && lane < nw) ? red[lane] : 0.f;
    if (w == 0) r = warpSum(r);
    if (threadIdx.x == 0) red[0] = r;
    __syncthreads();
    float out = red[0];
    __syncthreads();
    return out;
}
__device__ __forceinline__ float blockMax(float v, float* red){
    int lane = threadIdx.x & 31, w = threadIdx.x >> 5, nw = blockDim.x >> 5;
    v = warpMax(v);
    if (lane == 0) red[w] = v;
    __syncthreads();
    float r = (w == 0 && lane < nw) ? red[lane] : -INFINITY;
    if (w == 0) r = warpMax(r);
    if (threadIdx.x == 0) red[0] = r;
    __syncthreads();
    float out = red[0];
    __syncthreads();
    return out;
}
__device__ __forceinline__ float gelu_f(float v){
    return 0.5f * v * (1.f + erff(v * 0.70710678118654752f));
}
__device__ __forceinline__ float silu_f(float v){
    return v / (1.f + expf(-v));
}

// ---------------- tf32 split + mma ----------------
__device__ __forceinline__ void split_tf32(float v, float &hi, float &lo){
    unsigned h;
    asm("cvt.rna.tf32.f32 %0, %1;" : "=r"(h) : "f"(v));
    float lf = v - __uint_as_float(h);
    unsigned l;
    asm("cvt.rna.tf32.f32 %0, %1;" : "=r"(l) : "f"(lf));
    hi = __uint_as_float(h); lo = __uint_as_float(l);
}
__device__ __forceinline__ void mma8(float* c, const unsigned* a, const unsigned* b){
    asm volatile(
        "mma.sync.aligned.m16n8k8.row.col.f32.tf32.tf32.f32 "
        "{%0,%1,%2,%3}, {%4,%5,%6,%7}, {%8,%9}, {%0,%1,%2,%3};"
        : "+f"(c[0]), "+f"(c[1]), "+f"(c[2]), "+f"(c[3])
        : "r"(a[0]), "r"(a[1]), "r"(a[2]), "r"(a[3]), "r"(b[0]), "r"(b[1]));
}

// guarded float4 row load (handles unaligned ld and K tail)
__device__ __forceinline__ float4 ldg_row(const float* __restrict__ P, int ld, bool al4,
                                          int row, int gk, int RM, int K)
{
    float4 v = make_float4(0.f, 0.f, 0.f, 0.f);
    if (row < RM) {
        const float* p = P + (size_t)row * ld + gk;
        if (al4 && gk + 3 < K) v = *(const float4*)p;
        else {
            if (gk + 0 < K) v.x = p[0];
            if (gk + 1 < K) v.y = p[1];
            if (gk + 2 < K) v.z = p[2];
            if (gk + 3 < K) v.w = p[3];
        }
    }
    return v;
}

// ---------------- tensor-core GEMM: C[M,N] = epilogue(A[M,K] @ B[N,K]^T) ----------------
// 3xTF32 (hi/lo split done ONCE at smem fill), register-staged double buffering.
// EP: 0 store, 1 C=res+acc, 2 C=gelu(acc), 3 C=res+acc+bias[n], 4 C=silu(res)*acc
#define EP_STORE    0
#define EP_ADD      1
#define EP_GELU     2
#define EP_ADD_BIAS 3
#define EP_SILU_MUL 4

template<int EP>
__global__ __launch_bounds__(256)
void tgemm_abt(float* __restrict__ C, const float* __restrict__ A,
               const float* __restrict__ B, int M, int N, int K,
               int lda, int ldb, int ldc,
               const float* __restrict__ res, int ldres,
               const float* __restrict__ bias)
{
    // [m][k] layout, row stride 20 floats: frag banks (20g+tg)%32 -> all distinct.
    __shared__ float Ah[128][20], Al[128][20], Bh[128][20], Bl[128][20];
    const int bm = blockIdx.y * 128, bn = blockIdx.x * 128;
    const int tid  = threadIdx.x;
    const int warp = tid >> 5, lane = tid & 31;
    const int wm = (warp & 1) * 64;      // 2 warps along M
    const int wn = (warp >> 1) * 32;     // 4 warps along N
    const int g  = lane >> 2, tg = lane & 3;
    const bool a4 = ((lda & 3) == 0);
    const bool b4 = ((ldb & 3) == 0);
    const int lrow0 = tid >> 2, lvq0 = tid & 3;          // i=0 fill slot
    const int lrow1 = (tid + 256) >> 2, lvq1 = tid & 3;  // i=1 fill slot

    float acc[4][4][4];
    #pragma unroll
    for (int mi = 0; mi < 4; mi++)
        #pragma unroll
        for (int ni = 0; ni < 4; ni++)
            #pragma unroll
            for (int cc = 0; cc < 4; cc++) acc[mi][ni][cc] = 0.f;

    // prologue: stage tile k0=0 in registers
    float4 sA[2], sB[2];
    sA[0] = ldg_row(A, lda, a4, bm + lrow0, lvq0 * 4, M, K);
    sB[0] = ldg_row(B, ldb, b4, bn + lrow0, lvq0 * 4, N, K);
    sA[1] = ldg_row(A, lda, a4, bm + lrow1, lvq1 * 4, M, K);
    sB[1] = ldg_row(B, ldb, b4, bn + lrow1, lvq1 * 4, N, K);

    for (int k0 = 0; k0 < K; k0 += 16) {
        // fill smem from staged regs, splitting hi/lo once per element
        #pragma unroll
        for (int i = 0; i < 2; i++) {
            int row = (i == 0) ? lrow0 : lrow1;
            int vq  = (i == 0) ? lvq0  : lvq1;
            float va[4] = { sA[i].x, sA[i].y, sA[i].z, sA[i].w };
            float vb[4] = { sB[i].x, sB[i].y, sB[i].z, sB[i].w };
            float ah[4], al[4], bh[4], bl[4];
            #pragma unroll
            for (int j = 0; j < 4; j++) {
                split_tf32(va[j], ah[j], al[j]);
                split_tf32(vb[j], bh[j], bl[j]);
            }
            *(float4*)&Ah[row][vq * 4] = make_float4(ah[0], ah[1], ah[2], ah[3]);
            *(float4*)&Al[row][vq * 4] = make_float4(al[0], al[1], al[2], al[3]);
            *(float4*)&Bh[row][vq * 4] = make_float4(bh[0], bh[1], bh[2], bh[3]);
            *(float4*)&Bl[row][vq * 4] = make_float4(bl[0], bl[1], bl[2], bl[3]);
        }
        __syncthreads();

        // prefetch next tile into regs; LDG latency overlaps compute below
        if (k0 + 16 < K) {
            int gk0 = k0 + 16 + lvq0 * 4;
            int gk1 = k0 + 16 + lvq1 * 4;
            sA[0] = ldg_row(A, lda, a4, bm + lrow0, gk0, M, K);
            sB[0] = ldg_row(B, ldb, b4, bn + lrow0, gk0, N, K);
            sA[1] = ldg_row(A, lda, a4, bm + lrow1, gk1, M, K);
            sB[1] = ldg_row(B, ldb, b4, bn + lrow1, gk1, N, K);
        }

        #pragma unroll
        for (int ks = 0; ks < 16; ks += 8) {
            unsigned bhiF[4][2], bloF[4][2];
            #pragma unroll
            for (int ni = 0; ni < 4; ni++) {
                int col = wn + ni * 8 + g;
                bhiF[ni][0] = __float_as_uint(Bh[col][ks + tg]);
                bhiF[ni][1] = __float_as_uint(Bh[col][ks + tg + 4]);
                bloF[ni][0] = __float_as_uint(Bl[col][ks + tg]);
                bloF[ni][1] = __float_as_uint(Bl[col][ks + tg + 4]);
            }
            unsigned ahiF[4][4], aloF[4][4];
            #pragma unroll
            for (int mi = 0; mi < 4; mi++) {
                int r = wm + mi * 16 + g;
                ahiF[mi][0] = __float_as_uint(Ah[r][ks + tg]);
                ahiF[mi][1] = __float_as_uint(Ah[r + 8][ks + tg]);
                ahiF[mi][2] = __float_as_uint(Ah[r][ks + tg + 4]);
                ahiF[mi][3] = __float_as_uint(Ah[r + 8][ks + tg + 4]);
                aloF[mi][0] = __float_as_uint(Al[r][ks + tg]);
                aloF[mi][1] = __float_as_uint(Al[r + 8][ks + tg]);
                aloF[mi][2] = __float_as_uint(Al[r][ks + tg + 4]);
                aloF[mi][3] = __float_as_uint(Al[r + 8][ks + tg + 4]);
            }
            #pragma unroll
            for (int mi = 0; mi < 4; mi++)
                #pragma unroll
                for (int ni = 0; ni < 4; ni++) {
                    mma8(acc[mi][ni], ahiF[mi], bhiF[ni]);
                    mma8(acc[mi][ni], ahiF[mi], bloF[ni]);
                    mma8(acc[mi][ni], aloF[mi], bhiF[ni]);
                }
        }
        __syncthreads();
    }

    // epilogue
    #pragma unroll
    for (int mi = 0; mi < 4; mi++) {
        int row0 = bm + wm + mi * 16 + g;
        #pragma unroll
        for (int ni = 0; ni < 4; ni++) {
            int col0 = bn + wn + ni * 8 + tg * 2;
            #pragma unroll
            for (int cc = 0; cc < 4; cc++) {
                int gm = row0 + (cc >> 1) * 8;
                int gn = col0 + (cc & 1);
                if (gm < M && gn < N) {
                    float v = acc[mi][ni][cc];
                    if (EP == EP_ADD)           v += res[(size_t)gm * ldres + gn];
                    else if (EP == EP_GELU)     v = gelu_f(v);
                    else if (EP == EP_ADD_BIAS) v += res[(size_t)gm * ldres + gn] + bias[gn];
                    else if (EP == EP_SILU_MUL) v *= silu_f(res[(size_t)gm * ldres + gn]);
                    C[(size_t)gm * ldc + gn] = v;
                }
            }
        }
    }
}

// ---------------- embed + positional ----------------
__global__ void embed_kernel(float* __restrict__ x, const int* __restrict__ ids,
                             const float* __restrict__ emb, const float* __restrict__ pos)
{
    int row = blockIdx.x;          // b*T + t
    int t   = row & (TSEQ - 1);
    int id  = ids[row];
    int tid = threadIdx.x;
    #pragma unroll
    for (int i = 0; i < 4; i++) {
        int d = tid + i * 256;
        x[(size_t)row * DM + d] = emb[(size_t)id * DM + d] + pos[(size_t)t * DM + d];
    }
}

// ---------------- rmsnorm ----------------
__global__ void rms_kernel(float* __restrict__ y, const float* __restrict__ x,
                           const float* __restrict__ w)
{
    __shared__ float red[8];
    int row = blockIdx.x, tid = threadIdx.x;
    const float* xr = x + (size_t)row * DM;
    float s = 0.f;
    #pragma unroll
    for (int i = 0; i < 4; i++) { float v = xr[tid + i * 256]; s = fmaf(v, v, s); }
    s = blockSum(s, red);
    float r = rsqrtf(s * (1.f / DM) + 1e-6f);
    #pragma unroll
    for (int i = 0; i < 4; i++) {
        int d = tid + i * 256;
        y[(size_t)row * DM + d] = xr[d] * r * w[d];
    }
}

// ---------------- attention: one block per (query t, head h, batch b) ----------------
__global__ void attn_kernel(const float* __restrict__ qkv, float* __restrict__ out, int S)
{
    const int t = blockIdx.x, h = blockIdx.y, b = blockIdx.z;
    const int tid = threadIdx.x;   // 128 threads
    __shared__ float qsh[HD];
    __shared__ float sc[TSEQ];
    __shared__ float red[8];
    __shared__ float obuf[HD];
    const float* base = qkv + (size_t)b * S * (3 * DM);
    if (tid < HD) qsh[tid] = base[(size_t)t * (3 * DM) + h * HD + tid];
    __syncthreads();

    float lmax = -INFINITY;
    for (int j = tid; j <= t; j += 128) {
        const float* kr = base + (size_t)j * (3 * DM) + DM + h * HD;
        float s = 0.f;
        #pragma unroll
        for (int d = 0; d < HD; d++) s = fmaf(qsh[d], kr[d], s);
        s *= 0.125f;                 // 1/sqrt(64)
        sc[j] = s;
        lmax = fmaxf(lmax, s);
    }
    float m = blockMax(lmax, red);
    float lsum = 0.f;
    for (int j = tid; j <= t; j += 128) {
        float p = expf(sc[j] - m);
        sc[j] = p;
        lsum += p;
    }
    float ssum = blockSum(lsum, red);
    float inv = 1.f / ssum;

    const int d = tid & 63, half = tid >> 6;
    const float* vb = base + 2 * DM + h * HD + d;
    float o = 0.f;
    for (int j = half; j <= t; j += 2)
        o = fmaf(sc[j], vb[(size_t)j * (3 * DM)], o);
    if (half == 1) obuf[d] = o;
    __syncthreads();
    if (half == 0)
        out[((size_t)(b * S + t)) * DM + h * HD + d] = (o + obuf[d]) * inv;
}

// ---------------- MoD: router scores ----------------
__global__ void score_kernel(float* __restrict__ scores, const float* __restrict__ x,
                             const float* __restrict__ r)
{
    __shared__ float red[8];
    int row = blockIdx.x, tid = threadIdx.x;
    const float* xr = x + (size_t)row * DM;
    float s = 0.f;
    #pragma unroll
    for (int i = 0; i < 4; i++) { int d = tid + i * 256; s = fmaf(xr[d], r[d], s); }
    s = blockSum(s, red);
    if (tid == 0) scores[row] = s;
}

// ---------------- MoD: exact top-128 descending (bitonic sort, tie = smaller idx) ----------------
__global__ void topk_sort_kernel(int* __restrict__ idx, const float* __restrict__ scores)
{
    int b = blockIdx.x, tid = threadIdx.x;     // 1024 threads
    __shared__ float s[TSEQ];
    __shared__ int   si[TSEQ];
    s[tid]  = scores[b * TSEQ + tid];
    si[tid] = tid;
    __syncthreads();
    for (int k = 2; k <= TSEQ; k <<= 1) {
        for (int j = k >> 1; j > 0; j >>= 1) {
            int ixj = tid ^ j;
            if (ixj > tid) {
                bool desc = ((tid & k) == 0);
                float s1 = s[tid], s2 = s[ixj];
                int   i1 = si[tid], i2 = si[ixj];
                bool firstBetter = (s1 > s2) || (s1 == s2 && i1 < i2);
                if (desc != firstBetter) {
                    s[tid] = s2; s[ixj] = s1;
                    si[tid] = i2; si[ixj] = i1;
                }
            }
            __syncthreads();
        }
    }
    if (tid < CAP) idx[b * CAP + tid] = si[tid];
}

__global__ void gather_kernel(float* __restrict__ xs, const float* __restrict__ x,
                              const int* __restrict__ idx)
{
    int row = blockIdx.x;            // b*CAP + j
    int b = row >> 7;
    int src = b * TSEQ + idx[row];
    int tid = threadIdx.x;
    #pragma unroll
    for (int i = 0; i < 4; i++) {
        int d = tid + i * 256;
        xs[(size_t)row * DM + d] = x[(size_t)src * DM + d];
    }
}
__global__ void scatter_kernel(float* __restrict__ x, const float* __restrict__ xs,
                               const int* __restrict__ idx)
{
    int row = blockIdx.x;
    int b = row >> 7;
    int dst = b * TSEQ + idx[row];
    int tid = threadIdx.x;
    #pragma unroll
    for (int i = 0; i < 4; i++) {
        int d = tid + i * 256;
        x[(size_t)dst * DM + d] = xs[(size_t)row * DM + d];
    }
}

// ---------------- memory: top-8 + softmax + weighted value gather ----------------
__global__ void memtopk_kernel(float* __restrict__ outp, const float* __restrict__ sim,
                               const float* __restrict__ mem_values)
{
    int row = blockIdx.x, tid = threadIdx.x;   // 128 threads
    __shared__ float sv[NSLOTS];
    __shared__ float av[NSLOTS];
    __shared__ int   ai[NSLOTS];
    __shared__ float wk[TOPK];
    __shared__ int   ik[TOPK];
    sv[tid] = sim[(size_t)row * NSLOTS + tid] * 0.03125f;   // / sqrt(1024)
    __syncthreads();
    for (int k = 0; k < TOPK; k++) {
        av[tid] = sv[tid]; ai[tid] = tid;
        __syncthreads();
        for (int s = 64; s > 0; s >>= 1) {
            if (tid < s) {
                float v2 = av[tid + s]; int i2 = ai[tid + s];
                if (v2 > av[tid] || (v2 == av[tid] && i2 < ai[tid])) { av[tid] = v2; ai[tid] = i2; }
            }
            __syncthreads();
        }
        if (tid == 0) { wk[k] = av[0]; ik[k] = ai[0]; sv[ai[0]] = -INFINITY; }
        __syncthreads();
    }
    if (tid == 0) {
        float mx = wk[0], ssum = 0.f, e[TOPK];
        #pragma unroll
        for (int k = 0; k < TOPK; k++) { e[k] = expf(wk[k] - mx); ssum += e[k]; }
        #pragma unroll
        for (int k = 0; k < TOPK; k++) wk[k] = e[k] / ssum;
    }
    __syncthreads();
    #pragma unroll
    for (int i = 0; i < 8; i++) {
        int d = tid + i * 128;
        float o = 0.f;
        #pragma unroll
        for (int k = 0; k < TOPK; k++)
            o = fmaf(wk[k], mem_values[(size_t)ik[k] * DM + d], o);
        outp[(size_t)row * DM + d] = o;
    }
}

// ---------------- gate: gelu(g1)@w2 + b2 -> sigmoid -> x += gate*retr ----------------
__global__ void gate_kernel(float* __restrict__ x, const float* __restrict__ g1,
                            const float* __restrict__ gw2, const float* __restrict__ gb2,
                            const float* __restrict__ retr)
{
    __shared__ float red[8];
    int row = blockIdx.x, tid = threadIdx.x;   // 256
    float s = 0.f;
    for (int j = tid; j < 512; j += 256) {
        float v = g1[(size_t)row * 512 + j];
        s = fmaf(gelu_f(v), gw2[j], s);
    }
    s = blockSum(s, red);
    float gate = 1.f / (1.f + expf(-(s + gb2[0])));
    #pragma unroll
    for (int i = 0; i < 4; i++) {
        int d = tid + i * 256;
        size_t p = (size_t)row * DM + d;
        x[p] += gate * retr[p];
    }
}

// ---------------- host-side gemm dispatch ----------------
static void gemm(int ep, float* C, const float* A, const float* B,
                 int M, int N, int K, int lda, int ldb, int ldc,
                 const float* res = nullptr, int ldres = 0,
                 const float* bias = nullptr)
{
    dim3 grid((N + 127) / 128, (M + 127) / 128);
    switch (ep) {
    case EP_STORE:    tgemm_abt<EP_STORE>   <<<grid,256>>>(C,A,B,M,N,K,lda,ldb,ldc,res,ldres,bias); break;
    case EP_ADD:      tgemm_abt<EP_ADD>     <<<grid,256>>>(C,A,B,M,N,K,lda,ldb,ldc,res,ldres,bias); break;
    case EP_GELU:     tgemm_abt<EP_GELU>    <<<grid,256>>>(C,A,B,M,N,K,lda,ldb,ldc,res,ldres,bias); break;
    case EP_ADD_BIAS: tgemm_abt<EP_ADD_BIAS><<<grid,256>>>(C,A,B,M,N,K,lda,ldb,ldc,res,ldres,bias); break;
    case EP_SILU_MUL: tgemm_abt<EP_SILU_MUL><<<grid,256>>>(C,A,B,M,N,K,lda,ldb,ldc,res,ldres,bias); break;
    }
}

extern "C" void kernel_launch(void* const* d_in, const int* in_sizes, int n_in,
                              void* d_out, int out_size)
{
    const int*   ids       = (const int*)  d_in[0];
    const float* embed     = (const float*)d_in[1];
    const float* pos       = (const float*)d_in[2];
    const float* n1        = (const float*)d_in[3];
    const float* qkvw      = (const float*)d_in[4];
    const float* outw      = (const float*)d_in[5];
    const float* n2        = (const float*)d_in[6];
    const float* w1        = (const float*)d_in[7];
    const float* w2        = (const float*)d_in[8];
    const float* w3        = (const float*)d_in[9];
    const float* router    = (const float*)d_in[10];
    const float* mem_keys  = (const float*)d_in[11];
    const float* mem_vals  = (const float*)d_in[12];
    const float* mem_q     = (const float*)d_in[13];
    const float* mem_out   = (const float*)d_in[14];
    const float* gate_w1   = (const float*)d_in[15];
    const float* gate_b1   = (const float*)d_in[16];
    const float* gate_w2   = (const float*)d_in[17];
    const float* gate_b2   = (const float*)d_in[18];
    const float* lat_norm  = (const float*)d_in[19];
    const float* lat_w1    = (const float*)d_in[20];
    const float* lat_w2    = (const float*)d_in[21];
    const float* fin_norm  = (const float*)d_in[22];
    const float* lm_head   = (const float*)d_in[23];
    float* out = (float*)d_out;

    float *x,*xn,*qkvb,*attnb,*ff1,*ff2,*retr,*retrp,*sim,*g1,*h1,*xs,*scores;
    int *idxb;
    cudaGetSymbolAddress((void**)&x,     g_x);
    cudaGetSymbolAddress((void**)&xn,    g_xn);
    cudaGetSymbolAddress((void**)&qkvb,  g_qkv);
    cudaGetSymbolAddress((void**)&attnb, g_attn);
    cudaGetSymbolAddress((void**)&ff1,   g_ff1);
    cudaGetSymbolAddress((void**)&ff2,   g_ff2);
    cudaGetSymbolAddress((void**)&retr,  g_retr);
    cudaGetSymbolAddress((void**)&retrp, g_retrp);
    cudaGetSymbolAddress((void**)&sim,   g_sim);
    cudaGetSymbolAddress((void**)&g1,    g_g1);
    cudaGetSymbolAddress((void**)&h1,    g_h1);
    cudaGetSymbolAddress((void**)&xs,    g_xs);
    cudaGetSymbolAddress((void**)&scores,g_scores);
    cudaGetSymbolAddress((void**)&idxb,  g_idx);

    // x = embed[ids] + pos
    embed_kernel<<<NTOK, 256>>>(x, ids, embed, pos);

    // transformer block applied to a contiguous buffer of M rows (S tokens per batch)
    auto run_block = [&](float* buf, int M, int S, int l) {
        const float* Wqkv = qkvw + (size_t)l * 3 * DM * DM;
        const float* Wout = outw + (size_t)l * DM * DM;
        const float* W1   = w1   + (size_t)l * DFF * DM;
        const float* W2   = w2   + (size_t)l * DFF * DM;
        const float* W3   = w3   + (size_t)l * DM * DFF;
        rms_kernel<<<M, 256>>>(xn, buf, n1 + (size_t)l * DM);
        gemm(EP_STORE, qkvb, xn, Wqkv, M, 3 * DM, DM, DM, DM, 3 * DM);
        attn_kernel<<<dim3(S, NHEAD, BATCH), 128>>>(qkvb, attnb, S);
        gemm(EP_ADD, buf, attnb, Wout, M, DM, DM, DM, DM, DM, buf, DM);
        rms_kernel<<<M, 256>>>(xn, buf, n2 + (size_t)l * DM);
        gemm(EP_STORE,    ff1, xn, W1, M, DFF, DM, DM, DM, DFF);
        gemm(EP_SILU_MUL, ff2, xn, W2, M, DFF, DM, DM, DM, DFF, ff1, DFF);
        gemm(EP_ADD,      buf, ff2, W3, M, DM, DFF, DFF, DFF, DM, buf, DM);
    };

    for (int l = 0; l < NLAYER; l++) {
        if (l & 1) {
            // Mixture-of-Depths: route top-CAP tokens (descending score order)
            score_kernel<<<NTOK, 256>>>(scores, x, router + (size_t)l * DM);
            topk_sort_kernel<<<BATCH, TSEQ>>>(idxb, scores);
            gather_kernel<<<BATCH * CAP, 256>>>(xs, x, idxb);
            run_block(xs, BATCH * CAP, CAP, l);
            scatter_kernel<<<BATCH * CAP, 256>>>(x, xs, idxb);
        } else {
            run_block(x, NTOK, TSEQ, l);
        }
    }

    // kNN memory retrieval
    gemm(EP_STORE, xn,  x,  mem_q,    NTOK, DM,     DM, DM, DM, DM);      // q = x @ mem_q^T
    gemm(EP_STORE, sim, xn, mem_keys, NTOK, NSLOTS, DM, DM, DM, NSLOTS);  // sim (unscaled)
    memtopk_kernel<<<NTOK, 128>>>(retrp, sim, mem_vals);
    gemm(EP_STORE, retr, retrp, mem_out, NTOK, DM, DM, DM, DM, DM);
    // gate MLP: g1 = x@W1a^T + retr@W1b^T + b1   (gate_w1 is [512, 2048])
    gemm(EP_STORE,    g1, x,    gate_w1,        NTOK, 512, DM, DM, 2 * DM, 512);
    gemm(EP_ADD_BIAS, g1, retr, gate_w1 + DM,   NTOK, 512, DM, DM, 2 * DM, 512, g1, 512, gate_b1);
    gate_kernel<<<NTOK, 256>>>(x, g1, gate_w2, gate_b2, retr);

    // latent reasoning iterations
    for (int it = 0; it < 4; it++) {
        rms_kernel<<<NTOK, 256>>>(xn, x, lat_norm);
        gemm(EP_GELU, h1, xn, lat_w1, NTOK, 2 * DM, DM, DM, DM, 2 * DM);
        gemm(EP_ADD,  x,  h1, lat_w2, NTOK, DM, 2 * DM, 2 * DM, 2 * DM, DM, x, DM);
    }

    // final norm + LM head
    rms_kernel<<<NTOK, 256>>>(xn, x, fin_norm);
    gemm(EP_STORE, out, xn, lm_head, NTOK, 50257, DM, DM, DM, 50257);
}

// round 11
// speedup vs baseline: 1.1762x; 1.0123x over previous
#include <cuda_runtime.h>
#include <math.h>

// ---------------- problem constants ----------------
#define BATCH   2
#define TSEQ    1024
#define DM      1024
#define NHEAD   16
#define HD      64
#define NLAYER  12
#define DFF     2730
#define CAP     128
#define NSLOTS  128
#define TOPK    8
#define NTOK    (BATCH*TSEQ)      // 2048

// ---------------- scratch (device globals; no allocation allowed) ----------------
__device__ float g_x    [NTOK*DM];
__device__ float g_xn   [NTOK*DM];
__device__ float g_qkv  [NTOK*3*DM];
__device__ float g_attn [NTOK*DM];
__device__ float g_ff1  [NTOK*DFF];
__device__ float g_ff2  [NTOK*DFF];
__device__ float g_retr [NTOK*DM];
__device__ float g_retrp[NTOK*DM];
__device__ float g_sim  [NTOK*NSLOTS];
__device__ float g_g1   [NTOK*512];
__device__ float g_h1   [NTOK*2048];
__device__ float g_xs   [BATCH*CAP*DM];
__device__ float g_scores[NTOK];
__device__ int   g_idx  [BATCH*CAP];

// ---------------- helpers ----------------
__device__ __forceinline__ float warpSum(float v){
    #pragma unroll
    for (int o=16;o>0;o>>=1) v += __shfl_xor_sync(0xffffffffu, v, o);
    return v;
}
__device__ __forceinline__ float warpMax(float v){
    #pragma unroll
    for (int o=16;o>0;o>>=1) v = fmaxf(v, __shfl_xor_sync(0xffffffffu, v, o));
    return v;
}
__device__ __forceinline__ float blockSum(float v, float* red){
    int lane = threadIdx.x & 31, w = threadIdx.x >> 5, nw = blockDim.x >> 5;
    v = warpSum(v);
    if (lane == 0) red[w] = v;
    __syncthreads();
    float r = (w == 0 && lane < nw) ? red[lane] : 0.f;
    if (w == 0) r = warpSum(r);
    if (threadIdx.x == 0) red[0] = r;
    __syncthreads();
    float out = red[0];
    __syncthreads();
    return out;
}
__device__ __forceinline__ float blockMax(float v, float* red){
    int lane = threadIdx.x & 31, w = threadIdx.x >> 5, nw = blockDim.x >> 5;
    v = warpMax(v);
    if (lane == 0) red[w] = v;
    __syncthreads();
    float r = (w == 0 && lane < nw) ? red[lane] : -INFINITY;
    if (w == 0) r = warpMax(r);
    if (threadIdx.x == 0) red[0] = r;
    __syncthreads();
    float out = red[0];
    __syncthreads();
    return out;
}
__device__ __forceinline__ float gelu_f(float v){
    return 0.5f * v * (1.f + erff(v * 0.70710678118654752f));
}
__device__ __forceinline__ float silu_f(float v){
    return v / (1.f + expf(-v));
}

// ---------------- tf32 split + mma ----------------
__device__ __forceinline__ void split_tf32(float v, float &hi, float &lo){
    unsigned h;
    asm("cvt.rna.tf32.f32 %0, %1;" : "=r"(h) : "f"(v));
    float lf = v - __uint_as_float(h);
    unsigned l;
    asm("cvt.rna.tf32.f32 %0, %1;" : "=r"(l) : "f"(lf));
    hi = __uint_as_float(h); lo = __uint_as_float(l);
}
__device__ __forceinline__ void mma8(float* c, const unsigned* a, const unsigned* b){
    asm volatile(
        "mma.sync.aligned.m16n8k8.row.col.f32.tf32.tf32.f32 "
        "{%0,%1,%2,%3}, {%4,%5,%6,%7}, {%8,%9}, {%0,%1,%2,%3};"
        : "+f"(c[0]), "+f"(c[1]), "+f"(c[2]), "+f"(c[3])
        : "r"(a[0]), "r"(a[1]), "r"(a[2]), "r"(a[3]), "r"(b[0]), "r"(b[1]));
}

// guarded float4 row load (handles unaligned ld and K tail)
__device__ __forceinline__ float4 ldg_row(const float* __restrict__ P, int ld, bool al4,
                                          int row, int gk, int RM, int K)
{
    float4 v = make_float4(0.f, 0.f, 0.f, 0.f);
    if (row < RM) {
        const float* p = P + (size_t)row * ld + gk;
        if (al4 && gk + 3 < K) v = *(const float4*)p;
        else {
            if (gk + 0 < K) v.x = p[0];
            if (gk + 1 < K) v.y = p[1];
            if (gk + 2 < K) v.z = p[2];
            if (gk + 3 < K) v.w = p[3];
        }
    }
    return v;
}

// ---------------- tensor-core GEMM: C[M,N] = epilogue(A[M,K] @ B[N,K]^T) ----------------
// 3xTF32 (hi/lo split once at smem fill), register-staged double buffering,
// 2 blocks/SM (4 warps/SMSP) to hide LDS+MMA latency.
// EP: 0 store, 1 C=res+acc, 2 C=gelu(acc), 3 C=res+acc+bias[n], 4 C=silu(res)*acc
#define EP_STORE    0
#define EP_ADD      1
#define EP_GELU     2
#define EP_ADD_BIAS 3
#define EP_SILU_MUL 4

template<int EP>
__global__ __launch_bounds__(256, 2)
void tgemm_abt(float* __restrict__ C, const float* __restrict__ A,
               const float* __restrict__ B, int M, int N, int K,
               int lda, int ldb, int ldc,
               const float* __restrict__ res, int ldres,
               const float* __restrict__ bias)
{
    // [m][k] layout, row stride 20 floats: frag banks (20g+tg)%32 -> all distinct.
    __shared__ float Ah[128][20], Al[128][20], Bh[128][20], Bl[128][20];
    const int bm = blockIdx.y * 128, bn = blockIdx.x * 128;
    const int tid  = threadIdx.x;
    const int warp = tid >> 5, lane = tid & 31;
    const int wm = (warp & 1) * 64;      // 2 warps along M
    const int wn = (warp >> 1) * 32;     // 4 warps along N
    const int g  = lane >> 2, tg = lane & 3;
    const bool a4 = ((lda & 3) == 0);
    const bool b4 = ((ldb & 3) == 0);
    const int lrow0 = tid >> 2, lvq0 = tid & 3;          // i=0 fill slot
    const int lrow1 = (tid + 256) >> 2, lvq1 = tid & 3;  // i=1 fill slot

    float acc[4][4][4];
    #pragma unroll
    for (int mi = 0; mi < 4; mi++)
        #pragma unroll
        for (int ni = 0; ni < 4; ni++)
            #pragma unroll
            for (int cc = 0; cc < 4; cc++) acc[mi][ni][cc] = 0.f;

    // prologue: stage tile k0=0 in registers
    float4 sA[2], sB[2];
    sA[0] = ldg_row(A, lda, a4, bm + lrow0, lvq0 * 4, M, K);
    sB[0] = ldg_row(B, ldb, b4, bn + lrow0, lvq0 * 4, N, K);
    sA[1] = ldg_row(A, lda, a4, bm + lrow1, lvq1 * 4, M, K);
    sB[1] = ldg_row(B, ldb, b4, bn + lrow1, lvq1 * 4, N, K);

    for (int k0 = 0; k0 < K; k0 += 16) {
        // fill smem from staged regs, splitting hi/lo once per element
        #pragma unroll
        for (int i = 0; i < 2; i++) {
            int row = (i == 0) ? lrow0 : lrow1;
            int vq  = (i == 0) ? lvq0  : lvq1;
            float va[4] = { sA[i].x, sA[i].y, sA[i].z, sA[i].w };
            float vb[4] = { sB[i].x, sB[i].y, sB[i].z, sB[i].w };
            float ah[4], al[4], bh[4], bl[4];
            #pragma unroll
            for (int j = 0; j < 4; j++) {
                split_tf32(va[j], ah[j], al[j]);
                split_tf32(vb[j], bh[j], bl[j]);
            }
            *(float4*)&Ah[row][vq * 4] = make_float4(ah[0], ah[1], ah[2], ah[3]);
            *(float4*)&Al[row][vq * 4] = make_float4(al[0], al[1], al[2], al[3]);
            *(float4*)&Bh[row][vq * 4] = make_float4(bh[0], bh[1], bh[2], bh[3]);
            *(float4*)&Bl[row][vq * 4] = make_float4(bl[0], bl[1], bl[2], bl[3]);
        }
        __syncthreads();

        // prefetch next tile into regs; LDG latency overlaps compute below
        if (k0 + 16 < K) {
            int gk0 = k0 + 16 + lvq0 * 4;
            int gk1 = k0 + 16 + lvq1 * 4;
            sA[0] = ldg_row(A, lda, a4, bm + lrow0, gk0, M, K);
            sB[0] = ldg_row(B, ldb, b4, bn + lrow0, gk0, N, K);
            sA[1] = ldg_row(A, lda, a4, bm + lrow1, gk1, M, K);
            sB[1] = ldg_row(B, ldb, b4, bn + lrow1, gk1, N, K);
        }

        #pragma unroll
        for (int ks = 0; ks < 16; ks += 8) {
            unsigned bhiF[4][2], bloF[4][2];
            #pragma unroll
            for (int ni = 0; ni < 4; ni++) {
                int col = wn + ni * 8 + g;
                bhiF[ni][0] = __float_as_uint(Bh[col][ks + tg]);
                bhiF[ni][1] = __float_as_uint(Bh[col][ks + tg + 4]);
                bloF[ni][0] = __float_as_uint(Bl[col][ks + tg]);
                bloF[ni][1] = __float_as_uint(Bl[col][ks + tg + 4]);
            }
            // per mi: load 8 A frags, then 3 passes over ni (hi.hi, hi.lo, lo.hi)
            // -> same-acc reuse distance 4 MMAs, low register pressure
            #pragma unroll
            for (int mi = 0; mi < 4; mi++) {
                int r = wm + mi * 16 + g;
                unsigned ahiF[4], aloF[4];
                ahiF[0] = __float_as_uint(Ah[r][ks + tg]);
                ahiF[1] = __float_as_uint(Ah[r + 8][ks + tg]);
                ahiF[2] = __float_as_uint(Ah[r][ks + tg + 4]);
                ahiF[3] = __float_as_uint(Ah[r + 8][ks + tg + 4]);
                aloF[0] = __float_as_uint(Al[r][ks + tg]);
                aloF[1] = __float_as_uint(Al[r + 8][ks + tg]);
                aloF[2] = __float_as_uint(Al[r][ks + tg + 4]);
                aloF[3] = __float_as_uint(Al[r + 8][ks + tg + 4]);
                #pragma unroll
                for (int ni = 0; ni < 4; ni++) mma8(acc[mi][ni], ahiF, bhiF[ni]);
                #pragma unroll
                for (int ni = 0; ni < 4; ni++) mma8(acc[mi][ni], ahiF, bloF[ni]);
                #pragma unroll
                for (int ni = 0; ni < 4; ni++) mma8(acc[mi][ni], aloF, bhiF[ni]);
            }
        }
        __syncthreads();
    }

    // epilogue
    #pragma unroll
    for (int mi = 0; mi < 4; mi++) {
        int row0 = bm + wm + mi * 16 + g;
        #pragma unroll
        for (int ni = 0; ni < 4; ni++) {
            int col0 = bn + wn + ni * 8 + tg * 2;
            #pragma unroll
            for (int cc = 0; cc < 4; cc++) {
                int gm = row0 + (cc >> 1) * 8;
                int gn = col0 + (cc & 1);
                if (gm < M && gn < N) {
                    float v = acc[mi][ni][cc];
                    if (EP == EP_ADD)           v += res[(size_t)gm * ldres + gn];
                    else if (EP == EP_GELU)     v = gelu_f(v);
                    else if (EP == EP_ADD_BIAS) v += res[(size_t)gm * ldres + gn] + bias[gn];
                    else if (EP == EP_SILU_MUL) v *= silu_f(res[(size_t)gm * ldres + gn]);
                    C[(size_t)gm * ldc + gn] = v;
                }
            }
        }
    }
}

// ---------------- embed + positional ----------------
__global__ void embed_kernel(float* __restrict__ x, const int* __restrict__ ids,
                             const float* __restrict__ emb, const float* __restrict__ pos)
{
    int row = blockIdx.x;          // b*T + t
    int t   = row & (TSEQ - 1);
    int id  = ids[row];
    int tid = threadIdx.x;
    #pragma unroll
    for (int i = 0; i < 4; i++) {
        int d = tid + i * 256;
        x[(size_t)row * DM + d] = emb[(size_t)id * DM + d] + pos[(size_t)t * DM + d];
    }
}

// ---------------- rmsnorm ----------------
__global__ void rms_kernel(float* __restrict__ y, const float* __restrict__ x,
                           const float* __restrict__ w)
{
    __shared__ float red[8];
    int row = blockIdx.x, tid = threadIdx.x;
    const float* xr = x + (size_t)row * DM;
    float s = 0.f;
    #pragma unroll
    for (int i = 0; i < 4; i++) { float v = xr[tid + i * 256]; s = fmaf(v, v, s); }
    s = blockSum(s, red);
    float r = rsqrtf(s * (1.f / DM) + 1e-6f);
    #pragma unroll
    for (int i = 0; i < 4; i++) {
        int d = tid + i * 256;
        y[(size_t)row * DM + d] = xr[d] * r * w[d];
    }
}

// ---------------- attention: one block per (query t, head h, batch b) ----------------
__global__ void attn_kernel(const float* __restrict__ qkv, float* __restrict__ out, int S)
{
    const int t = blockIdx.x, h = blockIdx.y, b = blockIdx.z;
    const int tid = threadIdx.x;   // 128 threads
    __shared__ float qsh[HD];
    __shared__ float sc[TSEQ];
    __shared__ float red[8];
    __shared__ float obuf[HD];
    const float* base = qkv + (size_t)b * S * (3 * DM);
    if (tid < HD) qsh[tid] = base[(size_t)t * (3 * DM) + h * HD + tid];
    __syncthreads();

    float lmax = -INFINITY;
    for (int j = tid; j <= t; j += 128) {
        const float* kr = base + (size_t)j * (3 * DM) + DM + h * HD;
        float s = 0.f;
        #pragma unroll
        for (int d = 0; d < HD; d++) s = fmaf(qsh[d], kr[d], s);
        s *= 0.125f;                 // 1/sqrt(64)
        sc[j] = s;
        lmax = fmaxf(lmax, s);
    }
    float m = blockMax(lmax, red);
    float lsum = 0.f;
    for (int j = tid; j <= t; j += 128) {
        float p = expf(sc[j] - m);
        sc[j] = p;
        lsum += p;
    }
    float ssum = blockSum(lsum, red);
    float inv = 1.f / ssum;

    const int d = tid & 63, half = tid >> 6;
    const float* vb = base + 2 * DM + h * HD + d;
    float o = 0.f;
    for (int j = half; j <= t; j += 2)
        o = fmaf(sc[j], vb[(size_t)j * (3 * DM)], o);
    if (half == 1) obuf[d] = o;
    __syncthreads();
    if (half == 0)
        out[((size_t)(b * S + t)) * DM + h * HD + d] = (o + obuf[d]) * inv;
}

// ---------------- MoD: router scores ----------------
__global__ void score_kernel(float* __restrict__ scores, const float* __restrict__ x,
                             const float* __restrict__ r)
{
    __shared__ float red[8];
    int row = blockIdx.x, tid = threadIdx.x;
    const float* xr = x + (size_t)row * DM;
    float s = 0.f;
    #pragma unroll
    for (int i = 0; i < 4; i++) { int d = tid + i * 256; s = fmaf(xr[d], r[d], s); }
    s = blockSum(s, red);
    if (tid == 0) scores[row] = s;
}

// ---------------- MoD: exact top-128 descending (bitonic sort, tie = smaller idx) ----------------
__global__ void topk_sort_kernel(int* __restrict__ idx, const float* __restrict__ scores)
{
    int b = blockIdx.x, tid = threadIdx.x;     // 1024 threads
    __shared__ float s[TSEQ];
    __shared__ int   si[TSEQ];
    s[tid]  = scores[b * TSEQ + tid];
    si[tid] = tid;
    __syncthreads();
    for (int k = 2; k <= TSEQ; k <<= 1) {
        for (int j = k >> 1; j > 0; j >>= 1) {
            int ixj = tid ^ j;
            if (ixj > tid) {
                bool desc = ((tid & k) == 0);
                float s1 = s[tid], s2 = s[ixj];
                int   i1 = si[tid], i2 = si[ixj];
                bool firstBetter = (s1 > s2) || (s1 == s2 && i1 < i2);
                if (desc != firstBetter) {
                    s[tid] = s2; s[ixj] = s1;
                    si[tid] = i2; si[ixj] = i1;
                }
            }
            __syncthreads();
        }
    }
    if (tid < CAP) idx[b * CAP + tid] = si[tid];
}

__global__ void gather_kernel(float* __restrict__ xs, const float* __restrict__ x,
                              const int* __restrict__ idx)
{
    int row = blockIdx.x;            // b*CAP + j
    int b = row >> 7;
    int src = b * TSEQ + idx[row];
    int tid = threadIdx.x;
    #pragma unroll
    for (int i = 0; i < 4; i++) {
        int d = tid + i * 256;
        xs[(size_t)row * DM + d] = x[(size_t)src * DM + d];
    }
}
__global__ void scatter_kernel(float* __restrict__ x, const float* __restrict__ xs,
                               const int* __restrict__ idx)
{
    int row = blockIdx.x;
    int b = row >> 7;
    int dst = b * TSEQ + idx[row];
    int tid = threadIdx.x;
    #pragma unroll
    for (int i = 0; i < 4; i++) {
        int d = tid + i * 256;
        x[(size_t)dst * DM + d] = xs[(size_t)row * DM + d];
    }
}

// ---------------- memory: top-8 + softmax + weighted value gather ----------------
__global__ void memtopk_kernel(float* __restrict__ outp, const float* __restrict__ sim,
                               const float* __restrict__ mem_values)
{
    int row = blockIdx.x, tid = threadIdx.x;   // 128 threads
    __shared__ float sv[NSLOTS];
    __shared__ float av[NSLOTS];
    __shared__ int   ai[NSLOTS];
    __shared__ float wk[TOPK];
    __shared__ int   ik[TOPK];
    sv[tid] = sim[(size_t)row * NSLOTS + tid] * 0.03125f;   // / sqrt(1024)
    __syncthreads();
    for (int k = 0; k < TOPK; k++) {
        av[tid] = sv[tid]; ai[tid] = tid;
        __syncthreads();
        for (int s = 64; s > 0; s >>= 1) {
            if (tid < s) {
                float v2 = av[tid + s]; int i2 = ai[tid + s];
                if (v2 > av[tid] || (v2 == av[tid] && i2 < ai[tid])) { av[tid] = v2; ai[tid] = i2; }
            }
            __syncthreads();
        }
        if (tid == 0) { wk[k] = av[0]; ik[k] = ai[0]; sv[ai[0]] = -INFINITY; }
        __syncthreads();
    }
    if (tid == 0) {
        float mx = wk[0], ssum = 0.f, e[TOPK];
        #pragma unroll
        for (int k = 0; k < TOPK; k++) { e[k] = expf(wk[k] - mx); ssum += e[k]; }
        #pragma unroll
        for (int k = 0; k < TOPK; k++) wk[k] = e[k] / ssum;
    }
    __syncthreads();
    #pragma unroll
    for (int i = 0; i < 8; i++) {
        int d = tid + i * 128;
        float o = 0.f;
        #pragma unroll
        for (int k = 0; k < TOPK; k++)
            o = fmaf(wk[k], mem_values[(size_t)ik[k] * DM + d], o);
        outp[(size_t)row * DM + d] = o;
    }
}

// ---------------- gate: gelu(g1)@w2 + b2 -> sigmoid -> x += gate*retr ----------------
__global__ void gate_kernel(float* __restrict__ x, const float* __restrict__ g1,
                            const float* __restrict__ gw2, const float* __restrict__ gb2,
                            const float* __restrict__ retr)
{
    __shared__ float red[8];
    int row = blockIdx.x, tid = threadIdx.x;   // 256
    float s = 0.f;
    for (int j = tid; j < 512; j += 256) {
        float v = g1[(size_t)row * 512 + j];
        s = fmaf(gelu_f(v), gw2[j], s);
    }
    s = blockSum(s, red);
    float gate = 1.f / (1.f + expf(-(s + gb2[0])));
    #pragma unroll
    for (int i = 0; i < 4; i++) {
        int d = tid + i * 256;
        size_t p = (size_t)row * DM + d;
        x[p] += gate * retr[p];
    }
}

// ---------------- host-side gemm dispatch ----------------
static void gemm(int ep, float* C, const float* A, const float* B,
                 int M, int N, int K, int lda, int ldb, int ldc,
                 const float* res = nullptr, int ldres = 0,
                 const float* bias = nullptr)
{
    dim3 grid((N + 127) / 128, (M + 127) / 128);
    switch (ep) {
    case EP_STORE:    tgemm_abt<EP_STORE>   <<<grid,256>>>(C,A,B,M,N,K,lda,ldb,ldc,res,ldres,bias); break;
    case EP_ADD:      tgemm_abt<EP_ADD>     <<<grid,256>>>(C,A,B,M,N,K,lda,ldb,ldc,res,ldres,bias); break;
    case EP_GELU:     tgemm_abt<EP_GELU>    <<<grid,256>>>(C,A,B,M,N,K,lda,ldb,ldc,res,ldres,bias); break;
    case EP_ADD_BIAS: tgemm_abt<EP_ADD_BIAS><<<grid,256>>>(C,A,B,M,N,K,lda,ldb,ldc,res,ldres,bias); break;
    case EP_SILU_MUL: tgemm_abt<EP_SILU_MUL><<<grid,256>>>(C,A,B,M,N,K,lda,ldb,ldc,res,ldres,bias); break;
    }
}

extern "C" void kernel_launch(void* const* d_in, const int* in_sizes, int n_in,
                              void* d_out, int out_size)
{
    const int*   ids       = (const int*)  d_in[0];
    const float* embed     = (const float*)d_in[1];
    const float* pos       = (const float*)d_in[2];
    const float* n1        = (const float*)d_in[3];
    const float* qkvw      = (const float*)d_in[4];
    const float* outw      = (const float*)d_in[5];
    const float* n2        = (const float*)d_in[6];
    const float* w1        = (const float*)d_in[7];
    const float* w2        = (const float*)d_in[8];
    const float* w3        = (const float*)d_in[9];
    const float* router    = (const float*)d_in[10];
    const float* mem_keys  = (const float*)d_in[11];
    const float* mem_vals  = (const float*)d_in[12];
    const float* mem_q     = (const float*)d_in[13];
    const float* mem_out   = (const float*)d_in[14];
    const float* gate_w1   = (const float*)d_in[15];
    const float* gate_b1   = (const float*)d_in[16];
    const float* gate_w2   = (const float*)d_in[17];
    const float* gate_b2   = (const float*)d_in[18];
    const float* lat_norm  = (const float*)d_in[19];
    const float* lat_w1    = (const float*)d_in[20];
    const float* lat_w2    = (const float*)d_in[21];
    const float* fin_norm  = (const float*)d_in[22];
    const float* lm_head   = (const float*)d_in[23];
    float* out = (float*)d_out;

    float *x,*xn,*qkvb,*attnb,*ff1,*ff2,*retr,*retrp,*sim,*g1,*h1,*xs,*scores;
    int *idxb;
    cudaGetSymbolAddress((void**)&x,     g_x);
    cudaGetSymbolAddress((void**)&xn,    g_xn);
    cudaGetSymbolAddress((void**)&qkvb,  g_qkv);
    cudaGetSymbolAddress((void**)&attnb, g_attn);
    cudaGetSymbolAddress((void**)&ff1,   g_ff1);
    cudaGetSymbolAddress((void**)&ff2,   g_ff2);
    cudaGetSymbolAddress((void**)&retr,  g_retr);
    cudaGetSymbolAddress((void**)&retrp, g_retrp);
    cudaGetSymbolAddress((void**)&sim,   g_sim);
    cudaGetSymbolAddress((void**)&g1,    g_g1);
    cudaGetSymbolAddress((void**)&h1,    g_h1);
    cudaGetSymbolAddress((void**)&xs,    g_xs);
    cudaGetSymbolAddress((void**)&scores,g_scores);
    cudaGetSymbolAddress((void**)&idxb,  g_idx);

    // x = embed[ids] + pos
    embed_kernel<<<NTOK, 256>>>(x, ids, embed, pos);

    // transformer block applied to a contiguous buffer of M rows (S tokens per batch)
    auto run_block = [&](float* buf, int M, int S, int l) {
        const float* Wqkv = qkvw + (size_t)l * 3 * DM * DM;
        const float* Wout = outw + (size_t)l * DM * DM;
        const float* W1   = w1   + (size_t)l * DFF * DM;
        const float* W2   = w2   + (size_t)l * DFF * DM;
        const float* W3   = w3   + (size_t)l * DM * DFF;
        rms_kernel<<<M, 256>>>(xn, buf, n1 + (size_t)l * DM);
        gemm(EP_STORE, qkvb, xn, Wqkv, M, 3 * DM, DM, DM, DM, 3 * DM);
        attn_kernel<<<dim3(S, NHEAD, BATCH), 128>>>(qkvb, attnb, S);
        gemm(EP_ADD, buf, attnb, Wout, M, DM, DM, DM, DM, DM, buf, DM);
        rms_kernel<<<M, 256>>>(xn, buf, n2 + (size_t)l * DM);
        gemm(EP_STORE,    ff1, xn, W1, M, DFF, DM, DM, DM, DFF);
        gemm(EP_SILU_MUL, ff2, xn, W2, M, DFF, DM, DM, DM, DFF, ff1, DFF);
        gemm(EP_ADD,      buf, ff2, W3, M, DM, DFF, DFF, DFF, DM, buf, DM);
    };

    for (int l = 0; l < NLAYER; l++) {
        if (l & 1) {
            // Mixture-of-Depths: route top-CAP tokens (descending score order)
            score_kernel<<<NTOK, 256>>>(scores, x, router + (size_t)l * DM);
            topk_sort_kernel<<<BATCH, TSEQ>>>(idxb, scores);
            gather_kernel<<<BATCH * CAP, 256>>>(xs, x, idxb);
            run_block(xs, BATCH * CAP, CAP, l);
            scatter_kernel<<<BATCH * CAP, 256>>>(x, xs, idxb);
        } else {
            run_block(x, NTOK, TSEQ, l);
        }
    }

    // kNN memory retrieval
    gemm(EP_STORE, xn,  x,  mem_q,    NTOK, DM,     DM, DM, DM, DM);      // q = x @ mem_q^T
    gemm(EP_STORE, sim, xn, mem_keys, NTOK, NSLOTS, DM, DM, DM, NSLOTS);  // sim (unscaled)
    memtopk_kernel<<<NTOK, 128>>>(retrp, sim, mem_vals);
    gemm(EP_STORE, retr, retrp, mem_out, NTOK, DM, DM, DM, DM, DM);
    // gate MLP: g1 = x@W1a^T + retr@W1b^T + b1   (gate_w1 is [512, 2048])
    gemm(EP_STORE,    g1, x,    gate_w1,        NTOK, 512, DM, DM, 2 * DM, 512);
    gemm(EP_ADD_BIAS, g1, retr, gate_w1 + DM,   NTOK, 512, DM, DM, 2 * DM, 512, g1, 512, gate_b1);
    gate_kernel<<<NTOK, 256>>>(x, g1, gate_w2, gate_b2, retr);

    // latent reasoning iterations
    for (int it = 0; it < 4; it++) {
        rms_kernel<<<NTOK, 256>>>(xn, x, lat_norm);
        gemm(EP_GELU, h1, xn, lat_w1, NTOK, 2 * DM, DM, DM, DM, 2 * DM);
        gemm(EP_ADD,  x,  h1, lat_w2, NTOK, DM, 2 * DM, 2 * DM, 2 * DM, DM, x, DM);
    }

    // final norm + LM head
    rms_kernel<<<NTOK, 256>>>(xn, x, fin_norm);
    gemm(EP_STORE, out, xn, lm_head, NTOK, 50257, DM, DM, DM, 50257);
}

// round 13
// speedup vs baseline: 1.3953x; 1.1863x over previous
#include <cuda_runtime.h>
#include <cuda_bf16.h>
#include <math.h>

// ---------------- problem constants ----------------
#define BATCH   2
#define TSEQ    1024
#define DM      1024
#define NHEAD   16
#define HD      64
#define NLAYER  12
#define DFF     2730
#define CAP     128
#define NSLOTS  128
#define TOPK    8
#define NTOK    (BATCH*TSEQ)      // 2048

// ---------------- scratch (device globals; no allocation allowed) ----------------
__device__ float g_x    [NTOK*DM];
__device__ float g_xn   [NTOK*DM];
__device__ float g_qkv  [NTOK*3*DM];
__device__ float g_attn [NTOK*DM];
__device__ float g_ff1  [NTOK*DFF];
__device__ float g_ff2  [NTOK*DFF];
__device__ float g_retr [NTOK*DM];
__device__ float g_retrp[NTOK*DM];
__device__ float g_sim  [NTOK*NSLOTS];
__device__ float g_g1   [NTOK*512];
__device__ float g_h1   [NTOK*2048];
__device__ float g_xs   [BATCH*CAP*DM];
__device__ float g_scores[NTOK];
__device__ int   g_idx  [BATCH*CAP];

// ---------------- helpers ----------------
__device__ __forceinline__ float warpSum(float v){
    #pragma unroll
    for (int o=16;o>0;o>>=1) v += __shfl_xor_sync(0xffffffffu, v, o);
    return v;
}
__device__ __forceinline__ float warpMax(float v){
    #pragma unroll
    for (int o=16;o>0;o>>=1) v = fmaxf(v, __shfl_xor_sync(0xffffffffu, v, o));
    return v;
}
__device__ __forceinline__ float blockSum(float v, float* red){
    int lane = threadIdx.x & 31, w = threadIdx.x >> 5, nw = blockDim.x >> 5;
    v = warpSum(v);
    if (lane == 0) red[w] = v;
    __syncthreads();
    float r = (w == 0 && lane < nw) ? red[lane] : 0.f;
    if (w == 0) r = warpSum(r);
    if (threadIdx.x == 0) red[0] = r;
    __syncthreads();
    float out = red[0];
    __syncthreads();
    return out;
}
__device__ __forceinline__ float blockMax(float v, float* red){
    int lane = threadIdx.x & 31, w = threadIdx.x >> 5, nw = blockDim.x >> 5;
    v = warpMax(v);
    if (lane == 0) red[w] = v;
    __syncthreads();
    float r = (w == 0 && lane < nw) ? red[lane] : -INFINITY;
    if (w == 0) r = warpMax(r);
    if (threadIdx.x == 0) red[0] = r;
    __syncthreads();
    float out = red[0];
    __syncthreads();
    return out;
}
__device__ __forceinline__ float gelu_f(float v){
    return 0.5f * v * (1.f + erff(v * 0.70710678118654752f));
}
__device__ __forceinline__ float silu_f(float v){
    return v / (1.f + expf(-v));
}

// ---------------- bf16 hi/lo split + mma ----------------
// v = hi + lo + O(2^-18 |v|): hi = bf16(v), lo = bf16(v - hi)
__device__ __forceinline__ void split2_bf16(float x, float y, unsigned &hi2, unsigned &lo2){
    __nv_bfloat16 hx = __float2bfloat16_rn(x);
    __nv_bfloat16 hy = __float2bfloat16_rn(y);
    __nv_bfloat16 lx = __float2bfloat16_rn(x - __bfloat162float(hx));
    __nv_bfloat16 ly = __float2bfloat16_rn(y - __bfloat162float(hy));
    __nv_bfloat162 h; h.x = hx; h.y = hy;
    __nv_bfloat162 l; l.x = lx; l.y = ly;
    hi2 = *reinterpret_cast<unsigned*>(&h);
    lo2 = *reinterpret_cast<unsigned*>(&l);
}
__device__ __forceinline__ void mma16(float* c, const unsigned* a, const unsigned* b){
    asm volatile(
        "mma.sync.aligned.m16n8k16.row.col.f32.bf16.bf16.f32 "
        "{%0,%1,%2,%3}, {%4,%5,%6,%7}, {%8,%9}, {%0,%1,%2,%3};"
        : "+f"(c[0]), "+f"(c[1]), "+f"(c[2]), "+f"(c[3])
        : "r"(a[0]), "r"(a[1]), "r"(a[2]), "r"(a[3]), "r"(b[0]), "r"(b[1]));
}

// guarded float4 row load (handles unaligned ld and K tail)
__device__ __forceinline__ float4 ldg_row(const float* __restrict__ P, int ld, bool al4,
                                          int row, int gk, int RM, int K)
{
    float4 v = make_float4(0.f, 0.f, 0.f, 0.f);
    if (row < RM) {
        const float* p = P + (size_t)row * ld + gk;
        if (al4 && gk + 3 < K) v = *(const float4*)p;
        else {
            if (gk + 0 < K) v.x = p[0];
            if (gk + 1 < K) v.y = p[1];
            if (gk + 2 < K) v.z = p[2];
            if (gk + 3 < K) v.w = p[3];
        }
    }
    return v;
}

// ---------------- tensor-core GEMM: C[M,N] = epilogue(A[M,K] @ B[N,K]^T) ----------------
// 3-term bf16 hi/lo (fp32-near accuracy), m16n8k16 (2x flops/instr vs tf32 k8),
// register-staged double buffering, 2 blocks/SM.
// EP: 0 store, 1 C=res+acc, 2 C=gelu(acc), 3 C=res+acc+bias[n], 4 C=silu(res)*acc
#define EP_STORE    0
#define EP_ADD      1
#define EP_GELU     2
#define EP_ADD_BIAS 3
#define EP_SILU_MUL 4

template<int EP>
__global__ __launch_bounds__(256, 2)
void tgemm_abt(float* __restrict__ C, const float* __restrict__ A,
               const float* __restrict__ B, int M, int N, int K,
               int lda, int ldb, int ldc,
               const float* __restrict__ res, int ldres,
               const float* __restrict__ bias)
{
    // [m][kc] layout, kc = bf16x2 column (K/2), row stride 9 uint32:
    // frag loads (9r+tg) mod 32 conflict-free across the warp.
    __shared__ unsigned Ah[128][9], Al[128][9], Bh[128][9], Bl[128][9];
    const int bm = blockIdx.y * 128, bn = blockIdx.x * 128;
    const int tid  = threadIdx.x;
    const int warp = tid >> 5, lane = tid & 31;
    const int wm = (warp & 1) * 64;      // 2 warps along M
    const int wn = (warp >> 1) * 32;     // 4 warps along N
    const int g  = lane >> 2, tg = lane & 3;
    const bool a4 = ((lda & 3) == 0);
    const bool b4 = ((ldb & 3) == 0);
    const int lrow0 = tid >> 2, lvq0 = tid & 3;          // i=0 fill slot
    const int lrow1 = (tid + 256) >> 2, lvq1 = tid & 3;  // i=1 fill slot

    float acc[4][4][4];
    #pragma unroll
    for (int mi = 0; mi < 4; mi++)
        #pragma unroll
        for (int ni = 0; ni < 4; ni++)
            #pragma unroll
            for (int cc = 0; cc < 4; cc++) acc[mi][ni][cc] = 0.f;

    // prologue: stage tile k0=0 in registers
    float4 sA[2], sB[2];
    sA[0] = ldg_row(A, lda, a4, bm + lrow0, lvq0 * 4, M, K);
    sB[0] = ldg_row(B, ldb, b4, bn + lrow0, lvq0 * 4, N, K);
    sA[1] = ldg_row(A, lda, a4, bm + lrow1, lvq1 * 4, M, K);
    sB[1] = ldg_row(B, ldb, b4, bn + lrow1, lvq1 * 4, N, K);

    for (int k0 = 0; k0 < K; k0 += 16) {
        // fill smem from staged regs, splitting hi/lo once per element
        #pragma unroll
        for (int i = 0; i < 2; i++) {
            int row = (i == 0) ? lrow0 : lrow1;
            int vq  = (i == 0) ? lvq0  : lvq1;
            unsigned h0, l0, h1, l1;
            split2_bf16(sA[i].x, sA[i].y, h0, l0);
            split2_bf16(sA[i].z, sA[i].w, h1, l1);
            Ah[row][vq * 2] = h0;  Ah[row][vq * 2 + 1] = h1;
            Al[row][vq * 2] = l0;  Al[row][vq * 2 + 1] = l1;
            split2_bf16(sB[i].x, sB[i].y, h0, l0);
            split2_bf16(sB[i].z, sB[i].w, h1, l1);
            Bh[row][vq * 2] = h0;  Bh[row][vq * 2 + 1] = h1;
            Bl[row][vq * 2] = l0;  Bl[row][vq * 2 + 1] = l1;
        }
        __syncthreads();

        // prefetch next tile into regs; LDG latency overlaps compute below
        if (k0 + 16 < K) {
            int gk0 = k0 + 16 + lvq0 * 4;
            int gk1 = k0 + 16 + lvq1 * 4;
            sA[0] = ldg_row(A, lda, a4, bm + lrow0, gk0, M, K);
            sB[0] = ldg_row(B, ldb, b4, bn + lrow0, gk0, N, K);
            sA[1] = ldg_row(A, lda, a4, bm + lrow1, gk1, M, K);
            sB[1] = ldg_row(B, ldb, b4, bn + lrow1, gk1, N, K);
        }

        // one m16n8k16 step covers the whole 16-K tile
        unsigned bhiF[4][2], bloF[4][2];
        #pragma unroll
        for (int ni = 0; ni < 4; ni++) {
            int col = wn + ni * 8 + g;
            bhiF[ni][0] = Bh[col][tg];
            bhiF[ni][1] = Bh[col][tg + 4];
            bloF[ni][0] = Bl[col][tg];
            bloF[ni][1] = Bl[col][tg + 4];
        }
        #pragma unroll
        for (int mi = 0; mi < 4; mi++) {
            int r = wm + mi * 16 + g;
            unsigned ah[4], al[4];
            ah[0] = Ah[r][tg];     ah[1] = Ah[r + 8][tg];
            ah[2] = Ah[r][tg + 4]; ah[3] = Ah[r + 8][tg + 4];
            al[0] = Al[r][tg];     al[1] = Al[r + 8][tg];
            al[2] = Al[r][tg + 4]; al[3] = Al[r + 8][tg + 4];
            #pragma unroll
            for (int ni = 0; ni < 4; ni++) mma16(acc[mi][ni], ah, bhiF[ni]);
            #pragma unroll
            for (int ni = 0; ni < 4; ni++) mma16(acc[mi][ni], ah, bloF[ni]);
            #pragma unroll
            for (int ni = 0; ni < 4; ni++) mma16(acc[mi][ni], al, bhiF[ni]);
        }
        __syncthreads();
    }

    // epilogue
    #pragma unroll
    for (int mi = 0; mi < 4; mi++) {
        int row0 = bm + wm + mi * 16 + g;
        #pragma unroll
        for (int ni = 0; ni < 4; ni++) {
            int col0 = bn + wn + ni * 8 + tg * 2;
            #pragma unroll
            for (int cc = 0; cc < 4; cc++) {
                int gm = row0 + (cc >> 1) * 8;
                int gn = col0 + (cc & 1);
                if (gm < M && gn < N) {
                    float v = acc[mi][ni][cc];
                    if (EP == EP_ADD)           v += res[(size_t)gm * ldres + gn];
                    else if (EP == EP_GELU)     v = gelu_f(v);
                    else if (EP == EP_ADD_BIAS) v += res[(size_t)gm * ldres + gn] + bias[gn];
                    else if (EP == EP_SILU_MUL) v *= silu_f(res[(size_t)gm * ldres + gn]);
                    C[(size_t)gm * ldc + gn] = v;
                }
            }
        }
    }
}

// ---------------- embed + positional ----------------
__global__ void embed_kernel(float* __restrict__ x, const int* __restrict__ ids,
                             const float* __restrict__ emb, const float* __restrict__ pos)
{
    int row = blockIdx.x;          // b*T + t
    int t   = row & (TSEQ - 1);
    int id  = ids[row];
    int tid = threadIdx.x;
    #pragma unroll
    for (int i = 0; i < 4; i++) {
        int d = tid + i * 256;
        x[(size_t)row * DM + d] = emb[(size_t)id * DM + d] + pos[(size_t)t * DM + d];
    }
}

// ---------------- rmsnorm ----------------
__global__ void rms_kernel(float* __restrict__ y, const float* __restrict__ x,
                           const float* __restrict__ w)
{
    __shared__ float red[8];
    int row = blockIdx.x, tid = threadIdx.x;
    const float* xr = x + (size_t)row * DM;
    float s = 0.f;
    #pragma unroll
    for (int i = 0; i < 4; i++) { float v = xr[tid + i * 256]; s = fmaf(v, v, s); }
    s = blockSum(s, red);
    float r = rsqrtf(s * (1.f / DM) + 1e-6f);
    #pragma unroll
    for (int i = 0; i < 4; i++) {
        int d = tid + i * 256;
        y[(size_t)row * DM + d] = xr[d] * r * w[d];
    }
}

// ---------------- attention: one block per (query t, head h, batch b) ----------------
__global__ void attn_kernel(const float* __restrict__ qkv, float* __restrict__ out, int S)
{
    const int t = blockIdx.x, h = blockIdx.y, b = blockIdx.z;
    const int tid = threadIdx.x;   // 128 threads
    __shared__ float qsh[HD];
    __shared__ float sc[TSEQ];
    __shared__ float red[8];
    __shared__ float obuf[HD];
    const float* base = qkv + (size_t)b * S * (3 * DM);
    if (tid < HD) qsh[tid] = base[(size_t)t * (3 * DM) + h * HD + tid];
    __syncthreads();

    float lmax = -INFINITY;
    for (int j = tid; j <= t; j += 128) {
        const float* kr = base + (size_t)j * (3 * DM) + DM + h * HD;
        float s = 0.f;
        #pragma unroll
        for (int d = 0; d < HD; d++) s = fmaf(qsh[d], kr[d], s);
        s *= 0.125f;                 // 1/sqrt(64)
        sc[j] = s;
        lmax = fmaxf(lmax, s);
    }
    float m = blockMax(lmax, red);
    float lsum = 0.f;
    for (int j = tid; j <= t; j += 128) {
        float p = expf(sc[j] - m);
        sc[j] = p;
        lsum += p;
    }
    float ssum = blockSum(lsum, red);
    float inv = 1.f / ssum;

    const int d = tid & 63, half = tid >> 6;
    const float* vb = base + 2 * DM + h * HD + d;
    float o = 0.f;
    for (int j = half; j <= t; j += 2)
        o = fmaf(sc[j], vb[(size_t)j * (3 * DM)], o);
    if (half == 1) obuf[d] = o;
    __syncthreads();
    if (half == 0)
        out[((size_t)(b * S + t)) * DM + h * HD + d] = (o + obuf[d]) * inv;
}

// ---------------- MoD: router scores ----------------
__global__ void score_kernel(float* __restrict__ scores, const float* __restrict__ x,
                             const float* __restrict__ r)
{
    __shared__ float red[8];
    int row = blockIdx.x, tid = threadIdx.x;
    const float* xr = x + (size_t)row * DM;
    float s = 0.f;
    #pragma unroll
    for (int i = 0; i < 4; i++) { int d = tid + i * 256; s = fmaf(xr[d], r[d], s); }
    s = blockSum(s, red);
    if (tid == 0) scores[row] = s;
}

// ---------------- MoD: exact top-128 descending (bitonic sort, tie = smaller idx) ----------------
__global__ void topk_sort_kernel(int* __restrict__ idx, const float* __restrict__ scores)
{
    int b = blockIdx.x, tid = threadIdx.x;     // 1024 threads
    __shared__ float s[TSEQ];
    __shared__ int   si[TSEQ];
    s[tid]  = scores[b * TSEQ + tid];
    si[tid] = tid;
    __syncthreads();
    for (int k = 2; k <= TSEQ; k <<= 1) {
        for (int j = k >> 1; j > 0; j >>= 1) {
            int ixj = tid ^ j;
            if (ixj > tid) {
                bool desc = ((tid & k) == 0);
                float s1 = s[tid], s2 = s[ixj];
                int   i1 = si[tid], i2 = si[ixj];
                bool firstBetter = (s1 > s2) || (s1 == s2 && i1 < i2);
                if (desc != firstBetter) {
                    s[tid] = s2; s[ixj] = s1;
                    si[tid] = i2; si[ixj] = i1;
                }
            }
            __syncthreads();
        }
    }
    if (tid < CAP) idx[b * CAP + tid] = si[tid];
}

__global__ void gather_kernel(float* __restrict__ xs, const float* __restrict__ x,
                              const int* __restrict__ idx)
{
    int row = blockIdx.x;            // b*CAP + j
    int b = row >> 7;
    int src = b * TSEQ + idx[row];
    int tid = threadIdx.x;
    #pragma unroll
    for (int i = 0; i < 4; i++) {
        int d = tid + i * 256;
        xs[(size_t)row * DM + d] = x[(size_t)src * DM + d];
    }
}
__global__ void scatter_kernel(float* __restrict__ x, const float* __restrict__ xs,
                               const int* __restrict__ idx)
{
    int row = blockIdx.x;
    int b = row >> 7;
    int dst = b * TSEQ + idx[row];
    int tid = threadIdx.x;
    #pragma unroll
    for (int i = 0; i < 4; i++) {
        int d = tid + i * 256;
        x[(size_t)dst * DM + d] = xs[(size_t)row * DM + d];
    }
}

// ---------------- memory: top-8 + softmax + weighted value gather ----------------
__global__ void memtopk_kernel(float* __restrict__ outp, const float* __restrict__ sim,
                               const float* __restrict__ mem_values)
{
    int row = blockIdx.x, tid = threadIdx.x;   // 128 threads
    __shared__ float sv[NSLOTS];
    __shared__ float av[NSLOTS];
    __shared__ int   ai[NSLOTS];
    __shared__ float wk[TOPK];
    __shared__ int   ik[TOPK];
    sv[tid] = sim[(size_t)row * NSLOTS + tid] * 0.03125f;   // / sqrt(1024)
    __syncthreads();
    for (int k = 0; k < TOPK; k++) {
        av[tid] = sv[tid]; ai[tid] = tid;
        __syncthreads();
        for (int s = 64; s > 0; s >>= 1) {
            if (tid < s) {
                float v2 = av[tid + s]; int i2 = ai[tid + s];
                if (v2 > av[tid] || (v2 == av[tid] && i2 < ai[tid])) { av[tid] = v2; ai[tid] = i2; }
            }
            __syncthreads();
        }
        if (tid == 0) { wk[k] = av[0]; ik[k] = ai[0]; sv[ai[0]] = -INFINITY; }
        __syncthreads();
    }
    if (tid == 0) {
        float mx = wk[0], ssum = 0.f, e[TOPK];
        #pragma unroll
        for (int k = 0; k < TOPK; k++) { e[k] = expf(wk[k] - mx); ssum += e[k]; }
        #pragma unroll
        for (int k = 0; k < TOPK; k++) wk[k] = e[k] / ssum;
    }
    __syncthreads();
    #pragma unroll
    for (int i = 0; i < 8; i++) {
        int d = tid + i * 128;
        float o = 0.f;
        #pragma unroll
        for (int k = 0; k < TOPK; k++)
            o = fmaf(wk[k], mem_values[(size_t)ik[k] * DM + d], o);
        outp[(size_t)row * DM + d] = o;
    }
}

// ---------------- gate: gelu(g1)@w2 + b2 -> sigmoid -> x += gate*retr ----------------
__global__ void gate_kernel(float* __restrict__ x, const float* __restrict__ g1,
                            const float* __restrict__ gw2, const float* __restrict__ gb2,
                            const float* __restrict__ retr)
{
    __shared__ float red[8];
    int row = blockIdx.x, tid = threadIdx.x;   // 256
    float s = 0.f;
    for (int j = tid; j < 512; j += 256) {
        float v = g1[(size_t)row * 512 + j];
        s = fmaf(gelu_f(v), gw2[j], s);
    }
    s = blockSum(s, red);
    float gate = 1.f / (1.f + expf(-(s + gb2[0])));
    #pragma unroll
    for (int i = 0; i < 4; i++) {
        int d = tid + i * 256;
        size_t p = (size_t)row * DM + d;
        x[p] += gate * retr[p];
    }
}

// ---------------- host-side gemm dispatch ----------------
static void gemm(int ep, float* C, const float* A, const float* B,
                 int M, int N, int K, int lda, int ldb, int ldc,
                 const float* res = nullptr, int ldres = 0,
                 const float* bias = nullptr)
{
    dim3 grid((N + 127) / 128, (M + 127) / 128);
    switch (ep) {
    case EP_STORE:    tgemm_abt<EP_STORE>   <<<grid,256>>>(C,A,B,M,N,K,lda,ldb,ldc,res,ldres,bias); break;
    case EP_ADD:      tgemm_abt<EP_ADD>     <<<grid,256>>>(C,A,B,M,N,K,lda,ldb,ldc,res,ldres,bias); break;
    case EP_GELU:     tgemm_abt<EP_GELU>    <<<grid,256>>>(C,A,B,M,N,K,lda,ldb,ldc,res,ldres,bias); break;
    case EP_ADD_BIAS: tgemm_abt<EP_ADD_BIAS><<<grid,256>>>(C,A,B,M,N,K,lda,ldb,ldc,res,ldres,bias); break;
    case EP_SILU_MUL: tgemm_abt<EP_SILU_MUL><<<grid,256>>>(C,A,B,M,N,K,lda,ldb,ldc,res,ldres,bias); break;
    }
}

extern "C" void kernel_launch(void* const* d_in, const int* in_sizes, int n_in,
                              void* d_out, int out_size)
{
    const int*   ids       = (const int*)  d_in[0];
    const float* embed     = (const float*)d_in[1];
    const float* pos       = (const float*)d_in[2];
    const float* n1        = (const float*)d_in[3];
    const float* qkvw      = (const float*)d_in[4];
    const float* outw      = (const float*)d_in[5];
    const float* n2        = (const float*)d_in[6];
    const float* w1        = (const float*)d_in[7];
    const float* w2        = (const float*)d_in[8];
    const float* w3        = (const float*)d_in[9];
    const float* router    = (const float*)d_in[10];
    const float* mem_keys  = (const float*)d_in[11];
    const float* mem_vals  = (const float*)d_in[12];
    const float* mem_q     = (const float*)d_in[13];
    const float* mem_out   = (const float*)d_in[14];
    const float* gate_w1   = (const float*)d_in[15];
    const float* gate_b1   = (const float*)d_in[16];
    const float* gate_w2   = (const float*)d_in[17];
    const float* gate_b2   = (const float*)d_in[18];
    const float* lat_norm  = (const float*)d_in[19];
    const float* lat_w1    = (const float*)d_in[20];
    const float* lat_w2    = (const float*)d_in[21];
    const float* fin_norm  = (const float*)d_in[22];
    const float* lm_head   = (const float*)d_in[23];
    float* out = (float*)d_out;

    float *x,*xn,*qkvb,*attnb,*ff1,*ff2,*retr,*retrp,*sim,*g1,*h1,*xs,*scores;
    int *idxb;
    cudaGetSymbolAddress((void**)&x,     g_x);
    cudaGetSymbolAddress((void**)&xn,    g_xn);
    cudaGetSymbolAddress((void**)&qkvb,  g_qkv);
    cudaGetSymbolAddress((void**)&attnb, g_attn);
    cudaGetSymbolAddress((void**)&ff1,   g_ff1);
    cudaGetSymbolAddress((void**)&ff2,   g_ff2);
    cudaGetSymbolAddress((void**)&retr,  g_retr);
    cudaGetSymbolAddress((void**)&retrp, g_retrp);
    cudaGetSymbolAddress((void**)&sim,   g_sim);
    cudaGetSymbolAddress((void**)&g1,    g_g1);
    cudaGetSymbolAddress((void**)&h1,    g_h1);
    cudaGetSymbolAddress((void**)&xs,    g_xs);
    cudaGetSymbolAddress((void**)&scores,g_scores);
    cudaGetSymbolAddress((void**)&idxb,  g_idx);

    // x = embed[ids] + pos
    embed_kernel<<<NTOK, 256>>>(x, ids, embed, pos);

    // transformer block applied to a contiguous buffer of M rows (S tokens per batch)
    auto run_block = [&](float* buf, int M, int S, int l) {
        const float* Wqkv = qkvw + (size_t)l * 3 * DM * DM;
        const float* Wout = outw + (size_t)l * DM * DM;
        const float* W1   = w1   + (size_t)l * DFF * DM;
        const float* W2   = w2   + (size_t)l * DFF * DM;
        const float* W3   = w3   + (size_t)l * DM * DFF;
        rms_kernel<<<M, 256>>>(xn, buf, n1 + (size_t)l * DM);
        gemm(EP_STORE, qkvb, xn, Wqkv, M, 3 * DM, DM, DM, DM, 3 * DM);
        attn_kernel<<<dim3(S, NHEAD, BATCH), 128>>>(qkvb, attnb, S);
        gemm(EP_ADD, buf, attnb, Wout, M, DM, DM, DM, DM, DM, buf, DM);
        rms_kernel<<<M, 256>>>(xn, buf, n2 + (size_t)l * DM);
        gemm(EP_STORE,    ff1, xn, W1, M, DFF, DM, DM, DM, DFF);
        gemm(EP_SILU_MUL, ff2, xn, W2, M, DFF, DM, DM, DM, DFF, ff1, DFF);
        gemm(EP_ADD,      buf, ff2, W3, M, DM, DFF, DFF, DFF, DM, buf, DM);
    };

    for (int l = 0; l < NLAYER; l++) {
        if (l & 1) {
            // Mixture-of-Depths: route top-CAP tokens (descending score order)
            score_kernel<<<NTOK, 256>>>(scores, x, router + (size_t)l * DM);
            topk_sort_kernel<<<BATCH, TSEQ>>>(idxb, scores);
            gather_kernel<<<BATCH * CAP, 256>>>(xs, x, idxb);
            run_block(xs, BATCH * CAP, CAP, l);
            scatter_kernel<<<BATCH * CAP, 256>>>(x, xs, idxb);
        } else {
            run_block(x, NTOK, TSEQ, l);
        }
    }

    // kNN memory retrieval
    gemm(EP_STORE, xn,  x,  mem_q,    NTOK, DM,     DM, DM, DM, DM);      // q = x @ mem_q^T
    gemm(EP_STORE, sim, xn, mem_keys, NTOK, NSLOTS, DM, DM, DM, NSLOTS);  // sim (unscaled)
    memtopk_kernel<<<NTOK, 128>>>(retrp, sim, mem_vals);
    gemm(EP_STORE, retr, retrp, mem_out, NTOK, DM, DM, DM, DM, DM);
    // gate MLP: g1 = x@W1a^T + retr@W1b^T + b1   (gate_w1 is [512, 2048])
    gemm(EP_STORE,    g1, x,    gate_w1,        NTOK, 512, DM, DM, 2 * DM, 512);
    gemm(EP_ADD_BIAS, g1, retr, gate_w1 + DM,   NTOK, 512, DM, DM, 2 * DM, 512, g1, 512, gate_b1);
    gate_kernel<<<NTOK, 256>>>(x, g1, gate_w2, gate_b2, retr);

    // latent reasoning iterations
    for (int it = 0; it < 4; it++) {
        rms_kernel<<<NTOK, 256>>>(xn, x, lat_norm);
        gemm(EP_GELU, h1, xn, lat_w1, NTOK, 2 * DM, DM, DM, DM, 2 * DM);
        gemm(EP_ADD,  x,  h1, lat_w2, NTOK, DM, 2 * DM, 2 * DM, 2 * DM, DM, x, DM);
    }

    // final norm + LM head
    rms_kernel<<<NTOK, 256>>>(xn, x, fin_norm);
    gemm(EP_STORE, out, xn, lm_head, NTOK, 50257, DM, DM, DM, 50257);
}

// round 14
// speedup vs baseline: 2.3948x; 1.7163x over previous
#include <cuda_runtime.h>
#include <cuda_bf16.h>
#include <math.h>

// ---------------- problem constants ----------------
#define BATCH   2
#define TSEQ    1024
#define DM      1024
#define NHEAD   16
#define HD      64
#define NLAYER  12
#define DFF     2730
#define CAP     128
#define NSLOTS  128
#define TOPK    8
#define NTOK    (BATCH*TSEQ)      // 2048

// ---------------- scratch (device globals; no allocation allowed) ----------------
__device__ float g_x    [NTOK*DM];
__device__ float g_xn   [NTOK*DM];
__device__ float g_qkv  [NTOK*3*DM];
__device__ float g_attn [NTOK*DM];
__device__ float g_ff1  [NTOK*DFF];
__device__ float g_ff2  [NTOK*DFF];
__device__ float g_retr [NTOK*DM];
__device__ float g_retrp[NTOK*DM];
__device__ float g_sim  [NTOK*NSLOTS];
__device__ float g_g1   [NTOK*512];
__device__ float g_h1   [NTOK*2048];
__device__ float g_xs   [BATCH*CAP*DM];
__device__ float g_scores[NTOK];
__device__ int   g_idx  [BATCH*CAP];

// ---------------- helpers ----------------
__device__ __forceinline__ float warpSum(float v){
    #pragma unroll
    for (int o=16;o>0;o>>=1) v += __shfl_xor_sync(0xffffffffu, v, o);
    return v;
}
__device__ __forceinline__ float blockSum(float v, float* red){
    int lane = threadIdx.x & 31, w = threadIdx.x >> 5, nw = blockDim.x >> 5;
    v = warpSum(v);
    if (lane == 0) red[w] = v;
    __syncthreads();
    float r = (w == 0 && lane < nw) ? red[lane] : 0.f;
    if (w == 0) r = warpSum(r);
    if (threadIdx.x == 0) red[0] = r;
    __syncthreads();
    float out = red[0];
    __syncthreads();
    return out;
}
__device__ __forceinline__ float gelu_f(float v){
    return 0.5f * v * (1.f + erff(v * 0.70710678118654752f));
}
__device__ __forceinline__ float silu_f(float v){
    return v / (1.f + expf(-v));
}

// ---------------- bf16 hi/lo split + mma ----------------
__device__ __forceinline__ void split2_bf16(float x, float y, unsigned &hi2, unsigned &lo2){
    __nv_bfloat16 hx = __float2bfloat16_rn(x);
    __nv_bfloat16 hy = __float2bfloat16_rn(y);
    __nv_bfloat16 lx = __float2bfloat16_rn(x - __bfloat162float(hx));
    __nv_bfloat16 ly = __float2bfloat16_rn(y - __bfloat162float(hy));
    __nv_bfloat162 h; h.x = hx; h.y = hy;
    __nv_bfloat162 l; l.x = lx; l.y = ly;
    hi2 = *reinterpret_cast<unsigned*>(&h);
    lo2 = *reinterpret_cast<unsigned*>(&l);
}
__device__ __forceinline__ void mma16(float* c, const unsigned* a, const unsigned* b){
    asm volatile(
        "mma.sync.aligned.m16n8k16.row.col.f32.bf16.bf16.f32 "
        "{%0,%1,%2,%3}, {%4,%5,%6,%7}, {%8,%9}, {%0,%1,%2,%3};"
        : "+f"(c[0]), "+f"(c[1]), "+f"(c[2]), "+f"(c[3])
        : "r"(a[0]), "r"(a[1]), "r"(a[2]), "r"(a[3]), "r"(b[0]), "r"(b[1]));
}

// guarded float4 row load (handles unaligned ld and K tail)
__device__ __forceinline__ float4 ldg_row(const float* __restrict__ P, int ld, bool al4,
                                          int row, int gk, int RM, int K)
{
    float4 v = make_float4(0.f, 0.f, 0.f, 0.f);
    if (row < RM) {
        const float* p = P + (size_t)row * ld + gk;
        if (al4 && gk + 3 < K) v = *(const float4*)p;
        else {
            if (gk + 0 < K) v.x = p[0];
            if (gk + 1 < K) v.y = p[1];
            if (gk + 2 < K) v.z = p[2];
            if (gk + 3 < K) v.w = p[3];
        }
    }
    return v;
}

// ---------------- tensor-core GEMM: C[M,N] = epilogue(A[M,K] @ B[N,K]^T) ----------------
// 3-term bf16 hi/lo, m16n8k16, BK=32 (overhead amortized), split-at-prefetch staging.
#define EP_STORE    0
#define EP_ADD      1
#define EP_GELU     2
#define EP_ADD_BIAS 3
#define EP_SILU_MUL 4

template<int EP>
__global__ __launch_bounds__(256, 2)
void tgemm_abt(float* __restrict__ C, const float* __restrict__ A,
               const float* __restrict__ B, int M, int N, int K,
               int lda, int ldb, int ldc,
               const float* __restrict__ res, int ldres,
               const float* __restrict__ bias)
{
    // [m][kc] bf16x2 layout, 16 kc columns used, stride 20 -> frag LDS conflict-free
    __shared__ unsigned Ah[128][20], Al[128][20], Bh[128][20], Bl[128][20];
    const int bm = blockIdx.y * 128, bn = blockIdx.x * 128;
    const int tid  = threadIdx.x;
    const int warp = tid >> 5, lane = tid & 31;
    const int wm = (warp & 1) * 64;      // 2 warps along M
    const int wn = (warp >> 1) * 32;     // 4 warps along N
    const int g  = lane >> 2, tg = lane & 3;
    const bool a4 = ((lda & 3) == 0);
    const bool b4 = ((ldb & 3) == 0);
    const int frow = tid >> 1;           // fill row 0..127
    const int kcb  = (tid & 1) * 8;      // kc base (0 or 8)
    const int kgb  = (tid & 1) * 16;     // gmem K base (0 or 16)

    float acc[4][4][4];
    #pragma unroll
    for (int mi = 0; mi < 4; mi++)
        #pragma unroll
        for (int ni = 0; ni < 4; ni++)
            #pragma unroll
            for (int cc = 0; cc < 4; cc++) acc[mi][ni][cc] = 0.f;

    unsigned sAh[8], sAl[8], sBh[8], sBl[8];   // staged split tile (32 regs)
    // prologue: load + split tile 0
    #pragma unroll
    for (int q = 0; q < 4; q++) {
        float4 a = ldg_row(A, lda, a4, bm + frow, kgb + q * 4, M, K);
        split2_bf16(a.x, a.y, sAh[q*2],   sAl[q*2]);
        split2_bf16(a.z, a.w, sAh[q*2+1], sAl[q*2+1]);
        float4 b = ldg_row(B, ldb, b4, bn + frow, kgb + q * 4, N, K);
        split2_bf16(b.x, b.y, sBh[q*2],   sBl[q*2]);
        split2_bf16(b.z, b.w, sBh[q*2+1], sBl[q*2+1]);
    }

    for (int k0 = 0; k0 < K; k0 += 32) {
        // fill smem from staged split regs
        #pragma unroll
        for (int j = 0; j < 8; j++) {
            Ah[frow][kcb + j] = sAh[j];
            Al[frow][kcb + j] = sAl[j];
            Bh[frow][kcb + j] = sBh[j];
            Bl[frow][kcb + j] = sBl[j];
        }
        __syncthreads();

        // prefetch + split next tile (LDG latency overlaps MMA section)
        if (k0 + 32 < K) {
            #pragma unroll
            for (int q = 0; q < 4; q++) {
                float4 a = ldg_row(A, lda, a4, bm + frow, k0 + 32 + kgb + q * 4, M, K);
                split2_bf16(a.x, a.y, sAh[q*2],   sAl[q*2]);
                split2_bf16(a.z, a.w, sAh[q*2+1], sAl[q*2+1]);
                float4 b = ldg_row(B, ldb, b4, bn + frow, k0 + 32 + kgb + q * 4, N, K);
                split2_bf16(b.x, b.y, sBh[q*2],   sBl[q*2]);
                split2_bf16(b.z, b.w, sBh[q*2+1], sBl[q*2+1]);
            }
        }

        // two k16 substeps
        #pragma unroll
        for (int ks = 0; ks < 2; ks++) {
            const int c0 = ks * 8;
            unsigned bhiF[4][2], bloF[4][2];
            #pragma unroll
            for (int ni = 0; ni < 4; ni++) {
                int col = wn + ni * 8 + g;
                bhiF[ni][0] = Bh[col][c0 + tg];
                bhiF[ni][1] = Bh[col][c0 + tg + 4];
                bloF[ni][0] = Bl[col][c0 + tg];
                bloF[ni][1] = Bl[col][c0 + tg + 4];
            }
            #pragma unroll
            for (int mi = 0; mi < 4; mi++) {
                int r = wm + mi * 16 + g;
                unsigned ah[4], al[4];
                ah[0] = Ah[r][c0 + tg];     ah[1] = Ah[r + 8][c0 + tg];
                ah[2] = Ah[r][c0 + tg + 4]; ah[3] = Ah[r + 8][c0 + tg + 4];
                al[0] = Al[r][c0 + tg];     al[1] = Al[r + 8][c0 + tg];
                al[2] = Al[r][c0 + tg + 4]; al[3] = Al[r + 8][c0 + tg + 4];
                #pragma unroll
                for (int ni = 0; ni < 4; ni++) mma16(acc[mi][ni], ah, bhiF[ni]);
                #pragma unroll
                for (int ni = 0; ni < 4; ni++) mma16(acc[mi][ni], ah, bloF[ni]);
                #pragma unroll
                for (int ni = 0; ni < 4; ni++) mma16(acc[mi][ni], al, bhiF[ni]);
            }
        }
        __syncthreads();
    }

    // epilogue
    #pragma unroll
    for (int mi = 0; mi < 4; mi++) {
        int row0 = bm + wm + mi * 16 + g;
        #pragma unroll
        for (int ni = 0; ni < 4; ni++) {
            int col0 = bn + wn + ni * 8 + tg * 2;
            #pragma unroll
            for (int cc = 0; cc < 4; cc++) {
                int gm = row0 + (cc >> 1) * 8;
                int gn = col0 + (cc & 1);
                if (gm < M && gn < N) {
                    float v = acc[mi][ni][cc];
                    if (EP == EP_ADD)           v += res[(size_t)gm * ldres + gn];
                    else if (EP == EP_GELU)     v = gelu_f(v);
                    else if (EP == EP_ADD_BIAS) v += res[(size_t)gm * ldres + gn] + bias[gn];
                    else if (EP == EP_SILU_MUL) v *= silu_f(res[(size_t)gm * ldres + gn]);
                    C[(size_t)gm * ldc + gn] = v;
                }
            }
        }
    }
}

// ---------------- embed + positional ----------------
__global__ void embed_kernel(float* __restrict__ x, const int* __restrict__ ids,
                             const float* __restrict__ emb, const float* __restrict__ pos)
{
    int row = blockIdx.x;
    int t   = row & (TSEQ - 1);
    int id  = ids[row];
    int tid = threadIdx.x;
    #pragma unroll
    for (int i = 0; i < 4; i++) {
        int d = tid + i * 256;
        x[(size_t)row * DM + d] = emb[(size_t)id * DM + d] + pos[(size_t)t * DM + d];
    }
}

// ---------------- rmsnorm ----------------
__global__ void rms_kernel(float* __restrict__ y, const float* __restrict__ x,
                           const float* __restrict__ w)
{
    __shared__ float red[8];
    int row = blockIdx.x, tid = threadIdx.x;
    const float* xr = x + (size_t)row * DM;
    float s = 0.f;
    #pragma unroll
    for (int i = 0; i < 4; i++) { float v = xr[tid + i * 256]; s = fmaf(v, v, s); }
    s = blockSum(s, red);
    float r = rsqrtf(s * (1.f / DM) + 1e-6f);
    #pragma unroll
    for (int i = 0; i < 4; i++) {
        int d = tid + i * 256;
        y[(size_t)row * DM + d] = xr[d] * r * w[d];
    }
}

// ---------------- flash attention: block = (64-query chunk, head, batch) ----------------
// smem tiles [64][68] f32: Qs (plain), Ks/Vs (float4-XOR-swizzled), Ps (per-warp P).
#define FA_STRIDE 68
#define FA_SMEM   (4 * 64 * FA_STRIDE * 4)   // 69632 bytes

__global__ __launch_bounds__(256)
void fattn_kernel(const float* __restrict__ qkv, float* __restrict__ out, int S)
{
    extern __shared__ float fsm[];
    float* Qs = fsm;
    float* Ks = fsm + 64 * FA_STRIDE;
    float* Vs = fsm + 2 * 64 * FA_STRIDE;
    float* Ps = fsm + 3 * 64 * FA_STRIDE;
    const int qc = blockIdx.x, h = blockIdx.y, b = blockIdx.z;
    const int tid = threadIdx.x, w = tid >> 5, lane = tid & 31;
    const int pair = lane & 3, g = lane >> 2;
    const int r0 = w * 8 + pair * 2;          // local query rows r0, r0+1
    const float* base = qkv + (size_t)b * S * 3072;

    // load Q chunk (plain layout)
    {
        int row = tid >> 2, c0 = (tid & 3) * 16;
        const float* src = base + (size_t)(qc * 64 + row) * 3072 + h * 64 + c0;
        #pragma unroll
        for (int q = 0; q < 4; q++)
            *(float4*)&Qs[row * FA_STRIDE + c0 + q * 4] = *(const float4*)(src + q * 4);
    }

    float o0[8], o1[8];
    #pragma unroll
    for (int j = 0; j < 8; j++) { o0[j] = 0.f; o1[j] = 0.f; }
    float m0 = -1e30f, m1 = -1e30f, l0 = 0.f, l1 = 0.f;

    for (int kt = 0; kt <= qc; kt++) {
        __syncthreads();   // protect Ks/Vs from prior tile readers
        // load K,V tiles, XOR-swizzled float4 columns
        {
            int row = tid >> 2, c0 = (tid & 3) * 16;
            const float* ksrc = base + (size_t)(kt * 64 + row) * 3072 + 1024 + h * 64 + c0;
            const float* vsrc = ksrc + 1024;
            int sw = (row >> 3) & 7;
            #pragma unroll
            for (int q = 0; q < 4; q++) {
                int d4 = (c0 >> 2) + q;
                int cc = d4 ^ sw;
                *(float4*)&Ks[row * FA_STRIDE + cc * 4] = *(const float4*)(ksrc + q * 4);
                *(float4*)&Vs[row * FA_STRIDE + cc * 4] = *(const float4*)(vsrc + q * 4);
            }
        }
        __syncthreads();

        // scores: lane owns rows (r0, r0+1) x keys (g*8 .. g*8+7)
        float s0[8], s1[8];
        #pragma unroll
        for (int j = 0; j < 8; j++) { s0[j] = 0.f; s1[j] = 0.f; }
        #pragma unroll 4
        for (int d4 = 0; d4 < 16; d4++) {
            float4 q0 = *(float4*)&Qs[r0 * FA_STRIDE + d4 * 4];
            float4 q1 = *(float4*)&Qs[(r0 + 1) * FA_STRIDE + d4 * 4];
            #pragma unroll
            for (int j = 0; j < 8; j++) {
                float4 kv = *(float4*)&Ks[(g * 8 + j) * FA_STRIDE + (d4 ^ g) * 4];
                s0[j] += q0.x*kv.x + q0.y*kv.y + q0.z*kv.z + q0.w*kv.w;
                s1[j] += q1.x*kv.x + q1.y*kv.y + q1.z*kv.z + q1.w*kv.w;
            }
        }
        // scale + causal mask (only diagonal tile can violate)
        int qg0 = qc * 64 + r0;
        #pragma unroll
        for (int j = 0; j < 8; j++) {
            s0[j] *= 0.125f; s1[j] *= 0.125f;
            if (kt == qc) {
                int kg = kt * 64 + g * 8 + j;
                if (kg > qg0)     s0[j] = -1e30f;
                if (kg > qg0 + 1) s1[j] = -1e30f;
            }
        }
        // row max across the 8 octet lanes (xor 4,8,16)
        float mx0 = s0[0], mx1 = s1[0];
        #pragma unroll
        for (int j = 1; j < 8; j++) { mx0 = fmaxf(mx0, s0[j]); mx1 = fmaxf(mx1, s1[j]); }
        #pragma unroll
        for (int off = 4; off <= 16; off <<= 1) {
            mx0 = fmaxf(mx0, __shfl_xor_sync(0xffffffffu, mx0, off));
            mx1 = fmaxf(mx1, __shfl_xor_sync(0xffffffffu, mx1, off));
        }
        float mn0 = fmaxf(m0, mx0), mn1 = fmaxf(m1, mx1);
        float cor0 = __expf(m0 - mn0), cor1 = __expf(m1 - mn1);
        m0 = mn0; m1 = mn1;
        float ls0 = 0.f, ls1 = 0.f;
        #pragma unroll
        for (int j = 0; j < 8; j++) {
            s0[j] = __expf(s0[j] - mn0);
            s1[j] = __expf(s1[j] - mn1);
            ls0 += s0[j]; ls1 += s1[j];
        }
        #pragma unroll
        for (int off = 4; off <= 16; off <<= 1) {
            ls0 += __shfl_xor_sync(0xffffffffu, ls0, off);
            ls1 += __shfl_xor_sync(0xffffffffu, ls1, off);
        }
        l0 = l0 * cor0 + ls0;
        l1 = l1 * cor1 + ls1;
        #pragma unroll
        for (int j = 0; j < 8; j++) { o0[j] *= cor0; o1[j] *= cor1; }
        // write P (warp-private rows)
        *(float4*)&Ps[r0 * FA_STRIDE + g * 8]           = make_float4(s0[0], s0[1], s0[2], s0[3]);
        *(float4*)&Ps[r0 * FA_STRIDE + g * 8 + 4]       = make_float4(s0[4], s0[5], s0[6], s0[7]);
        *(float4*)&Ps[(r0 + 1) * FA_STRIDE + g * 8]     = make_float4(s1[0], s1[1], s1[2], s1[3]);
        *(float4*)&Ps[(r0 + 1) * FA_STRIDE + g * 8 + 4] = make_float4(s1[4], s1[5], s1[6], s1[7]);
        __syncwarp();
        // AV: lane owns rows (r0, r0+1) x d = g*8 .. g*8+7
        #pragma unroll 4
        for (int kk = 0; kk < 64; kk++) {
            float pa = Ps[r0 * FA_STRIDE + kk];
            float pb = Ps[(r0 + 1) * FA_STRIDE + kk];
            int sw = kk >> 3;
            float4 va = *(float4*)&Vs[kk * FA_STRIDE + ((2 * g) ^ sw) * 4];
            float4 vb = *(float4*)&Vs[kk * FA_STRIDE + ((2 * g + 1) ^ sw) * 4];
            o0[0] += pa * va.x; o0[1] += pa * va.y; o0[2] += pa * va.z; o0[3] += pa * va.w;
            o0[4] += pa * vb.x; o0[5] += pa * vb.y; o0[6] += pa * vb.z; o0[7] += pa * vb.w;
            o1[0] += pb * va.x; o1[1] += pb * va.y; o1[2] += pb * va.z; o1[3] += pb * va.w;
            o1[4] += pb * vb.x; o1[5] += pb * vb.y; o1[6] += pb * vb.z; o1[7] += pb * vb.w;
        }
        __syncwarp();   // P reads done before next tile's P writes
    }

    float inv0 = 1.f / l0, inv1 = 1.f / l1;
    size_t row0g = (size_t)(b * S + qc * 64 + r0);
    float* d0 = out + row0g * DM + h * 64 + g * 8;
    float* d1 = d0 + DM;
    *(float4*)d0       = make_float4(o0[0]*inv0, o0[1]*inv0, o0[2]*inv0, o0[3]*inv0);
    *(float4*)(d0 + 4) = make_float4(o0[4]*inv0, o0[5]*inv0, o0[6]*inv0, o0[7]*inv0);
    *(float4*)d1       = make_float4(o1[0]*inv1, o1[1]*inv1, o1[2]*inv1, o1[3]*inv1);
    *(float4*)(d1 + 4) = make_float4(o1[4]*inv1, o1[5]*inv1, o1[6]*inv1, o1[7]*inv1);
}

// ---------------- MoD: router scores ----------------
__global__ void score_kernel(float* __restrict__ scores, const float* __restrict__ x,
                             const float* __restrict__ r)
{
    __shared__ float red[8];
    int row = blockIdx.x, tid = threadIdx.x;
    const float* xr = x + (size_t)row * DM;
    float s = 0.f;
    #pragma unroll
    for (int i = 0; i < 4; i++) { int d = tid + i * 256; s = fmaf(xr[d], r[d], s); }
    s = blockSum(s, red);
    if (tid == 0) scores[row] = s;
}

// ---------------- MoD: exact top-128 descending (bitonic sort, tie = smaller idx) ----------------
__global__ void topk_sort_kernel(int* __restrict__ idx, const float* __restrict__ scores)
{
    int b = blockIdx.x, tid = threadIdx.x;
    __shared__ float s[TSEQ];
    __shared__ int   si[TSEQ];
    s[tid]  = scores[b * TSEQ + tid];
    si[tid] = tid;
    __syncthreads();
    for (int k = 2; k <= TSEQ; k <<= 1) {
        for (int j = k >> 1; j > 0; j >>= 1) {
            int ixj = tid ^ j;
            if (ixj > tid) {
                bool desc = ((tid & k) == 0);
                float s1 = s[tid], s2 = s[ixj];
                int   i1 = si[tid], i2 = si[ixj];
                bool firstBetter = (s1 > s2) || (s1 == s2 && i1 < i2);
                if (desc != firstBetter) {
                    s[tid] = s2; s[ixj] = s1;
                    si[tid] = i2; si[ixj] = i1;
                }
            }
            __syncthreads();
        }
    }
    if (tid < CAP) idx[b * CAP + tid] = si[tid];
}

__global__ void gather_kernel(float* __restrict__ xs, const float* __restrict__ x,
                              const int* __restrict__ idx)
{
    int row = blockIdx.x;
    int b = row >> 7;
    int src = b * TSEQ + idx[row];
    int tid = threadIdx.x;
    #pragma unroll
    for (int i = 0; i < 4; i++) {
        int d = tid + i * 256;
        xs[(size_t)row * DM + d] = x[(size_t)src * DM + d];
    }
}
__global__ void scatter_kernel(float* __restrict__ x, const float* __restrict__ xs,
                               const int* __restrict__ idx)
{
    int row = blockIdx.x;
    int b = row >> 7;
    int dst = b * TSEQ + idx[row];
    int tid = threadIdx.x;
    #pragma unroll
    for (int i = 0; i < 4; i++) {
        int d = tid + i * 256;
        x[(size_t)dst * DM + d] = xs[(size_t)row * DM + d];
    }
}

// ---------------- memory: top-8 + softmax + weighted value gather ----------------
__global__ void memtopk_kernel(float* __restrict__ outp, const float* __restrict__ sim,
                               const float* __restrict__ mem_values)
{
    int row = blockIdx.x, tid = threadIdx.x;
    __shared__ float sv[NSLOTS];
    __shared__ float av[NSLOTS];
    __shared__ int   ai[NSLOTS];
    __shared__ float wk[TOPK];
    __shared__ int   ik[TOPK];
    sv[tid] = sim[(size_t)row * NSLOTS + tid] * 0.03125f;
    __syncthreads();
    for (int k = 0; k < TOPK; k++) {
        av[tid] = sv[tid]; ai[tid] = tid;
        __syncthreads();
        for (int s = 64; s > 0; s >>= 1) {
            if (tid < s) {
                float v2 = av[tid + s]; int i2 = ai[tid + s];
                if (v2 > av[tid] || (v2 == av[tid] && i2 < ai[tid])) { av[tid] = v2; ai[tid] = i2; }
            }
            __syncthreads();
        }
        if (tid == 0) { wk[k] = av[0]; ik[k] = ai[0]; sv[ai[0]] = -INFINITY; }
        __syncthreads();
    }
    if (tid == 0) {
        float mx = wk[0], ssum = 0.f, e[TOPK];
        #pragma unroll
        for (int k = 0; k < TOPK; k++) { e[k] = expf(wk[k] - mx); ssum += e[k]; }
        #pragma unroll
        for (int k = 0; k < TOPK; k++) wk[k] = e[k] / ssum;
    }
    __syncthreads();
    #pragma unroll
    for (int i = 0; i < 8; i++) {
        int d = tid + i * 128;
        float o = 0.f;
        #pragma unroll
        for (int k = 0; k < TOPK; k++)
            o = fmaf(wk[k], mem_values[(size_t)ik[k] * DM + d], o);
        outp[(size_t)row * DM + d] = o;
    }
}

// ---------------- gate ----------------
__global__ void gate_kernel(float* __restrict__ x, const float* __restrict__ g1,
                            const float* __restrict__ gw2, const float* __restrict__ gb2,
                            const float* __restrict__ retr)
{
    __shared__ float red[8];
    int row = blockIdx.x, tid = threadIdx.x;
    float s = 0.f;
    for (int j = tid; j < 512; j += 256) {
        float v = g1[(size_t)row * 512 + j];
        s = fmaf(gelu_f(v), gw2[j], s);
    }
    s = blockSum(s, red);
    float gate = 1.f / (1.f + expf(-(s + gb2[0])));
    #pragma unroll
    for (int i = 0; i < 4; i++) {
        int d = tid + i * 256;
        size_t p = (size_t)row * DM + d;
        x[p] += gate * retr[p];
    }
}

// ---------------- host-side gemm dispatch ----------------
static void gemm(int ep, float* C, const float* A, const float* B,
                 int M, int N, int K, int lda, int ldb, int ldc,
                 const float* res = nullptr, int ldres = 0,
                 const float* bias = nullptr)
{
    dim3 grid((N + 127) / 128, (M + 127) / 128);
    switch (ep) {
    case EP_STORE:    tgemm_abt<EP_STORE>   <<<grid,256>>>(C,A,B,M,N,K,lda,ldb,ldc,res,ldres,bias); break;
    case EP_ADD:      tgemm_abt<EP_ADD>     <<<grid,256>>>(C,A,B,M,N,K,lda,ldb,ldc,res,ldres,bias); break;
    case EP_GELU:     tgemm_abt<EP_GELU>    <<<grid,256>>>(C,A,B,M,N,K,lda,ldb,ldc,res,ldres,bias); break;
    case EP_ADD_BIAS: tgemm_abt<EP_ADD_BIAS><<<grid,256>>>(C,A,B,M,N,K,lda,ldb,ldc,res,ldres,bias); break;
    case EP_SILU_MUL: tgemm_abt<EP_SILU_MUL><<<grid,256>>>(C,A,B,M,N,K,lda,ldb,ldc,res,ldres,bias); break;
    }
}

extern "C" void kernel_launch(void* const* d_in, const int* in_sizes, int n_in,
                              void* d_out, int out_size)
{
    const int*   ids       = (const int*)  d_in[0];
    const float* embed     = (const float*)d_in[1];
    const float* pos       = (const float*)d_in[2];
    const float* n1        = (const float*)d_in[3];
    const float* qkvw      = (const float*)d_in[4];
    const float* outw      = (const float*)d_in[5];
    const float* n2        = (const float*)d_in[6];
    const float* w1        = (const float*)d_in[7];
    const float* w2        = (const float*)d_in[8];
    const float* w3        = (const float*)d_in[9];
    const float* router    = (const float*)d_in[10];
    const float* mem_keys  = (const float*)d_in[11];
    const float* mem_vals  = (const float*)d_in[12];
    const float* mem_q     = (const float*)d_in[13];
    const float* mem_out   = (const float*)d_in[14];
    const float* gate_w1   = (const float*)d_in[15];
    const float* gate_b1   = (const float*)d_in[16];
    const float* gate_w2   = (const float*)d_in[17];
    const float* gate_b2   = (const float*)d_in[18];
    const float* lat_norm  = (const float*)d_in[19];
    const float* lat_w1    = (const float*)d_in[20];
    const float* lat_w2    = (const float*)d_in[21];
    const float* fin_norm  = (const float*)d_in[22];
    const float* lm_head   = (const float*)d_in[23];
    float* out = (float*)d_out;

    float *x,*xn,*qkvb,*attnb,*ff1,*ff2,*retr,*retrp,*sim,*g1,*h1,*xs,*scores;
    int *idxb;
    cudaGetSymbolAddress((void**)&x,     g_x);
    cudaGetSymbolAddress((void**)&xn,    g_xn);
    cudaGetSymbolAddress((void**)&qkvb,  g_qkv);
    cudaGetSymbolAddress((void**)&attnb, g_attn);
    cudaGetSymbolAddress((void**)&ff1,   g_ff1);
    cudaGetSymbolAddress((void**)&ff2,   g_ff2);
    cudaGetSymbolAddress((void**)&retr,  g_retr);
    cudaGetSymbolAddress((void**)&retrp, g_retrp);
    cudaGetSymbolAddress((void**)&sim,   g_sim);
    cudaGetSymbolAddress((void**)&g1,    g_g1);
    cudaGetSymbolAddress((void**)&h1,    g_h1);
    cudaGetSymbolAddress((void**)&xs,    g_xs);
    cudaGetSymbolAddress((void**)&scores,g_scores);
    cudaGetSymbolAddress((void**)&idxb,  g_idx);

    // allow >48KB dynamic smem for flash attention
    cudaFuncSetAttribute(fattn_kernel, cudaFuncAttributeMaxDynamicSharedMemorySize, FA_SMEM);

    embed_kernel<<<NTOK, 256>>>(x, ids, embed, pos);

    auto run_block = [&](float* buf, int M, int S, int l) {
        const float* Wqkv = qkvw + (size_t)l * 3 * DM * DM;
        const float* Wout = outw + (size_t)l * DM * DM;
        const float* W1   = w1   + (size_t)l * DFF * DM;
        const float* W2   = w2   + (size_t)l * DFF * DM;
        const float* W3   = w3   + (size_t)l * DM * DFF;
        rms_kernel<<<M, 256>>>(xn, buf, n1 + (size_t)l * DM);
        gemm(EP_STORE, qkvb, xn, Wqkv, M, 3 * DM, DM, DM, DM, 3 * DM);
        fattn_kernel<<<dim3(S / 64, NHEAD, BATCH), 256, FA_SMEM>>>(qkvb, attnb, S);
        gemm(EP_ADD, buf, attnb, Wout, M, DM, DM, DM, DM, DM, buf, DM);
        rms_kernel<<<M, 256>>>(xn, buf, n2 + (size_t)l * DM);
        gemm(EP_STORE,    ff1, xn, W1, M, DFF, DM, DM, DM, DFF);
        gemm(EP_SILU_MUL, ff2, xn, W2, M, DFF, DM, DM, DM, DFF, ff1, DFF);
        gemm(EP_ADD,      buf, ff2, W3, M, DM, DFF, DFF, DFF, DM, buf, DM);
    };

    for (int l = 0; l < NLAYER; l++) {
        if (l & 1) {
            score_kernel<<<NTOK, 256>>>(scores, x, router + (size_t)l * DM);
            topk_sort_kernel<<<BATCH, TSEQ>>>(idxb, scores);
            gather_kernel<<<BATCH * CAP, 256>>>(xs, x, idxb);
            run_block(xs, BATCH * CAP, CAP, l);
            scatter_kernel<<<BATCH * CAP, 256>>>(x, xs, idxb);
        } else {
            run_block(x, NTOK, TSEQ, l);
        }
    }

    // kNN memory retrieval
    gemm(EP_STORE, xn,  x,  mem_q,    NTOK, DM,     DM, DM, DM, DM);
    gemm(EP_STORE, sim, xn, mem_keys, NTOK, NSLOTS, DM, DM, DM, NSLOTS);
    memtopk_kernel<<<NTOK, 128>>>(retrp, sim, mem_vals);
    gemm(EP_STORE, retr, retrp, mem_out, NTOK, DM, DM, DM, DM, DM);
    gemm(EP_STORE,    g1, x,    gate_w1,      NTOK, 512, DM, DM, 2 * DM, 512);
    gemm(EP_ADD_BIAS, g1, retr, gate_w1 + DM, NTOK, 512, DM, DM, 2 * DM, 512, g1, 512, gate_b1);
    gate_kernel<<<NTOK, 256>>>(x, g1, gate_w2, gate_b2, retr);

    // latent reasoning iterations
    for (int it = 0; it < 4; it++) {
        rms_kernel<<<NTOK, 256>>>(xn, x, lat_norm);
        gemm(EP_GELU, h1, xn, lat_w1, NTOK, 2 * DM, DM, DM, DM, 2 * DM);
        gemm(EP_ADD,  x,  h1, lat_w2, NTOK, DM, 2 * DM, 2 * DM, 2 * DM, DM, x, DM);
    }

    // final norm + LM head
    rms_kernel<<<NTOK, 256>>>(xn, x, fin_norm);
    gemm(EP_STORE, out, xn, lm_head, NTOK, 50257, DM, DM, DM, 50257);
}

// round 15
// speedup vs baseline: 2.6202x; 1.0941x over previous
#include <cuda_runtime.h>
#include <cuda_bf16.h>
#include <math.h>

// ---------------- problem constants ----------------
#define BATCH   2
#define TSEQ    1024
#define DM      1024
#define NHEAD   16
#define HD      64
#define NLAYER  12
#define DFF     2730
#define CAP     128
#define NSLOTS  128
#define TOPK    8
#define NTOK    (BATCH*TSEQ)      // 2048

// ---------------- scratch (device globals; no allocation allowed) ----------------
__device__ float g_x    [NTOK*DM];
__device__ float g_xn   [NTOK*DM];
__device__ float g_qkv  [NTOK*3*DM];
__device__ float g_attn [NTOK*DM];
__device__ float g_ff1  [NTOK*DFF];
__device__ float g_ff2  [NTOK*DFF];
__device__ float g_retr [NTOK*DM];
__device__ float g_retrp[NTOK*DM];
__device__ float g_sim  [NTOK*NSLOTS];
__device__ float g_g1   [NTOK*512];
__device__ float g_h1   [NTOK*2048];
__device__ float g_xs   [BATCH*CAP*DM];
__device__ float g_scores[NTOK];
__device__ int   g_idx  [BATCH*CAP];

// ---------------- helpers ----------------
__device__ __forceinline__ float warpSum(float v){
    #pragma unroll
    for (int o=16;o>0;o>>=1) v += __shfl_xor_sync(0xffffffffu, v, o);
    return v;
}
__device__ __forceinline__ float blockSum(float v, float* red){
    int lane = threadIdx.x & 31, w = threadIdx.x >> 5, nw = blockDim.x >> 5;
    v = warpSum(v);
    if (lane == 0) red[w] = v;
    __syncthreads();
    float r = (w == 0 && lane < nw) ? red[lane] : 0.f;
    if (w == 0) r = warpSum(r);
    if (threadIdx.x == 0) red[0] = r;
    __syncthreads();
    float out = red[0];
    __syncthreads();
    return out;
}
__device__ __forceinline__ float gelu_f(float v){
    return 0.5f * v * (1.f + erff(v * 0.70710678118654752f));
}
__device__ __forceinline__ float silu_f(float v){
    return v / (1.f + expf(-v));
}

// ---------------- bf16 hi/lo split + mma ----------------
__device__ __forceinline__ void split2_bf16(float x, float y, unsigned &hi2, unsigned &lo2){
    __nv_bfloat16 hx = __float2bfloat16_rn(x);
    __nv_bfloat16 hy = __float2bfloat16_rn(y);
    __nv_bfloat16 lx = __float2bfloat16_rn(x - __bfloat162float(hx));
    __nv_bfloat16 ly = __float2bfloat16_rn(y - __bfloat162float(hy));
    __nv_bfloat162 h; h.x = hx; h.y = hy;
    __nv_bfloat162 l; l.x = lx; l.y = ly;
    hi2 = *reinterpret_cast<unsigned*>(&h);
    lo2 = *reinterpret_cast<unsigned*>(&l);
}
__device__ __forceinline__ void mma16(float* c, const unsigned* a, const unsigned* b){
    asm volatile(
        "mma.sync.aligned.m16n8k16.row.col.f32.bf16.bf16.f32 "
        "{%0,%1,%2,%3}, {%4,%5,%6,%7}, {%8,%9}, {%0,%1,%2,%3};"
        : "+f"(c[0]), "+f"(c[1]), "+f"(c[2]), "+f"(c[3])
        : "r"(a[0]), "r"(a[1]), "r"(a[2]), "r"(a[3]), "r"(b[0]), "r"(b[1]));
}

// guarded float4 row load (handles unaligned ld and K tail)
__device__ __forceinline__ float4 ldg_row(const float* __restrict__ P, int ld, bool al4,
                                          int row, int gk, int RM, int K)
{
    float4 v = make_float4(0.f, 0.f, 0.f, 0.f);
    if (row < RM) {
        const float* p = P + (size_t)row * ld + gk;
        if (al4 && gk + 3 < K) v = *(const float4*)p;
        else {
            if (gk + 0 < K) v.x = p[0];
            if (gk + 1 < K) v.y = p[1];
            if (gk + 2 < K) v.z = p[2];
            if (gk + 3 < K) v.w = p[3];
        }
    }
    return v;
}

#define EP_STORE    0
#define EP_ADD      1
#define EP_GELU     2
#define EP_ADD_BIAS 3
#define EP_SILU_MUL 4

__device__ __forceinline__ float apply_ep(int EP, float v, const float* res, int ldres,
                                          const float* bias, int gm, int gn)
{
    if (EP == EP_ADD)           v += res[(size_t)gm * ldres + gn];
    else if (EP == EP_GELU)     v = gelu_f(v);
    else if (EP == EP_ADD_BIAS) v += res[(size_t)gm * ldres + gn] + bias[gn];
    else if (EP == EP_SILU_MUL) v *= silu_f(res[(size_t)gm * ldres + gn]);
    return v;
}

// ---------------- GEMM 128x128: 3-term bf16 hi/lo, BK=32, reg-staged prefetch ----------------
template<int EP>
__global__ __launch_bounds__(256, 2)
void tgemm_abt(float* __restrict__ C, const float* __restrict__ A,
               const float* __restrict__ B, int M, int N, int K,
               int lda, int ldb, int ldc,
               const float* __restrict__ res, int ldres,
               const float* __restrict__ bias)
{
    __shared__ unsigned Ah[128][20], Al[128][20], Bh[128][20], Bl[128][20];
    const int bm = blockIdx.y * 128, bn = blockIdx.x * 128;
    const int tid  = threadIdx.x;
    const int warp = tid >> 5, lane = tid & 31;
    const int wm = (warp & 1) * 64;
    const int wn = (warp >> 1) * 32;
    const int g  = lane >> 2, tg = lane & 3;
    const bool a4 = ((lda & 3) == 0);
    const bool b4 = ((ldb & 3) == 0);
    const int frow = tid >> 1;
    const int kcb  = (tid & 1) * 8;
    const int kgb  = (tid & 1) * 16;

    float acc[4][4][4];
    #pragma unroll
    for (int mi = 0; mi < 4; mi++)
        #pragma unroll
        for (int ni = 0; ni < 4; ni++)
            #pragma unroll
            for (int cc = 0; cc < 4; cc++) acc[mi][ni][cc] = 0.f;

    unsigned sAh[8], sAl[8], sBh[8], sBl[8];
    #pragma unroll
    for (int q = 0; q < 4; q++) {
        float4 a = ldg_row(A, lda, a4, bm + frow, kgb + q * 4, M, K);
        split2_bf16(a.x, a.y, sAh[q*2],   sAl[q*2]);
        split2_bf16(a.z, a.w, sAh[q*2+1], sAl[q*2+1]);
        float4 b = ldg_row(B, ldb, b4, bn + frow, kgb + q * 4, N, K);
        split2_bf16(b.x, b.y, sBh[q*2],   sBl[q*2]);
        split2_bf16(b.z, b.w, sBh[q*2+1], sBl[q*2+1]);
    }

    for (int k0 = 0; k0 < K; k0 += 32) {
        #pragma unroll
        for (int j = 0; j < 8; j++) {
            Ah[frow][kcb + j] = sAh[j];
            Al[frow][kcb + j] = sAl[j];
            Bh[frow][kcb + j] = sBh[j];
            Bl[frow][kcb + j] = sBl[j];
        }
        __syncthreads();

        if (k0 + 32 < K) {
            #pragma unroll
            for (int q = 0; q < 4; q++) {
                float4 a = ldg_row(A, lda, a4, bm + frow, k0 + 32 + kgb + q * 4, M, K);
                split2_bf16(a.x, a.y, sAh[q*2],   sAl[q*2]);
                split2_bf16(a.z, a.w, sAh[q*2+1], sAl[q*2+1]);
                float4 b = ldg_row(B, ldb, b4, bn + frow, k0 + 32 + kgb + q * 4, N, K);
                split2_bf16(b.x, b.y, sBh[q*2],   sBl[q*2]);
                split2_bf16(b.z, b.w, sBh[q*2+1], sBl[q*2+1]);
            }
        }

        #pragma unroll
        for (int ks = 0; ks < 2; ks++) {
            const int c0 = ks * 8;
            unsigned bhiF[4][2], bloF[4][2];
            #pragma unroll
            for (int ni = 0; ni < 4; ni++) {
                int col = wn + ni * 8 + g;
                bhiF[ni][0] = Bh[col][c0 + tg];
                bhiF[ni][1] = Bh[col][c0 + tg + 4];
                bloF[ni][0] = Bl[col][c0 + tg];
                bloF[ni][1] = Bl[col][c0 + tg + 4];
            }
            #pragma unroll
            for (int mi = 0; mi < 4; mi++) {
                int r = wm + mi * 16 + g;
                unsigned ah[4], al[4];
                ah[0] = Ah[r][c0 + tg];     ah[1] = Ah[r + 8][c0 + tg];
                ah[2] = Ah[r][c0 + tg + 4]; ah[3] = Ah[r + 8][c0 + tg + 4];
                al[0] = Al[r][c0 + tg];     al[1] = Al[r + 8][c0 + tg];
                al[2] = Al[r][c0 + tg + 4]; al[3] = Al[r + 8][c0 + tg + 4];
                #pragma unroll
                for (int ni = 0; ni < 4; ni++) mma16(acc[mi][ni], ah, bhiF[ni]);
                #pragma unroll
                for (int ni = 0; ni < 4; ni++) mma16(acc[mi][ni], ah, bloF[ni]);
                #pragma unroll
                for (int ni = 0; ni < 4; ni++) mma16(acc[mi][ni], al, bhiF[ni]);
            }
        }
        __syncthreads();
    }

    #pragma unroll
    for (int mi = 0; mi < 4; mi++) {
        int row0 = bm + wm + mi * 16 + g;
        #pragma unroll
        for (int ni = 0; ni < 4; ni++) {
            int col0 = bn + wn + ni * 8 + tg * 2;
            #pragma unroll
            for (int cc = 0; cc < 4; cc++) {
                int gm = row0 + (cc >> 1) * 8;
                int gn = col0 + (cc & 1);
                if (gm < M && gn < N)
                    C[(size_t)gm * ldc + gn] = apply_ep(EP, acc[mi][ni][cc], res, ldres, bias, gm, gn);
            }
        }
    }
}

// ---------------- GEMM 64x128: small-grid variant (higher occupancy, single-buffered) ----------------
template<int EP>
__global__ __launch_bounds__(256)
void tgemm64_abt(float* __restrict__ C, const float* __restrict__ A,
                 const float* __restrict__ B, int M, int N, int K,
                 int lda, int ldb, int ldc,
                 const float* __restrict__ res, int ldres,
                 const float* __restrict__ bias)
{
    __shared__ unsigned Ah[64][20], Al[64][20], Bh[128][20], Bl[128][20];
    const int bm = blockIdx.y * 64, bn = blockIdx.x * 128;
    const int tid  = threadIdx.x;
    const int warp = tid >> 5, lane = tid & 31;
    const int wm = (warp & 1) * 32;      // 2 warps along M (64)
    const int wn = (warp >> 1) * 32;     // 4 warps along N (128)
    const int g  = lane >> 2, tg = lane & 3;
    const bool a4 = ((lda & 3) == 0);
    const bool b4 = ((ldb & 3) == 0);

    float acc[2][4][4];
    #pragma unroll
    for (int mi = 0; mi < 2; mi++)
        #pragma unroll
        for (int ni = 0; ni < 4; ni++)
            #pragma unroll
            for (int cc = 0; cc < 4; cc++) acc[mi][ni][cc] = 0.f;

    for (int k0 = 0; k0 < K; k0 += 32) {
        // fill A (64x32) : 512 float4 slots, 2 per thread
        #pragma unroll
        for (int s = 0; s < 2; s++) {
            int e = tid + s * 256;
            int row = e >> 3, q = e & 7;
            float4 a = ldg_row(A, lda, a4, bm + row, k0 + q * 4, M, K);
            unsigned h0, l0, h1, l1;
            split2_bf16(a.x, a.y, h0, l0);
            split2_bf16(a.z, a.w, h1, l1);
            Ah[row][q*2] = h0; Ah[row][q*2+1] = h1;
            Al[row][q*2] = l0; Al[row][q*2+1] = l1;
        }
        // fill B (128x32) : 1024 float4 slots, 4 per thread
        #pragma unroll
        for (int s = 0; s < 4; s++) {
            int e = tid + s * 256;
            int row = e >> 3, q = e & 7;
            float4 b = ldg_row(B, ldb, b4, bn + row, k0 + q * 4, N, K);
            unsigned h0, l0, h1, l1;
            split2_bf16(b.x, b.y, h0, l0);
            split2_bf16(b.z, b.w, h1, l1);
            Bh[row][q*2] = h0; Bh[row][q*2+1] = h1;
            Bl[row][q*2] = l0; Bl[row][q*2+1] = l1;
        }
        __syncthreads();

        #pragma unroll
        for (int ks = 0; ks < 2; ks++) {
            const int c0 = ks * 8;
            unsigned bhiF[4][2], bloF[4][2];
            #pragma unroll
            for (int ni = 0; ni < 4; ni++) {
                int col = wn + ni * 8 + g;
                bhiF[ni][0] = Bh[col][c0 + tg];
                bhiF[ni][1] = Bh[col][c0 + tg + 4];
                bloF[ni][0] = Bl[col][c0 + tg];
                bloF[ni][1] = Bl[col][c0 + tg + 4];
            }
            #pragma unroll
            for (int mi = 0; mi < 2; mi++) {
                int r = wm + mi * 16 + g;
                unsigned ah[4], al[4];
                ah[0] = Ah[r][c0 + tg];     ah[1] = Ah[r + 8][c0 + tg];
                ah[2] = Ah[r][c0 + tg + 4]; ah[3] = Ah[r + 8][c0 + tg + 4];
                al[0] = Al[r][c0 + tg];     al[1] = Al[r + 8][c0 + tg];
                al[2] = Al[r][c0 + tg + 4]; al[3] = Al[r + 8][c0 + tg + 4];
                #pragma unroll
                for (int ni = 0; ni < 4; ni++) mma16(acc[mi][ni], ah, bhiF[ni]);
                #pragma unroll
                for (int ni = 0; ni < 4; ni++) mma16(acc[mi][ni], ah, bloF[ni]);
                #pragma unroll
                for (int ni = 0; ni < 4; ni++) mma16(acc[mi][ni], al, bhiF[ni]);
            }
        }
        __syncthreads();
    }

    #pragma unroll
    for (int mi = 0; mi < 2; mi++) {
        int row0 = bm + wm + mi * 16 + g;
        #pragma unroll
        for (int ni = 0; ni < 4; ni++) {
            int col0 = bn + wn + ni * 8 + tg * 2;
            #pragma unroll
            for (int cc = 0; cc < 4; cc++) {
                int gm = row0 + (cc >> 1) * 8;
                int gn = col0 + (cc & 1);
                if (gm < M && gn < N)
                    C[(size_t)gm * ldc + gn] = apply_ep(EP, acc[mi][ni][cc], res, ldres, bias, gm, gn);
            }
        }
    }
}

// ---------------- embed + positional ----------------
__global__ void embed_kernel(float* __restrict__ x, const int* __restrict__ ids,
                             const float* __restrict__ emb, const float* __restrict__ pos)
{
    int row = blockIdx.x;
    int t   = row & (TSEQ - 1);
    int id  = ids[row];
    int tid = threadIdx.x;
    #pragma unroll
    for (int i = 0; i < 4; i++) {
        int d = tid + i * 256;
        x[(size_t)row * DM + d] = emb[(size_t)id * DM + d] + pos[(size_t)t * DM + d];
    }
}

// ---------------- rmsnorm ----------------
__global__ void rms_kernel(float* __restrict__ y, const float* __restrict__ x,
                           const float* __restrict__ w)
{
    __shared__ float red[8];
    int row = blockIdx.x, tid = threadIdx.x;
    const float* xr = x + (size_t)row * DM;
    float s = 0.f;
    #pragma unroll
    for (int i = 0; i < 4; i++) { float v = xr[tid + i * 256]; s = fmaf(v, v, s); }
    s = blockSum(s, red);
    float r = rsqrtf(s * (1.f / DM) + 1e-6f);
    #pragma unroll
    for (int i = 0; i < 4; i++) {
        int d = tid + i * 256;
        y[(size_t)row * DM + d] = xr[d] * r * w[d];
    }
}

// ---------------- flash attention ----------------
#define FA_STRIDE 68
#define FA_SMEM   (4 * 64 * FA_STRIDE * 4)

__global__ __launch_bounds__(256)
void fattn_kernel(const float* __restrict__ qkv, float* __restrict__ out, int S)
{
    extern __shared__ float fsm[];
    float* Qs = fsm;
    float* Ks = fsm + 64 * FA_STRIDE;
    float* Vs = fsm + 2 * 64 * FA_STRIDE;
    float* Ps = fsm + 3 * 64 * FA_STRIDE;
    const int qc = blockIdx.x, h = blockIdx.y, b = blockIdx.z;
    const int tid = threadIdx.x, w = tid >> 5, lane = tid & 31;
    const int pair = lane & 3, g = lane >> 2;
    const int r0 = w * 8 + pair * 2;
    const float* base = qkv + (size_t)b * S * 3072;

    {
        int row = tid >> 2, c0 = (tid & 3) * 16;
        const float* src = base + (size_t)(qc * 64 + row) * 3072 + h * 64 + c0;
        #pragma unroll
        for (int q = 0; q < 4; q++)
            *(float4*)&Qs[row * FA_STRIDE + c0 + q * 4] = *(const float4*)(src + q * 4);
    }

    float o0[8], o1[8];
    #pragma unroll
    for (int j = 0; j < 8; j++) { o0[j] = 0.f; o1[j] = 0.f; }
    float m0 = -1e30f, m1 = -1e30f, l0 = 0.f, l1 = 0.f;

    for (int kt = 0; kt <= qc; kt++) {
        __syncthreads();
        {
            int row = tid >> 2, c0 = (tid & 3) * 16;
            const float* ksrc = base + (size_t)(kt * 64 + row) * 3072 + 1024 + h * 64 + c0;
            const float* vsrc = ksrc + 1024;
            int sw = (row >> 3) & 7;
            #pragma unroll
            for (int q = 0; q < 4; q++) {
                int d4 = (c0 >> 2) + q;
                int cc = d4 ^ sw;
                *(float4*)&Ks[row * FA_STRIDE + cc * 4] = *(const float4*)(ksrc + q * 4);
                *(float4*)&Vs[row * FA_STRIDE + cc * 4] = *(const float4*)(vsrc + q * 4);
            }
        }
        __syncthreads();

        float s0[8], s1[8];
        #pragma unroll
        for (int j = 0; j < 8; j++) { s0[j] = 0.f; s1[j] = 0.f; }
        #pragma unroll 4
        for (int d4 = 0; d4 < 16; d4++) {
            float4 q0 = *(float4*)&Qs[r0 * FA_STRIDE + d4 * 4];
            float4 q1 = *(float4*)&Qs[(r0 + 1) * FA_STRIDE + d4 * 4];
            #pragma unroll
            for (int j = 0; j < 8; j++) {
                float4 kv = *(float4*)&Ks[(g * 8 + j) * FA_STRIDE + (d4 ^ g) * 4];
                s0[j] += q0.x*kv.x + q0.y*kv.y + q0.z*kv.z + q0.w*kv.w;
                s1[j] += q1.x*kv.x + q1.y*kv.y + q1.z*kv.z + q1.w*kv.w;
            }
        }
        int qg0 = qc * 64 + r0;
        #pragma unroll
        for (int j = 0; j < 8; j++) {
            s0[j] *= 0.125f; s1[j] *= 0.125f;
            if (kt == qc) {
                int kg = kt * 64 + g * 8 + j;
                if (kg > qg0)     s0[j] = -1e30f;
                if (kg > qg0 + 1) s1[j] = -1e30f;
            }
        }
        float mx0 = s0[0], mx1 = s1[0];
        #pragma unroll
        for (int j = 1; j < 8; j++) { mx0 = fmaxf(mx0, s0[j]); mx1 = fmaxf(mx1, s1[j]); }
        #pragma unroll
        for (int off = 4; off <= 16; off <<= 1) {
            mx0 = fmaxf(mx0, __shfl_xor_sync(0xffffffffu, mx0, off));
            mx1 = fmaxf(mx1, __shfl_xor_sync(0xffffffffu, mx1, off));
        }
        float mn0 = fmaxf(m0, mx0), mn1 = fmaxf(m1, mx1);
        float cor0 = __expf(m0 - mn0), cor1 = __expf(m1 - mn1);
        m0 = mn0; m1 = mn1;
        float ls0 = 0.f, ls1 = 0.f;
        #pragma unroll
        for (int j = 0; j < 8; j++) {
            s0[j] = __expf(s0[j] - mn0);
            s1[j] = __expf(s1[j] - mn1);
            ls0 += s0[j]; ls1 += s1[j];
        }
        #pragma unroll
        for (int off = 4; off <= 16; off <<= 1) {
            ls0 += __shfl_xor_sync(0xffffffffu, ls0, off);
            ls1 += __shfl_xor_sync(0xffffffffu, ls1, off);
        }
        l0 = l0 * cor0 + ls0;
        l1 = l1 * cor1 + ls1;
        #pragma unroll
        for (int j = 0; j < 8; j++) { o0[j] *= cor0; o1[j] *= cor1; }
        *(float4*)&Ps[r0 * FA_STRIDE + g * 8]           = make_float4(s0[0], s0[1], s0[2], s0[3]);
        *(float4*)&Ps[r0 * FA_STRIDE + g * 8 + 4]       = make_float4(s0[4], s0[5], s0[6], s0[7]);
        *(float4*)&Ps[(r0 + 1) * FA_STRIDE + g * 8]     = make_float4(s1[0], s1[1], s1[2], s1[3]);
        *(float4*)&Ps[(r0 + 1) * FA_STRIDE + g * 8 + 4] = make_float4(s1[4], s1[5], s1[6], s1[7]);
        __syncwarp();
        #pragma unroll 4
        for (int kk = 0; kk < 64; kk++) {
            float pa = Ps[r0 * FA_STRIDE + kk];
            float pb = Ps[(r0 + 1) * FA_STRIDE + kk];
            int sw = kk >> 3;
            float4 va = *(float4*)&Vs[kk * FA_STRIDE + ((2 * g) ^ sw) * 4];
            float4 vb = *(float4*)&Vs[kk * FA_STRIDE + ((2 * g + 1) ^ sw) * 4];
            o0[0] += pa * va.x; o0[1] += pa * va.y; o0[2] += pa * va.z; o0[3] += pa * va.w;
            o0[4] += pa * vb.x; o0[5] += pa * vb.y; o0[6] += pa * vb.z; o0[7] += pa * vb.w;
            o1[0] += pb * va.x; o1[1] += pb * va.y; o1[2] += pb * va.z; o1[3] += pb * va.w;
            o1[4] += pb * vb.x; o1[5] += pb * vb.y; o1[6] += pb * vb.z; o1[7] += pb * vb.w;
        }
        __syncwarp();
    }

    float inv0 = 1.f / l0, inv1 = 1.f / l1;
    size_t row0g = (size_t)(b * S + qc * 64 + r0);
    float* d0 = out + row0g * DM + h * 64 + g * 8;
    float* d1 = d0 + DM;
    *(float4*)d0       = make_float4(o0[0]*inv0, o0[1]*inv0, o0[2]*inv0, o0[3]*inv0);
    *(float4*)(d0 + 4) = make_float4(o0[4]*inv0, o0[5]*inv0, o0[6]*inv0, o0[7]*inv0);
    *(float4*)d1       = make_float4(o1[0]*inv1, o1[1]*inv1, o1[2]*inv1, o1[3]*inv1);
    *(float4*)(d1 + 4) = make_float4(o1[4]*inv1, o1[5]*inv1, o1[6]*inv1, o1[7]*inv1);
}

// ---------------- MoD: router scores ----------------
__global__ void score_kernel(float* __restrict__ scores, const float* __restrict__ x,
                             const float* __restrict__ r)
{
    __shared__ float red[8];
    int row = blockIdx.x, tid = threadIdx.x;
    const float* xr = x + (size_t)row * DM;
    float s = 0.f;
    #pragma unroll
    for (int i = 0; i < 4; i++) { int d = tid + i * 256; s = fmaf(xr[d], r[d], s); }
    s = blockSum(s, red);
    if (tid == 0) scores[row] = s;
}

// ---------------- MoD: exact top-128 descending (bitonic, tie = smaller idx) ----------------
__global__ void topk_sort_kernel(int* __restrict__ idx, const float* __restrict__ scores)
{
    int b = blockIdx.x, tid = threadIdx.x;
    __shared__ float s[TSEQ];
    __shared__ int   si[TSEQ];
    s[tid]  = scores[b * TSEQ + tid];
    si[tid] = tid;
    __syncthreads();
    for (int k = 2; k <= TSEQ; k <<= 1) {
        for (int j = k >> 1; j > 0; j >>= 1) {
            int ixj = tid ^ j;
            if (ixj > tid) {
                bool desc = ((tid & k) == 0);
                float s1 = s[tid], s2 = s[ixj];
                int   i1 = si[tid], i2 = si[ixj];
                bool firstBetter = (s1 > s2) || (s1 == s2 && i1 < i2);
                if (desc != firstBetter) {
                    s[tid] = s2; s[ixj] = s1;
                    si[tid] = i2; si[ixj] = i1;
                }
            }
            __syncthreads();
        }
    }
    if (tid < CAP) idx[b * CAP + tid] = si[tid];
}

__global__ void gather_kernel(float* __restrict__ xs, const float* __restrict__ x,
                              const int* __restrict__ idx)
{
    int row = blockIdx.x;
    int b = row >> 7;
    int src = b * TSEQ + idx[row];
    int tid = threadIdx.x;
    #pragma unroll
    for (int i = 0; i < 4; i++) {
        int d = tid + i * 256;
        xs[(size_t)row * DM + d] = x[(size_t)src * DM + d];
    }
}
__global__ void scatter_kernel(float* __restrict__ x, const float* __restrict__ xs,
                               const int* __restrict__ idx)
{
    int row = blockIdx.x;
    int b = row >> 7;
    int dst = b * TSEQ + idx[row];
    int tid = threadIdx.x;
    #pragma unroll
    for (int i = 0; i < 4; i++) {
        int d = tid + i * 256;
        x[(size_t)dst * DM + d] = xs[(size_t)row * DM + d];
    }
}

// ---------------- memory: top-8 + softmax + weighted value gather ----------------
__global__ void memtopk_kernel(float* __restrict__ outp, const float* __restrict__ sim,
                               const float* __restrict__ mem_values)
{
    int row = blockIdx.x, tid = threadIdx.x;
    __shared__ float sv[NSLOTS];
    __shared__ float av[NSLOTS];
    __shared__ int   ai[NSLOTS];
    __shared__ float wk[TOPK];
    __shared__ int   ik[TOPK];
    sv[tid] = sim[(size_t)row * NSLOTS + tid] * 0.03125f;
    __syncthreads();
    for (int k = 0; k < TOPK; k++) {
        av[tid] = sv[tid]; ai[tid] = tid;
        __syncthreads();
        for (int s = 64; s > 0; s >>= 1) {
            if (tid < s) {
                float v2 = av[tid + s]; int i2 = ai[tid + s];
                if (v2 > av[tid] || (v2 == av[tid] && i2 < ai[tid])) { av[tid] = v2; ai[tid] = i2; }
            }
            __syncthreads();
        }
        if (tid == 0) { wk[k] = av[0]; ik[k] = ai[0]; sv[ai[0]] = -INFINITY; }
        __syncthreads();
    }
    if (tid == 0) {
        float mx = wk[0], ssum = 0.f, e[TOPK];
        #pragma unroll
        for (int k = 0; k < TOPK; k++) { e[k] = expf(wk[k] - mx); ssum += e[k]; }
        #pragma unroll
        for (int k = 0; k < TOPK; k++) wk[k] = e[k] / ssum;
    }
    __syncthreads();
    #pragma unroll
    for (int i = 0; i < 8; i++) {
        int d = tid + i * 128;
        float o = 0.f;
        #pragma unroll
        for (int k = 0; k < TOPK; k++)
            o = fmaf(wk[k], mem_values[(size_t)ik[k] * DM + d], o);
        outp[(size_t)row * DM + d] = o;
    }
}

// ---------------- gate ----------------
__global__ void gate_kernel(float* __restrict__ x, const float* __restrict__ g1,
                            const float* __restrict__ gw2, const float* __restrict__ gb2,
                            const float* __restrict__ retr)
{
    __shared__ float red[8];
    int row = blockIdx.x, tid = threadIdx.x;
    float s = 0.f;
    for (int j = tid; j < 512; j += 256) {
        float v = g1[(size_t)row * 512 + j];
        s = fmaf(gelu_f(v), gw2[j], s);
    }
    s = blockSum(s, red);
    float gate = 1.f / (1.f + expf(-(s + gb2[0])));
    #pragma unroll
    for (int i = 0; i < 4; i++) {
        int d = tid + i * 256;
        size_t p = (size_t)row * DM + d;
        x[p] += gate * retr[p];
    }
}

// ---------------- host-side gemm dispatch (routes small grids to 64-row tile) ----------------
static void gemm(int ep, float* C, const float* A, const float* B,
                 int M, int N, int K, int lda, int ldb, int ldc,
                 const float* res = nullptr, int ldres = 0,
                 const float* bias = nullptr)
{
    int gx = (N + 127) / 128;
    int gy128 = (M + 127) / 128;
    if (gx * gy128 < 200) {
        dim3 grid(gx, (M + 63) / 64);
        switch (ep) {
        case EP_STORE:    tgemm64_abt<EP_STORE>   <<<grid,256>>>(C,A,B,M,N,K,lda,ldb,ldc,res,ldres,bias); break;
        case EP_ADD:      tgemm64_abt<EP_ADD>     <<<grid,256>>>(C,A,B,M,N,K,lda,ldb,ldc,res,ldres,bias); break;
        case EP_GELU:     tgemm64_abt<EP_GELU>    <<<grid,256>>>(C,A,B,M,N,K,lda,ldb,ldc,res,ldres,bias); break;
        case EP_ADD_BIAS: tgemm64_abt<EP_ADD_BIAS><<<grid,256>>>(C,A,B,M,N,K,lda,ldb,ldc,res,ldres,bias); break;
        case EP_SILU_MUL: tgemm64_abt<EP_SILU_MUL><<<grid,256>>>(C,A,B,M,N,K,lda,ldb,ldc,res,ldres,bias); break;
        }
    } else {
        dim3 grid(gx, gy128);
        switch (ep) {
        case EP_STORE:    tgemm_abt<EP_STORE>   <<<grid,256>>>(C,A,B,M,N,K,lda,ldb,ldc,res,ldres,bias); break;
        case EP_ADD:      tgemm_abt<EP_ADD>     <<<grid,256>>>(C,A,B,M,N,K,lda,ldb,ldc,res,ldres,bias); break;
        case EP_GELU:     tgemm_abt<EP_GELU>    <<<grid,256>>>(C,A,B,M,N,K,lda,ldb,ldc,res,ldres,bias); break;
        case EP_ADD_BIAS: tgemm_abt<EP_ADD_BIAS><<<grid,256>>>(C,A,B,M,N,K,lda,ldb,ldc,res,ldres,bias); break;
        case EP_SILU_MUL: tgemm_abt<EP_SILU_MUL><<<grid,256>>>(C,A,B,M,N,K,lda,ldb,ldc,res,ldres,bias); break;
        }
    }
}

extern "C" void kernel_launch(void* const* d_in, const int* in_sizes, int n_in,
                              void* d_out, int out_size)
{
    const int*   ids       = (const int*)  d_in[0];
    const float* embed     = (const float*)d_in[1];
    const float* pos       = (const float*)d_in[2];
    const float* n1        = (const float*)d_in[3];
    const float* qkvw      = (const float*)d_in[4];
    const float* outw      = (const float*)d_in[5];
    const float* n2        = (const float*)d_in[6];
    const float* w1        = (const float*)d_in[7];
    const float* w2        = (const float*)d_in[8];
    const float* w3        = (const float*)d_in[9];
    const float* router    = (const float*)d_in[10];
    const float* mem_keys  = (const float*)d_in[11];
    const float* mem_vals  = (const float*)d_in[12];
    const float* mem_q     = (const float*)d_in[13];
    const float* mem_out   = (const float*)d_in[14];
    const float* gate_w1   = (const float*)d_in[15];
    const float* gate_b1   = (const float*)d_in[16];
    const float* gate_w2   = (const float*)d_in[17];
    const float* gate_b2   = (const float*)d_in[18];
    const float* lat_norm  = (const float*)d_in[19];
    const float* lat_w1    = (const float*)d_in[20];
    const float* lat_w2    = (const float*)d_in[21];
    const float* fin_norm  = (const float*)d_in[22];
    const float* lm_head   = (const float*)d_in[23];
    float* out = (float*)d_out;

    float *x,*xn,*qkvb,*attnb,*ff1,*ff2,*retr,*retrp,*sim,*g1,*h1,*xs,*scores;
    int *idxb;
    cudaGetSymbolAddress((void**)&x,     g_x);
    cudaGetSymbolAddress((void**)&xn,    g_xn);
    cudaGetSymbolAddress((void**)&qkvb,  g_qkv);
    cudaGetSymbolAddress((void**)&attnb, g_attn);
    cudaGetSymbolAddress((void**)&ff1,   g_ff1);
    cudaGetSymbolAddress((void**)&ff2,   g_ff2);
    cudaGetSymbolAddress((void**)&retr,  g_retr);
    cudaGetSymbolAddress((void**)&retrp, g_retrp);
    cudaGetSymbolAddress((void**)&sim,   g_sim);
    cudaGetSymbolAddress((void**)&g1,    g_g1);
    cudaGetSymbolAddress((void**)&h1,    g_h1);
    cudaGetSymbolAddress((void**)&xs,    g_xs);
    cudaGetSymbolAddress((void**)&scores,g_scores);
    cudaGetSymbolAddress((void**)&idxb,  g_idx);

    cudaFuncSetAttribute(fattn_kernel, cudaFuncAttributeMaxDynamicSharedMemorySize, FA_SMEM);

    embed_kernel<<<NTOK, 256>>>(x, ids, embed, pos);

    auto run_block = [&](float* buf, int M, int S, int l) {
        const float* Wqkv = qkvw + (size_t)l * 3 * DM * DM;
        const float* Wout = outw + (size_t)l * DM * DM;
        const float* W1   = w1   + (size_t)l * DFF * DM;
        const float* W2   = w2   + (size_t)l * DFF * DM;
        const float* W3   = w3   + (size_t)l * DM * DFF;
        rms_kernel<<<M, 256>>>(xn, buf, n1 + (size_t)l * DM);
        gemm(EP_STORE, qkvb, xn, Wqkv, M, 3 * DM, DM, DM, DM, 3 * DM);
        fattn_kernel<<<dim3(S / 64, NHEAD, BATCH), 256, FA_SMEM>>>(qkvb, attnb, S);
        gemm(EP_ADD, buf, attnb, Wout, M, DM, DM, DM, DM, DM, buf, DM);
        rms_kernel<<<M, 256>>>(xn, buf, n2 + (size_t)l * DM);
        gemm(EP_STORE,    ff1, xn, W1, M, DFF, DM, DM, DM, DFF);
        gemm(EP_SILU_MUL, ff2, xn, W2, M, DFF, DM, DM, DM, DFF, ff1, DFF);
        gemm(EP_ADD,      buf, ff2, W3, M, DM, DFF, DFF, DFF, DM, buf, DM);
    };

    for (int l = 0; l < NLAYER; l++) {
        if (l & 1) {
            score_kernel<<<NTOK, 256>>>(scores, x, router + (size_t)l * DM);
            topk_sort_kernel<<<BATCH, TSEQ>>>(idxb, scores);
            gather_kernel<<<BATCH * CAP, 256>>>(xs, x, idxb);
            run_block(xs, BATCH * CAP, CAP, l);
            scatter_kernel<<<BATCH * CAP, 256>>>(x, xs, idxb);
        } else {
            run_block(x, NTOK, TSEQ, l);
        }
    }

    // kNN memory retrieval
    gemm(EP_STORE, xn,  x,  mem_q,    NTOK, DM,     DM, DM, DM, DM);
    gemm(EP_STORE, sim, xn, mem_keys, NTOK, NSLOTS, DM, DM, DM, NSLOTS);
    memtopk_kernel<<<NTOK, 128>>>(retrp, sim, mem_vals);
    gemm(EP_STORE, retr, retrp, mem_out, NTOK, DM, DM, DM, DM, DM);
    gemm(EP_STORE,    g1, x,    gate_w1,      NTOK, 512, DM, DM, 2 * DM, 512);
    gemm(EP_ADD_BIAS, g1, retr, gate_w1 + DM, NTOK, 512, DM, DM, 2 * DM, 512, g1, 512, gate_b1);
    gate_kernel<<<NTOK, 256>>>(x, g1, gate_w2, gate_b2, retr);

    // latent reasoning iterations
    for (int it = 0; it < 4; it++) {
        rms_kernel<<<NTOK, 256>>>(xn, x, lat_norm);
        gemm(EP_GELU, h1, xn, lat_w1, NTOK, 2 * DM, DM, DM, DM, 2 * DM);
        gemm(EP_ADD,  x,  h1, lat_w2, NTOK, DM, 2 * DM, 2 * DM, 2 * DM, DM, x, DM);
    }

    // final norm + LM head
    rms_kernel<<<NTOK, 256>>>(xn, x, fin_norm);
    gemm(EP_STORE, out, xn, lm_head, NTOK, 50257, DM, DM, DM, 50257);
}

// round 16
// speedup vs baseline: 2.6487x; 1.0109x over previous
#include <cuda_runtime.h>
#include <cuda_bf16.h>
#include <math.h>

// ---------------- problem constants ----------------
#define BATCH   2
#define TSEQ    1024
#define DM      1024
#define NHEAD   16
#define HD      64
#define NLAYER  12
#define DFF     2730
#define CAP     128
#define NSLOTS  128
#define TOPK    8
#define NTOK    (BATCH*TSEQ)      // 2048

// ---------------- scratch (device globals; no allocation allowed) ----------------
__device__ float g_x    [NTOK*DM];
__device__ float g_xn   [NTOK*DM];
__device__ float g_qkv  [NTOK*3*DM];
__device__ float g_attn [NTOK*DM];
__device__ float g_ff1  [NTOK*DFF];
__device__ float g_ff2  [NTOK*DFF];
__device__ float g_retr [NTOK*DM];
__device__ float g_retrp[NTOK*DM];
__device__ float g_sim  [NTOK*NSLOTS];
__device__ float g_g1   [NTOK*512];
__device__ float g_h1   [NTOK*2048];
__device__ float g_xs   [BATCH*CAP*DM];
__device__ float g_scores[NTOK];
__device__ int   g_idx  [BATCH*CAP];

// ---------------- helpers ----------------
__device__ __forceinline__ float warpSum(float v){
    #pragma unroll
    for (int o=16;o>0;o>>=1) v += __shfl_xor_sync(0xffffffffu, v, o);
    return v;
}
__device__ __forceinline__ float blockSum(float v, float* red){
    int lane = threadIdx.x & 31, w = threadIdx.x >> 5, nw = blockDim.x >> 5;
    v = warpSum(v);
    if (lane == 0) red[w] = v;
    __syncthreads();
    float r = (w == 0 && lane < nw) ? red[lane] : 0.f;
    if (w == 0) r = warpSum(r);
    if (threadIdx.x == 0) red[0] = r;
    __syncthreads();
    float out = red[0];
    __syncthreads();
    return out;
}
__device__ __forceinline__ float gelu_f(float v){
    return 0.5f * v * (1.f + erff(v * 0.70710678118654752f));
}
__device__ __forceinline__ float silu_f(float v){
    return v / (1.f + expf(-v));
}

// ---------------- bf16 hi/lo split + mma + ldmatrix ----------------
__device__ __forceinline__ void split2_bf16(float x, float y, unsigned &hi2, unsigned &lo2){
    __nv_bfloat16 hx = __float2bfloat16_rn(x);
    __nv_bfloat16 hy = __float2bfloat16_rn(y);
    __nv_bfloat16 lx = __float2bfloat16_rn(x - __bfloat162float(hx));
    __nv_bfloat16 ly = __float2bfloat16_rn(y - __bfloat162float(hy));
    __nv_bfloat162 h; h.x = hx; h.y = hy;
    __nv_bfloat162 l; l.x = lx; l.y = ly;
    hi2 = *reinterpret_cast<unsigned*>(&h);
    lo2 = *reinterpret_cast<unsigned*>(&l);
}
__device__ __forceinline__ void mma16(float* c, const unsigned* a, const unsigned* b){
    asm volatile(
        "mma.sync.aligned.m16n8k16.row.col.f32.bf16.bf16.f32 "
        "{%0,%1,%2,%3}, {%4,%5,%6,%7}, {%8,%9}, {%0,%1,%2,%3};"
        : "+f"(c[0]), "+f"(c[1]), "+f"(c[2]), "+f"(c[3])
        : "r"(a[0]), "r"(a[1]), "r"(a[2]), "r"(a[3]), "r"(b[0]), "r"(b[1]));
}
__device__ __forceinline__ void ldm4(unsigned &r0, unsigned &r1, unsigned &r2, unsigned &r3,
                                     unsigned a){
    asm volatile("ldmatrix.sync.aligned.m8n8.x4.shared.b16 {%0,%1,%2,%3}, [%4];"
                 : "=r"(r0), "=r"(r1), "=r"(r2), "=r"(r3) : "r"(a));
}

// guarded float4 row load (handles unaligned ld and K tail)
__device__ __forceinline__ float4 ldg_row(const float* __restrict__ P, int ld, bool al4,
                                          int row, int gk, int RM, int K)
{
    float4 v = make_float4(0.f, 0.f, 0.f, 0.f);
    if (row < RM) {
        const float* p = P + (size_t)row * ld + gk;
        if (al4 && gk + 3 < K) v = *(const float4*)p;
        else {
            if (gk + 0 < K) v.x = p[0];
            if (gk + 1 < K) v.y = p[1];
            if (gk + 2 < K) v.z = p[2];
            if (gk + 3 < K) v.w = p[3];
        }
    }
    return v;
}

#define EP_STORE    0
#define EP_ADD      1
#define EP_GELU     2
#define EP_ADD_BIAS 3
#define EP_SILU_MUL 4

__device__ __forceinline__ float apply_ep(int EP, float v, const float* res, int ldres,
                                          const float* bias, int gm, int gn)
{
    if (EP == EP_ADD)           v += res[(size_t)gm * ldres + gn];
    else if (EP == EP_GELU)     v = gelu_f(v);
    else if (EP == EP_ADD_BIAS) v += res[(size_t)gm * ldres + gn] + bias[gn];
    else if (EP == EP_SILU_MUL) v *= silu_f(res[(size_t)gm * ldres + gn]);
    return v;
}

// ---------------- GEMM 128x128: 3-term bf16 hi/lo, BK=32, ldmatrix frags ----------------
template<int EP>
__global__ __launch_bounds__(256, 2)
void tgemm_abt(float* __restrict__ C, const float* __restrict__ A,
               const float* __restrict__ B, int M, int N, int K,
               int lda, int ldb, int ldc,
               const float* __restrict__ res, int ldres,
               const float* __restrict__ bias)
{
    __shared__ unsigned Ah[128][20], Al[128][20], Bh[128][20], Bl[128][20];
    const int bm = blockIdx.y * 128, bn = blockIdx.x * 128;
    const int tid  = threadIdx.x;
    const int warp = tid >> 5, lane = tid & 31;
    const int wm = (warp & 1) * 64;
    const int wn = (warp >> 1) * 32;
    const int g  = lane >> 2, tg = lane & 3;
    const bool a4 = ((lda & 3) == 0);
    const bool b4 = ((ldb & 3) == 0);
    const int frow = tid >> 1;
    const int kcb  = (tid & 1) * 8;
    const int kgb  = (tid & 1) * 16;

    // ldmatrix per-lane row/col offsets
    const int rowA = wm + ((lane >> 3) & 1) * 8 + (lane & 7);   // + mi*16
    const int kcA  = (lane >> 4) * 4;                            // + c0
    const int rowB = wn + ((lane >> 4) & 1) * 8 + (lane & 7);   // + p*16
    const int kcB  = ((lane >> 3) & 1) * 4;                      // + c0
    const unsigned baseAh = (unsigned)__cvta_generic_to_shared(&Ah[0][0]);
    const unsigned baseAl = (unsigned)__cvta_generic_to_shared(&Al[0][0]);
    const unsigned baseBh = (unsigned)__cvta_generic_to_shared(&Bh[0][0]);
    const unsigned baseBl = (unsigned)__cvta_generic_to_shared(&Bl[0][0]);

    float acc[4][4][4];
    #pragma unroll
    for (int mi = 0; mi < 4; mi++)
        #pragma unroll
        for (int ni = 0; ni < 4; ni++)
            #pragma unroll
            for (int cc = 0; cc < 4; cc++) acc[mi][ni][cc] = 0.f;

    unsigned sAh[8], sAl[8], sBh[8], sBl[8];
    #pragma unroll
    for (int q = 0; q < 4; q++) {
        float4 a = ldg_row(A, lda, a4, bm + frow, kgb + q * 4, M, K);
        split2_bf16(a.x, a.y, sAh[q*2],   sAl[q*2]);
        split2_bf16(a.z, a.w, sAh[q*2+1], sAl[q*2+1]);
        float4 b = ldg_row(B, ldb, b4, bn + frow, kgb + q * 4, N, K);
        split2_bf16(b.x, b.y, sBh[q*2],   sBl[q*2]);
        split2_bf16(b.z, b.w, sBh[q*2+1], sBl[q*2+1]);
    }

    for (int k0 = 0; k0 < K; k0 += 32) {
        #pragma unroll
        for (int j = 0; j < 8; j++) {
            Ah[frow][kcb + j] = sAh[j];
            Al[frow][kcb + j] = sAl[j];
            Bh[frow][kcb + j] = sBh[j];
            Bl[frow][kcb + j] = sBl[j];
        }
        __syncthreads();

        if (k0 + 32 < K) {
            #pragma unroll
            for (int q = 0; q < 4; q++) {
                float4 a = ldg_row(A, lda, a4, bm + frow, k0 + 32 + kgb + q * 4, M, K);
                split2_bf16(a.x, a.y, sAh[q*2],   sAl[q*2]);
                split2_bf16(a.z, a.w, sAh[q*2+1], sAl[q*2+1]);
                float4 b = ldg_row(B, ldb, b4, bn + frow, k0 + 32 + kgb + q * 4, N, K);
                split2_bf16(b.x, b.y, sBh[q*2],   sBl[q*2]);
                split2_bf16(b.z, b.w, sBh[q*2+1], sBl[q*2+1]);
            }
        }

        #pragma unroll
        for (int ks = 0; ks < 2; ks++) {
            const int c0 = ks * 8;
            unsigned bhiF[4][2], bloF[4][2];
            #pragma unroll
            for (int p = 0; p < 2; p++) {
                unsigned off = (unsigned)(((rowB + p * 16) * 20 + c0 + kcB) * 4);
                ldm4(bhiF[2*p][0], bhiF[2*p][1], bhiF[2*p+1][0], bhiF[2*p+1][1], baseBh + off);
                ldm4(bloF[2*p][0], bloF[2*p][1], bloF[2*p+1][0], bloF[2*p+1][1], baseBl + off);
            }
            #pragma unroll
            for (int mi = 0; mi < 4; mi++) {
                unsigned off = (unsigned)(((rowA + mi * 16) * 20 + c0 + kcA) * 4);
                unsigned ah[4], al[4];
                ldm4(ah[0], ah[1], ah[2], ah[3], baseAh + off);
                ldm4(al[0], al[1], al[2], al[3], baseAl + off);
                #pragma unroll
                for (int ni = 0; ni < 4; ni++) mma16(acc[mi][ni], ah, bhiF[ni]);
                #pragma unroll
                for (int ni = 0; ni < 4; ni++) mma16(acc[mi][ni], ah, bloF[ni]);
                #pragma unroll
                for (int ni = 0; ni < 4; ni++) mma16(acc[mi][ni], al, bhiF[ni]);
            }
        }
        __syncthreads();
    }

    #pragma unroll
    for (int mi = 0; mi < 4; mi++) {
        int row0 = bm + wm + mi * 16 + g;
        #pragma unroll
        for (int ni = 0; ni < 4; ni++) {
            int col0 = bn + wn + ni * 8 + tg * 2;
            #pragma unroll
            for (int cc = 0; cc < 4; cc++) {
                int gm = row0 + (cc >> 1) * 8;
                int gn = col0 + (cc & 1);
                if (gm < M && gn < N)
                    C[(size_t)gm * ldc + gn] = apply_ep(EP, acc[mi][ni][cc], res, ldres, bias, gm, gn);
            }
        }
    }
}

// ---------------- GEMM 64x128: small-grid variant (higher occupancy), ldmatrix frags ----------------
template<int EP>
__global__ __launch_bounds__(256)
void tgemm64_abt(float* __restrict__ C, const float* __restrict__ A,
                 const float* __restrict__ B, int M, int N, int K,
                 int lda, int ldb, int ldc,
                 const float* __restrict__ res, int ldres,
                 const float* __restrict__ bias)
{
    __shared__ unsigned Ah[64][20], Al[64][20], Bh[128][20], Bl[128][20];
    const int bm = blockIdx.y * 64, bn = blockIdx.x * 128;
    const int tid  = threadIdx.x;
    const int warp = tid >> 5, lane = tid & 31;
    const int wm = (warp & 1) * 32;
    const int wn = (warp >> 1) * 32;
    const int g  = lane >> 2, tg = lane & 3;
    const bool a4 = ((lda & 3) == 0);
    const bool b4 = ((ldb & 3) == 0);

    const int rowA = wm + ((lane >> 3) & 1) * 8 + (lane & 7);
    const int kcA  = (lane >> 4) * 4;
    const int rowB = wn + ((lane >> 4) & 1) * 8 + (lane & 7);
    const int kcB  = ((lane >> 3) & 1) * 4;
    const unsigned baseAh = (unsigned)__cvta_generic_to_shared(&Ah[0][0]);
    const unsigned baseAl = (unsigned)__cvta_generic_to_shared(&Al[0][0]);
    const unsigned baseBh = (unsigned)__cvta_generic_to_shared(&Bh[0][0]);
    const unsigned baseBl = (unsigned)__cvta_generic_to_shared(&Bl[0][0]);

    float acc[2][4][4];
    #pragma unroll
    for (int mi = 0; mi < 2; mi++)
        #pragma unroll
        for (int ni = 0; ni < 4; ni++)
            #pragma unroll
            for (int cc = 0; cc < 4; cc++) acc[mi][ni][cc] = 0.f;

    for (int k0 = 0; k0 < K; k0 += 32) {
        #pragma unroll
        for (int s = 0; s < 2; s++) {
            int e = tid + s * 256;
            int row = e >> 3, q = e & 7;
            float4 a = ldg_row(A, lda, a4, bm + row, k0 + q * 4, M, K);
            unsigned h0, l0, h1, l1;
            split2_bf16(a.x, a.y, h0, l0);
            split2_bf16(a.z, a.w, h1, l1);
            Ah[row][q*2] = h0; Ah[row][q*2+1] = h1;
            Al[row][q*2] = l0; Al[row][q*2+1] = l1;
        }
        #pragma unroll
        for (int s = 0; s < 4; s++) {
            int e = tid + s * 256;
            int row = e >> 3, q = e & 7;
            float4 b = ldg_row(B, ldb, b4, bn + row, k0 + q * 4, N, K);
            unsigned h0, l0, h1, l1;
            split2_bf16(b.x, b.y, h0, l0);
            split2_bf16(b.z, b.w, h1, l1);
            Bh[row][q*2] = h0; Bh[row][q*2+1] = h1;
            Bl[row][q*2] = l0; Bl[row][q*2+1] = l1;
        }
        __syncthreads();

        #pragma unroll
        for (int ks = 0; ks < 2; ks++) {
            const int c0 = ks * 8;
            unsigned bhiF[4][2], bloF[4][2];
            #pragma unroll
            for (int p = 0; p < 2; p++) {
                unsigned off = (unsigned)(((rowB + p * 16) * 20 + c0 + kcB) * 4);
                ldm4(bhiF[2*p][0], bhiF[2*p][1], bhiF[2*p+1][0], bhiF[2*p+1][1], baseBh + off);
                ldm4(bloF[2*p][0], bloF[2*p][1], bloF[2*p+1][0], bloF[2*p+1][1], baseBl + off);
            }
            #pragma unroll
            for (int mi = 0; mi < 2; mi++) {
                unsigned off = (unsigned)(((rowA + mi * 16) * 20 + c0 + kcA) * 4);
                unsigned ah[4], al[4];
                ldm4(ah[0], ah[1], ah[2], ah[3], baseAh + off);
                ldm4(al[0], al[1], al[2], al[3], baseAl + off);
                #pragma unroll
                for (int ni = 0; ni < 4; ni++) mma16(acc[mi][ni], ah, bhiF[ni]);
                #pragma unroll
                for (int ni = 0; ni < 4; ni++) mma16(acc[mi][ni], ah, bloF[ni]);
                #pragma unroll
                for (int ni = 0; ni < 4; ni++) mma16(acc[mi][ni], al, bhiF[ni]);
            }
        }
        __syncthreads();
    }

    #pragma unroll
    for (int mi = 0; mi < 2; mi++) {
        int row0 = bm + wm + mi * 16 + g;
        #pragma unroll
        for (int ni = 0; ni < 4; ni++) {
            int col0 = bn + wn + ni * 8 + tg * 2;
            #pragma unroll
            for (int cc = 0; cc < 4; cc++) {
                int gm = row0 + (cc >> 1) * 8;
                int gn = col0 + (cc & 1);
                if (gm < M && gn < N)
                    C[(size_t)gm * ldc + gn] = apply_ep(EP, acc[mi][ni][cc], res, ldres, bias, gm, gn);
            }
        }
    }
}

// ---------------- embed + positional ----------------
__global__ void embed_kernel(float* __restrict__ x, const int* __restrict__ ids,
                             const float* __restrict__ emb, const float* __restrict__ pos)
{
    int row = blockIdx.x;
    int t   = row & (TSEQ - 1);
    int id  = ids[row];
    int tid = threadIdx.x;
    #pragma unroll
    for (int i = 0; i < 4; i++) {
        int d = tid + i * 256;
        x[(size_t)row * DM + d] = emb[(size_t)id * DM + d] + pos[(size_t)t * DM + d];
    }
}

// ---------------- rmsnorm ----------------
__global__ void rms_kernel(float* __restrict__ y, const float* __restrict__ x,
                           const float* __restrict__ w)
{
    __shared__ float red[8];
    int row = blockIdx.x, tid = threadIdx.x;
    const float* xr = x + (size_t)row * DM;
    float s = 0.f;
    #pragma unroll
    for (int i = 0; i < 4; i++) { float v = xr[tid + i * 256]; s = fmaf(v, v, s); }
    s = blockSum(s, red);
    float r = rsqrtf(s * (1.f / DM) + 1e-6f);
    #pragma unroll
    for (int i = 0; i < 4; i++) {
        int d = tid + i * 256;
        y[(size_t)row * DM + d] = xr[d] * r * w[d];
    }
}

// ---------------- flash attention ----------------
#define FA_STRIDE 68
#define FA_SMEM   (4 * 64 * FA_STRIDE * 4)

__global__ __launch_bounds__(256)
void fattn_kernel(const float* __restrict__ qkv, float* __restrict__ out, int S)
{
    extern __shared__ float fsm[];
    float* Qs = fsm;
    float* Ks = fsm + 64 * FA_STRIDE;
    float* Vs = fsm + 2 * 64 * FA_STRIDE;
    float* Ps = fsm + 3 * 64 * FA_STRIDE;
    const int qc = blockIdx.x, h = blockIdx.y, b = blockIdx.z;
    const int tid = threadIdx.x, w = tid >> 5, lane = tid & 31;
    const int pair = lane & 3, g = lane >> 2;
    const int r0 = w * 8 + pair * 2;
    const float* base = qkv + (size_t)b * S * 3072;

    {
        int row = tid >> 2, c0 = (tid & 3) * 16;
        const float* src = base + (size_t)(qc * 64 + row) * 3072 + h * 64 + c0;
        #pragma unroll
        for (int q = 0; q < 4; q++)
            *(float4*)&Qs[row * FA_STRIDE + c0 + q * 4] = *(const float4*)(src + q * 4);
    }

    float o0[8], o1[8];
    #pragma unroll
    for (int j = 0; j < 8; j++) { o0[j] = 0.f; o1[j] = 0.f; }
    float m0 = -1e30f, m1 = -1e30f, l0 = 0.f, l1 = 0.f;

    for (int kt = 0; kt <= qc; kt++) {
        __syncthreads();
        {
            int row = tid >> 2, c0 = (tid & 3) * 16;
            const float* ksrc = base + (size_t)(kt * 64 + row) * 3072 + 1024 + h * 64 + c0;
            const float* vsrc = ksrc + 1024;
            int sw = (row >> 3) & 7;
            #pragma unroll
            for (int q = 0; q < 4; q++) {
                int d4 = (c0 >> 2) + q;
                int cc = d4 ^ sw;
                *(float4*)&Ks[row * FA_STRIDE + cc * 4] = *(const float4*)(ksrc + q * 4);
                *(float4*)&Vs[row * FA_STRIDE + cc * 4] = *(const float4*)(vsrc + q * 4);
            }
        }
        __syncthreads();

        float s0[8], s1[8];
        #pragma unroll
        for (int j = 0; j < 8; j++) { s0[j] = 0.f; s1[j] = 0.f; }
        #pragma unroll 4
        for (int d4 = 0; d4 < 16; d4++) {
            float4 q0 = *(float4*)&Qs[r0 * FA_STRIDE + d4 * 4];
            float4 q1 = *(float4*)&Qs[(r0 + 1) * FA_STRIDE + d4 * 4];
            #pragma unroll
            for (int j = 0; j < 8; j++) {
                float4 kv = *(float4*)&Ks[(g * 8 + j) * FA_STRIDE + (d4 ^ g) * 4];
                s0[j] += q0.x*kv.x + q0.y*kv.y + q0.z*kv.z + q0.w*kv.w;
                s1[j] += q1.x*kv.x + q1.y*kv.y + q1.z*kv.z + q1.w*kv.w;
            }
        }
        int qg0 = qc * 64 + r0;
        #pragma unroll
        for (int j = 0; j < 8; j++) {
            s0[j] *= 0.125f; s1[j] *= 0.125f;
            if (kt == qc) {
                int kg = kt * 64 + g * 8 + j;
                if (kg > qg0)     s0[j] = -1e30f;
                if (kg > qg0 + 1) s1[j] = -1e30f;
            }
        }
        float mx0 = s0[0], mx1 = s1[0];
        #pragma unroll
        for (int j = 1; j < 8; j++) { mx0 = fmaxf(mx0, s0[j]); mx1 = fmaxf(mx1, s1[j]); }
        #pragma unroll
        for (int off = 4; off <= 16; off <<= 1) {
            mx0 = fmaxf(mx0, __shfl_xor_sync(0xffffffffu, mx0, off));
            mx1 = fmaxf(mx1, __shfl_xor_sync(0xffffffffu, mx1, off));
        }
        float mn0 = fmaxf(m0, mx0), mn1 = fmaxf(m1, mx1);
        float cor0 = __expf(m0 - mn0), cor1 = __expf(m1 - mn1);
        m0 = mn0; m1 = mn1;
        float ls0 = 0.f, ls1 = 0.f;
        #pragma unroll
        for (int j = 0; j < 8; j++) {
            s0[j] = __expf(s0[j] - mn0);
            s1[j] = __expf(s1[j] - mn1);
            ls0 += s0[j]; ls1 += s1[j];
        }
        #pragma unroll
        for (int off = 4; off <= 16; off <<= 1) {
            ls0 += __shfl_xor_sync(0xffffffffu, ls0, off);
            ls1 += __shfl_xor_sync(0xffffffffu, ls1, off);
        }
        l0 = l0 * cor0 + ls0;
        l1 = l1 * cor1 + ls1;
        #pragma unroll
        for (int j = 0; j < 8; j++) { o0[j] *= cor0; o1[j] *= cor1; }
        *(float4*)&Ps[r0 * FA_STRIDE + g * 8]           = make_float4(s0[0], s0[1], s0[2], s0[3]);
        *(float4*)&Ps[r0 * FA_STRIDE + g * 8 + 4]       = make_float4(s0[4], s0[5], s0[6], s0[7]);
        *(float4*)&Ps[(r0 + 1) * FA_STRIDE + g * 8]     = make_float4(s1[0], s1[1], s1[2], s1[3]);
        *(float4*)&Ps[(r0 + 1) * FA_STRIDE + g * 8 + 4] = make_float4(s1[4], s1[5], s1[6], s1[7]);
        __syncwarp();
        #pragma unroll 4
        for (int kk = 0; kk < 64; kk++) {
            float pa = Ps[r0 * FA_STRIDE + kk];
            float pb = Ps[(r0 + 1) * FA_STRIDE + kk];
            int sw = kk >> 3;
            float4 va = *(float4*)&Vs[kk * FA_STRIDE + ((2 * g) ^ sw) * 4];
            float4 vb = *(float4*)&Vs[kk * FA_STRIDE + ((2 * g + 1) ^ sw) * 4];
            o0[0] += pa * va.x; o0[1] += pa * va.y; o0[2] += pa * va.z; o0[3] += pa * va.w;
            o0[4] += pa * vb.x; o0[5] += pa * vb.y; o0[6] += pa * vb.z; o0[7] += pa * vb.w;
            o1[0] += pb * va.x; o1[1] += pb * va.y; o1[2] += pb * va.z; o1[3] += pb * va.w;
            o1[4] += pb * vb.x; o1[5] += pb * vb.y; o1[6] += pb * vb.z; o1[7] += pb * vb.w;
        }
        __syncwarp();
    }

    float inv0 = 1.f / l0, inv1 = 1.f / l1;
    size_t row0g = (size_t)(b * S + qc * 64 + r0);
    float* d0 = out + row0g * DM + h * 64 + g * 8;
    float* d1 = d0 + DM;
    *(float4*)d0       = make_float4(o0[0]*inv0, o0[1]*inv0, o0[2]*inv0, o0[3]*inv0);
    *(float4*)(d0 + 4) = make_float4(o0[4]*inv0, o0[5]*inv0, o0[6]*inv0, o0[7]*inv0);
    *(float4*)d1       = make_float4(o1[0]*inv1, o1[1]*inv1, o1[2]*inv1, o1[3]*inv1);
    *(float4*)(d1 + 4) = make_float4(o1[4]*inv1, o1[5]*inv1, o1[6]*inv1, o1[7]*inv1);
}

// ---------------- MoD: router scores ----------------
__global__ void score_kernel(float* __restrict__ scores, const float* __restrict__ x,
                             const float* __restrict__ r)
{
    __shared__ float red[8];
    int row = blockIdx.x, tid = threadIdx.x;
    const float* xr = x + (size_t)row * DM;
    float s = 0.f;
    #pragma unroll
    for (int i = 0; i < 4; i++) { int d = tid + i * 256; s = fmaf(xr[d], r[d], s); }
    s = blockSum(s, red);
    if (tid == 0) scores[row] = s;
}

// ---------------- MoD: exact top-128 descending (bitonic, tie = smaller idx) ----------------
__global__ void topk_sort_kernel(int* __restrict__ idx, const float* __restrict__ scores)
{
    int b = blockIdx.x, tid = threadIdx.x;
    __shared__ float s[TSEQ];
    __shared__ int   si[TSEQ];
    s[tid]  = scores[b * TSEQ + tid];
    si[tid] = tid;
    __syncthreads();
    for (int k = 2; k <= TSEQ; k <<= 1) {
        for (int j = k >> 1; j > 0; j >>= 1) {
            int ixj = tid ^ j;
            if (ixj > tid) {
                bool desc = ((tid & k) == 0);
                float s1 = s[tid], s2 = s[ixj];
                int   i1 = si[tid], i2 = si[ixj];
                bool firstBetter = (s1 > s2) || (s1 == s2 && i1 < i2);
                if (desc != firstBetter) {
                    s[tid] = s2; s[ixj] = s1;
                    si[tid] = i2; si[ixj] = i1;
                }
            }
            __syncthreads();
        }
    }
    if (tid < CAP) idx[b * CAP + tid] = si[tid];
}

__global__ void gather_kernel(float* __restrict__ xs, const float* __restrict__ x,
                              const int* __restrict__ idx)
{
    int row = blockIdx.x;
    int b = row >> 7;
    int src = b * TSEQ + idx[row];
    int tid = threadIdx.x;
    #pragma unroll
    for (int i = 0; i < 4; i++) {
        int d = tid + i * 256;
        xs[(size_t)row * DM + d] = x[(size_t)src * DM + d];
    }
}
__global__ void scatter_kernel(float* __restrict__ x, const float* __restrict__ xs,
                               const int* __restrict__ idx)
{
    int row = blockIdx.x;
    int b = row >> 7;
    int dst = b * TSEQ + idx[row];
    int tid = threadIdx.x;
    #pragma unroll
    for (int i = 0; i < 4; i++) {
        int d = tid + i * 256;
        x[(size_t)dst * DM + d] = xs[(size_t)row * DM + d];
    }
}

// ---------------- memory: top-8 + softmax + weighted value gather ----------------
__global__ void memtopk_kernel(float* __restrict__ outp, const float* __restrict__ sim,
                               const float* __restrict__ mem_values)
{
    int row = blockIdx.x, tid = threadIdx.x;
    __shared__ float sv[NSLOTS];
    __shared__ float av[NSLOTS];
    __shared__ int   ai[NSLOTS];
    __shared__ float wk[TOPK];
    __shared__ int   ik[TOPK];
    sv[tid] = sim[(size_t)row * NSLOTS + tid] * 0.03125f;
    __syncthreads();
    for (int k = 0; k < TOPK; k++) {
        av[tid] = sv[tid]; ai[tid] = tid;
        __syncthreads();
        for (int s = 64; s > 0; s >>= 1) {
            if (tid < s) {
                float v2 = av[tid + s]; int i2 = ai[tid + s];
                if (v2 > av[tid] || (v2 == av[tid] && i2 < ai[tid])) { av[tid] = v2; ai[tid] = i2; }
            }
            __syncthreads();
        }
        if (tid == 0) { wk[k] = av[0]; ik[k] = ai[0]; sv[ai[0]] = -INFINITY; }
        __syncthreads();
    }
    if (tid == 0) {
        float mx = wk[0], ssum = 0.f, e[TOPK];
        #pragma unroll
        for (int k = 0; k < TOPK; k++) { e[k] = expf(wk[k] - mx); ssum += e[k]; }
        #pragma unroll
        for (int k = 0; k < TOPK; k++) wk[k] = e[k] / ssum;
    }
    __syncthreads();
    #pragma unroll
    for (int i = 0; i < 8; i++) {
        int d = tid + i * 128;
        float o = 0.f;
        #pragma unroll
        for (int k = 0; k < TOPK; k++)
            o = fmaf(wk[k], mem_values[(size_t)ik[k] * DM + d], o);
        outp[(size_t)row * DM + d] = o;
    }
}

// ---------------- gate ----------------
__global__ void gate_kernel(float* __restrict__ x, const float* __restrict__ g1,
                            const float* __restrict__ gw2, const float* __restrict__ gb2,
                            const float* __restrict__ retr)
{
    __shared__ float red[8];
    int row = blockIdx.x, tid = threadIdx.x;
    float s = 0.f;
    for (int j = tid; j < 512; j += 256) {
        float v = g1[(size_t)row * 512 + j];
        s = fmaf(gelu_f(v), gw2[j], s);
    }
    s = blockSum(s, red);
    float gate = 1.f / (1.f + expf(-(s + gb2[0])));
    #pragma unroll
    for (int i = 0; i < 4; i++) {
        int d = tid + i * 256;
        size_t p = (size_t)row * DM + d;
        x[p] += gate * retr[p];
    }
}

// ---------------- host-side gemm dispatch (routes small grids to 64-row tile) ----------------
static void gemm(int ep, float* C, const float* A, const float* B,
                 int M, int N, int K, int lda, int ldb, int ldc,
                 const float* res = nullptr, int ldres = 0,
                 const float* bias = nullptr)
{
    int gx = (N + 127) / 128;
    int gy128 = (M + 127) / 128;
    if (gx * gy128 < 200) {
        dim3 grid(gx, (M + 63) / 64);
        switch (ep) {
        case EP_STORE:    tgemm64_abt<EP_STORE>   <<<grid,256>>>(C,A,B,M,N,K,lda,ldb,ldc,res,ldres,bias); break;
        case EP_ADD:      tgemm64_abt<EP_ADD>     <<<grid,256>>>(C,A,B,M,N,K,lda,ldb,ldc,res,ldres,bias); break;
        case EP_GELU:     tgemm64_abt<EP_GELU>    <<<grid,256>>>(C,A,B,M,N,K,lda,ldb,ldc,res,ldres,bias); break;
        case EP_ADD_BIAS: tgemm64_abt<EP_ADD_BIAS><<<grid,256>>>(C,A,B,M,N,K,lda,ldb,ldc,res,ldres,bias); break;
        case EP_SILU_MUL: tgemm64_abt<EP_SILU_MUL><<<grid,256>>>(C,A,B,M,N,K,lda,ldb,ldc,res,ldres,bias); break;
        }
    } else {
        dim3 grid(gx, gy128);
        switch (ep) {
        case EP_STORE:    tgemm_abt<EP_STORE>   <<<grid,256>>>(C,A,B,M,N,K,lda,ldb,ldc,res,ldres,bias); break;
        case EP_ADD:      tgemm_abt<EP_ADD>     <<<grid,256>>>(C,A,B,M,N,K,lda,ldb,ldc,res,ldres,bias); break;
        case EP_GELU:     tgemm_abt<EP_GELU>    <<<grid,256>>>(C,A,B,M,N,K,lda,ldb,ldc,res,ldres,bias); break;
        case EP_ADD_BIAS: tgemm_abt<EP_ADD_BIAS><<<grid,256>>>(C,A,B,M,N,K,lda,ldb,ldc,res,ldres,bias); break;
        case EP_SILU_MUL: tgemm_abt<EP_SILU_MUL><<<grid,256>>>(C,A,B,M,N,K,lda,ldb,ldc,res,ldres,bias); break;
        }
    }
}

extern "C" void kernel_launch(void* const* d_in, const int* in_sizes, int n_in,
                              void* d_out, int out_size)
{
    const int*   ids       = (const int*)  d_in[0];
    const float* embed     = (const float*)d_in[1];
    const float* pos       = (const float*)d_in[2];
    const float* n1        = (const float*)d_in[3];
    const float* qkvw      = (const float*)d_in[4];
    const float* outw      = (const float*)d_in[5];
    const float* n2        = (const float*)d_in[6];
    const float* w1        = (const float*)d_in[7];
    const float* w2        = (const float*)d_in[8];
    const float* w3        = (const float*)d_in[9];
    const float* router    = (const float*)d_in[10];
    const float* mem_keys  = (const float*)d_in[11];
    const float* mem_vals  = (const float*)d_in[12];
    const float* mem_q     = (const float*)d_in[13];
    const float* mem_out   = (const float*)d_in[14];
    const float* gate_w1   = (const float*)d_in[15];
    const float* gate_b1   = (const float*)d_in[16];
    const float* gate_w2   = (const float*)d_in[17];
    const float* gate_b2   = (const float*)d_in[18];
    const float* lat_norm  = (const float*)d_in[19];
    const float* lat_w1    = (const float*)d_in[20];
    const float* lat_w2    = (const float*)d_in[21];
    const float* fin_norm  = (const float*)d_in[22];
    const float* lm_head   = (const float*)d_in[23];
    float* out = (float*)d_out;

    float *x,*xn,*qkvb,*attnb,*ff1,*ff2,*retr,*retrp,*sim,*g1,*h1,*xs,*scores;
    int *idxb;
    cudaGetSymbolAddress((void**)&x,     g_x);
    cudaGetSymbolAddress((void**)&xn,    g_xn);
    cudaGetSymbolAddress((void**)&qkvb,  g_qkv);
    cudaGetSymbolAddress((void**)&attnb, g_attn);
    cudaGetSymbolAddress((void**)&ff1,   g_ff1);
    cudaGetSymbolAddress((void**)&ff2,   g_ff2);
    cudaGetSymbolAddress((void**)&retr,  g_retr);
    cudaGetSymbolAddress((void**)&retrp, g_retrp);
    cudaGetSymbolAddress((void**)&sim,   g_sim);
    cudaGetSymbolAddress((void**)&g1,    g_g1);
    cudaGetSymbolAddress((void**)&h1,    g_h1);
    cudaGetSymbolAddress((void**)&xs,    g_xs);
    cudaGetSymbolAddress((void**)&scores,g_scores);
    cudaGetSymbolAddress((void**)&idxb,  g_idx);

    cudaFuncSetAttribute(fattn_kernel, cudaFuncAttributeMaxDynamicSharedMemorySize, FA_SMEM);

    embed_kernel<<<NTOK, 256>>>(x, ids, embed, pos);

    auto run_block = [&](float* buf, int M, int S, int l) {
        const float* Wqkv = qkvw + (size_t)l * 3 * DM * DM;
        const float* Wout = outw + (size_t)l * DM * DM;
        const float* W1   = w1   + (size_t)l * DFF * DM;
        const float* W2   = w2   + (size_t)l * DFF * DM;
        const float* W3   = w3   + (size_t)l * DM * DFF;
        rms_kernel<<<M, 256>>>(xn, buf, n1 + (size_t)l * DM);
        gemm(EP_STORE, qkvb, xn, Wqkv, M, 3 * DM, DM, DM, DM, 3 * DM);
        fattn_kernel<<<dim3(S / 64, NHEAD, BATCH), 256, FA_SMEM>>>(qkvb, attnb, S);
        gemm(EP_ADD, buf, attnb, Wout, M, DM, DM, DM, DM, DM, buf, DM);
        rms_kernel<<<M, 256>>>(xn, buf, n2 + (size_t)l * DM);
        gemm(EP_STORE,    ff1, xn, W1, M, DFF, DM, DM, DM, DFF);
        gemm(EP_SILU_MUL, ff2, xn, W2, M, DFF, DM, DM, DM, DFF, ff1, DFF);
        gemm(EP_ADD,      buf, ff2, W3, M, DM, DFF, DFF, DFF, DM, buf, DM);
    };

    for (int l = 0; l < NLAYER; l++) {
        if (l & 1) {
            score_kernel<<<NTOK, 256>>>(scores, x, router + (size_t)l * DM);
            topk_sort_kernel<<<BATCH, TSEQ>>>(idxb, scores);
            gather_kernel<<<BATCH * CAP, 256>>>(xs, x, idxb);
            run_block(xs, BATCH * CAP, CAP, l);
            scatter_kernel<<<BATCH * CAP, 256>>>(x, xs, idxb);
        } else {
            run_block(x, NTOK, TSEQ, l);
        }
    }

    // kNN memory retrieval
    gemm(EP_STORE, xn,  x,  mem_q,    NTOK, DM,     DM, DM, DM, DM);
    gemm(EP_STORE, sim, xn, mem_keys, NTOK, NSLOTS, DM, DM, DM, NSLOTS);
    memtopk_kernel<<<NTOK, 128>>>(retrp, sim, mem_vals);
    gemm(EP_STORE, retr, retrp, mem_out, NTOK, DM, DM, DM, DM, DM);
    gemm(EP_STORE,    g1, x,    gate_w1,      NTOK, 512, DM, DM, 2 * DM, 512);
    gemm(EP_ADD_BIAS, g1, retr, gate_w1 + DM, NTOK, 512, DM, DM, 2 * DM, 512, g1, 512, gate_b1);
    gate_kernel<<<NTOK, 256>>>(x, g1, gate_w2, gate_b2, retr);

    // latent reasoning iterations
    for (int it = 0; it < 4; it++) {
        rms_kernel<<<NTOK, 256>>>(xn, x, lat_norm);
        gemm(EP_GELU, h1, xn, lat_w1, NTOK, 2 * DM, DM, DM, DM, 2 * DM);
        gemm(EP_ADD,  x,  h1, lat_w2, NTOK, DM, 2 * DM, 2 * DM, 2 * DM, DM, x, DM);
    }

    // final norm + LM head
    rms_kernel<<<NTOK, 256>>>(xn, x, fin_norm);
    gemm(EP_STORE, out, xn, lm_head, NTOK, 50257, DM, DM, DM, 50257);
}

// round 17
// speedup vs baseline: 2.8452x; 1.0742x over previous
#include <cuda_runtime.h>
#include <cuda_fp16.h>
#include <math.h>

// ---------------- problem constants ----------------
#define BATCH   2
#define TSEQ    1024
#define DM      1024
#define NHEAD   16
#define HD      64
#define NLAYER  12
#define DFF     2730
#define CAP     128
#define NSLOTS  128
#define TOPK    8
#define NTOK    (BATCH*TSEQ)      // 2048

// ---------------- scratch (device globals; no allocation allowed) ----------------
__device__ float g_x    [NTOK*DM];
__device__ float g_xn   [NTOK*DM];
__device__ float g_qkv  [NTOK*3*DM];
__device__ float g_attn [NTOK*DM];
__device__ float g_ff1  [NTOK*DFF];
__device__ float g_ff2  [NTOK*DFF];
__device__ float g_retr [NTOK*DM];
__device__ float g_retrp[NTOK*DM];
__device__ float g_sim  [NTOK*NSLOTS];
__device__ float g_g1   [NTOK*512];
__device__ float g_h1   [NTOK*2048];
__device__ float g_xs   [BATCH*CAP*DM];
__device__ float g_scores[NTOK];
__device__ int   g_idx  [BATCH*CAP];

// ---------------- helpers ----------------
__device__ __forceinline__ float warpSum(float v){
    #pragma unroll
    for (int o=16;o>0;o>>=1) v += __shfl_xor_sync(0xffffffffu, v, o);
    return v;
}
__device__ __forceinline__ float blockSum(float v, float* red){
    int lane = threadIdx.x & 31, w = threadIdx.x >> 5, nw = blockDim.x >> 5;
    v = warpSum(v);
    if (lane == 0) red[w] = v;
    __syncthreads();
    float r = (w == 0 && lane < nw) ? red[lane] : 0.f;
    if (w == 0) r = warpSum(r);
    if (threadIdx.x == 0) red[0] = r;
    __syncthreads();
    float out = red[0];
    __syncthreads();
    return out;
}
__device__ __forceinline__ float gelu_f(float v){
    return 0.5f * v * (1.f + erff(v * 0.70710678118654752f));
}
__device__ __forceinline__ float silu_f(float v){
    return v / (1.f + expf(-v));
}

// ---------------- fp16 hi/lo split + mma + ldmatrix ----------------
__device__ __forceinline__ void split2_f16(float x, float y, unsigned &hi2, unsigned &lo2){
    __half hx = __float2half_rn(x);
    __half hy = __float2half_rn(y);
    __half lx = __float2half_rn(x - __half2float(hx));
    __half ly = __float2half_rn(y - __half2float(hy));
    __half2 h; h.x = hx; h.y = hy;
    __half2 l; l.x = lx; l.y = ly;
    hi2 = *reinterpret_cast<unsigned*>(&h);
    lo2 = *reinterpret_cast<unsigned*>(&l);
}
__device__ __forceinline__ void mma16(float* c, const unsigned* a, const unsigned* b){
    asm volatile(
        "mma.sync.aligned.m16n8k16.row.col.f32.f16.f16.f32 "
        "{%0,%1,%2,%3}, {%4,%5,%6,%7}, {%8,%9}, {%0,%1,%2,%3};"
        : "+f"(c[0]), "+f"(c[1]), "+f"(c[2]), "+f"(c[3])
        : "r"(a[0]), "r"(a[1]), "r"(a[2]), "r"(a[3]), "r"(b[0]), "r"(b[1]));
}
__device__ __forceinline__ void ldm4(unsigned &r0, unsigned &r1, unsigned &r2, unsigned &r3,
                                     unsigned a){
    asm volatile("ldmatrix.sync.aligned.m8n8.x4.shared.b16 {%0,%1,%2,%3}, [%4];"
                 : "=r"(r0), "=r"(r1), "=r"(r2), "=r"(r3) : "r"(a));
}

// guarded float4 row load (handles unaligned ld and K tail)
__device__ __forceinline__ float4 ldg_row(const float* __restrict__ P, int ld, bool al4,
                                          int row, int gk, int RM, int K)
{
    float4 v = make_float4(0.f, 0.f, 0.f, 0.f);
    if (row < RM) {
        const float* p = P + (size_t)row * ld + gk;
        if (al4 && gk + 3 < K) v = *(const float4*)p;
        else {
            if (gk + 0 < K) v.x = p[0];
            if (gk + 1 < K) v.y = p[1];
            if (gk + 2 < K) v.z = p[2];
            if (gk + 3 < K) v.w = p[3];
        }
    }
    return v;
}

#define EP_STORE    0
#define EP_ADD      1
#define EP_GELU     2
#define EP_ADD_BIAS 3
#define EP_SILU_MUL 4

__device__ __forceinline__ float apply_ep(int EP, float v, const float* res, int ldres,
                                          const float* bias, int gm, int gn)
{
    if (EP == EP_ADD)           v += res[(size_t)gm * ldres + gn];
    else if (EP == EP_GELU)     v = gelu_f(v);
    else if (EP == EP_ADD_BIAS) v += res[(size_t)gm * ldres + gn] + bias[gn];
    else if (EP == EP_SILU_MUL) v *= silu_f(res[(size_t)gm * ldres + gn]);
    return v;
}

// ---------------- GEMM 128x128: fp16 hi/lo, TERMS=3 (full) or 2 (drop loA*hiB) ----------------
template<int EP, int TERMS>
__global__ __launch_bounds__(256, 2)
void tgemm_abt(float* __restrict__ C, const float* __restrict__ A,
               const float* __restrict__ B, int M, int N, int K,
               int lda, int ldb, int ldc,
               const float* __restrict__ res, int ldres,
               const float* __restrict__ bias)
{
    __shared__ unsigned Ah[128][20], Al[128][20], Bh[128][20], Bl[128][20];
    const int bm = blockIdx.y * 128, bn = blockIdx.x * 128;
    const int tid  = threadIdx.x;
    const int warp = tid >> 5, lane = tid & 31;
    const int wm = (warp & 1) * 64;
    const int wn = (warp >> 1) * 32;
    const int g  = lane >> 2, tg = lane & 3;
    const bool a4 = ((lda & 3) == 0);
    const bool b4 = ((ldb & 3) == 0);
    const int frow = tid >> 1;
    const int kcb  = (tid & 1) * 8;
    const int kgb  = (tid & 1) * 16;

    const int rowA = wm + ((lane >> 3) & 1) * 8 + (lane & 7);
    const int kcA  = (lane >> 4) * 4;
    const int rowB = wn + ((lane >> 4) & 1) * 8 + (lane & 7);
    const int kcB  = ((lane >> 3) & 1) * 4;
    const unsigned baseAh = (unsigned)__cvta_generic_to_shared(&Ah[0][0]);
    const unsigned baseAl = (unsigned)__cvta_generic_to_shared(&Al[0][0]);
    const unsigned baseBh = (unsigned)__cvta_generic_to_shared(&Bh[0][0]);
    const unsigned baseBl = (unsigned)__cvta_generic_to_shared(&Bl[0][0]);

    float acc[4][4][4];
    #pragma unroll
    for (int mi = 0; mi < 4; mi++)
        #pragma unroll
        for (int ni = 0; ni < 4; ni++)
            #pragma unroll
            for (int cc = 0; cc < 4; cc++) acc[mi][ni][cc] = 0.f;

    unsigned sAh[8], sAl[8], sBh[8], sBl[8];
    #pragma unroll
    for (int q = 0; q < 4; q++) {
        float4 a = ldg_row(A, lda, a4, bm + frow, kgb + q * 4, M, K);
        split2_f16(a.x, a.y, sAh[q*2],   sAl[q*2]);
        split2_f16(a.z, a.w, sAh[q*2+1], sAl[q*2+1]);
        float4 b = ldg_row(B, ldb, b4, bn + frow, kgb + q * 4, N, K);
        split2_f16(b.x, b.y, sBh[q*2],   sBl[q*2]);
        split2_f16(b.z, b.w, sBh[q*2+1], sBl[q*2+1]);
    }

    for (int k0 = 0; k0 < K; k0 += 32) {
        #pragma unroll
        for (int j = 0; j < 8; j++) {
            Ah[frow][kcb + j] = sAh[j];
            Bh[frow][kcb + j] = sBh[j];
            Bl[frow][kcb + j] = sBl[j];
            if (TERMS == 3) Al[frow][kcb + j] = sAl[j];
        }
        __syncthreads();

        if (k0 + 32 < K) {
            #pragma unroll
            for (int q = 0; q < 4; q++) {
                float4 a = ldg_row(A, lda, a4, bm + frow, k0 + 32 + kgb + q * 4, M, K);
                split2_f16(a.x, a.y, sAh[q*2],   sAl[q*2]);
                split2_f16(a.z, a.w, sAh[q*2+1], sAl[q*2+1]);
                float4 b = ldg_row(B, ldb, b4, bn + frow, k0 + 32 + kgb + q * 4, N, K);
                split2_f16(b.x, b.y, sBh[q*2],   sBl[q*2]);
                split2_f16(b.z, b.w, sBh[q*2+1], sBl[q*2+1]);
            }
        }

        #pragma unroll
        for (int ks = 0; ks < 2; ks++) {
            const int c0 = ks * 8;
            unsigned bhiF[4][2], bloF[4][2];
            #pragma unroll
            for (int p = 0; p < 2; p++) {
                unsigned off = (unsigned)(((rowB + p * 16) * 20 + c0 + kcB) * 4);
                ldm4(bhiF[2*p][0], bhiF[2*p][1], bhiF[2*p+1][0], bhiF[2*p+1][1], baseBh + off);
                ldm4(bloF[2*p][0], bloF[2*p][1], bloF[2*p+1][0], bloF[2*p+1][1], baseBl + off);
            }
            #pragma unroll
            for (int mi = 0; mi < 4; mi++) {
                unsigned off = (unsigned)(((rowA + mi * 16) * 20 + c0 + kcA) * 4);
                unsigned ah[4], al[4];
                ldm4(ah[0], ah[1], ah[2], ah[3], baseAh + off);
                if (TERMS == 3) ldm4(al[0], al[1], al[2], al[3], baseAl + off);
                #pragma unroll
                for (int ni = 0; ni < 4; ni++) mma16(acc[mi][ni], ah, bhiF[ni]);
                #pragma unroll
                for (int ni = 0; ni < 4; ni++) mma16(acc[mi][ni], ah, bloF[ni]);
                if (TERMS == 3) {
                    #pragma unroll
                    for (int ni = 0; ni < 4; ni++) mma16(acc[mi][ni], al, bhiF[ni]);
                }
            }
        }
        __syncthreads();
    }

    #pragma unroll
    for (int mi = 0; mi < 4; mi++) {
        int row0 = bm + wm + mi * 16 + g;
        #pragma unroll
        for (int ni = 0; ni < 4; ni++) {
            int col0 = bn + wn + ni * 8 + tg * 2;
            #pragma unroll
            for (int cc = 0; cc < 4; cc++) {
                int gm = row0 + (cc >> 1) * 8;
                int gn = col0 + (cc & 1);
                if (gm < M && gn < N)
                    C[(size_t)gm * ldc + gn] = apply_ep(EP, acc[mi][ni][cc], res, ldres, bias, gm, gn);
            }
        }
    }
}

// ---------------- GEMM 64x128: small-grid variant ----------------
template<int EP, int TERMS>
__global__ __launch_bounds__(256)
void tgemm64_abt(float* __restrict__ C, const float* __restrict__ A,
                 const float* __restrict__ B, int M, int N, int K,
                 int lda, int ldb, int ldc,
                 const float* __restrict__ res, int ldres,
                 const float* __restrict__ bias)
{
    __shared__ unsigned Ah[64][20], Al[64][20], Bh[128][20], Bl[128][20];
    const int bm = blockIdx.y * 64, bn = blockIdx.x * 128;
    const int tid  = threadIdx.x;
    const int warp = tid >> 5, lane = tid & 31;
    const int wm = (warp & 1) * 32;
    const int wn = (warp >> 1) * 32;
    const int g  = lane >> 2, tg = lane & 3;
    const bool a4 = ((lda & 3) == 0);
    const bool b4 = ((ldb & 3) == 0);

    const int rowA = wm + ((lane >> 3) & 1) * 8 + (lane & 7);
    const int kcA  = (lane >> 4) * 4;
    const int rowB = wn + ((lane >> 4) & 1) * 8 + (lane & 7);
    const int kcB  = ((lane >> 3) & 1) * 4;
    const unsigned baseAh = (unsigned)__cvta_generic_to_shared(&Ah[0][0]);
    const unsigned baseAl = (unsigned)__cvta_generic_to_shared(&Al[0][0]);
    const unsigned baseBh = (unsigned)__cvta_generic_to_shared(&Bh[0][0]);
    const unsigned baseBl = (unsigned)__cvta_generic_to_shared(&Bl[0][0]);

    float acc[2][4][4];
    #pragma unroll
    for (int mi = 0; mi < 2; mi++)
        #pragma unroll
        for (int ni = 0; ni < 4; ni++)
            #pragma unroll
            for (int cc = 0; cc < 4; cc++) acc[mi][ni][cc] = 0.f;

    for (int k0 = 0; k0 < K; k0 += 32) {
        #pragma unroll
        for (int s = 0; s < 2; s++) {
            int e = tid + s * 256;
            int row = e >> 3, q = e & 7;
            float4 a = ldg_row(A, lda, a4, bm + row, k0 + q * 4, M, K);
            unsigned h0, l0, h1, l1;
            split2_f16(a.x, a.y, h0, l0);
            split2_f16(a.z, a.w, h1, l1);
            Ah[row][q*2] = h0; Ah[row][q*2+1] = h1;
            if (TERMS == 3) { Al[row][q*2] = l0; Al[row][q*2+1] = l1; }
        }
        #pragma unroll
        for (int s = 0; s < 4; s++) {
            int e = tid + s * 256;
            int row = e >> 3, q = e & 7;
            float4 b = ldg_row(B, ldb, b4, bn + row, k0 + q * 4, N, K);
            unsigned h0, l0, h1, l1;
            split2_f16(b.x, b.y, h0, l0);
            split2_f16(b.z, b.w, h1, l1);
            Bh[row][q*2] = h0; Bh[row][q*2+1] = h1;
            Bl[row][q*2] = l0; Bl[row][q*2+1] = l1;
        }
        __syncthreads();

        #pragma unroll
        for (int ks = 0; ks < 2; ks++) {
            const int c0 = ks * 8;
            unsigned bhiF[4][2], bloF[4][2];
            #pragma unroll
            for (int p = 0; p < 2; p++) {
                unsigned off = (unsigned)(((rowB + p * 16) * 20 + c0 + kcB) * 4);
                ldm4(bhiF[2*p][0], bhiF[2*p][1], bhiF[2*p+1][0], bhiF[2*p+1][1], baseBh + off);
                ldm4(bloF[2*p][0], bloF[2*p][1], bloF[2*p+1][0], bloF[2*p+1][1], baseBl + off);
            }
            #pragma unroll
            for (int mi = 0; mi < 2; mi++) {
                unsigned off = (unsigned)(((rowA + mi * 16) * 20 + c0 + kcA) * 4);
                unsigned ah[4], al[4];
                ldm4(ah[0], ah[1], ah[2], ah[3], baseAh + off);
                if (TERMS == 3) ldm4(al[0], al[1], al[2], al[3], baseAl + off);
                #pragma unroll
                for (int ni = 0; ni < 4; ni++) mma16(acc[mi][ni], ah, bhiF[ni]);
                #pragma unroll
                for (int ni = 0; ni < 4; ni++) mma16(acc[mi][ni], ah, bloF[ni]);
                if (TERMS == 3) {
                    #pragma unroll
                    for (int ni = 0; ni < 4; ni++) mma16(acc[mi][ni], al, bhiF[ni]);
                }
            }
        }
        __syncthreads();
    }

    #pragma unroll
    for (int mi = 0; mi < 2; mi++) {
        int row0 = bm + wm + mi * 16 + g;
        #pragma unroll
        for (int ni = 0; ni < 4; ni++) {
            int col0 = bn + wn + ni * 8 + tg * 2;
            #pragma unroll
            for (int cc = 0; cc < 4; cc++) {
                int gm = row0 + (cc >> 1) * 8;
                int gn = col0 + (cc & 1);
                if (gm < M && gn < N)
                    C[(size_t)gm * ldc + gn] = apply_ep(EP, acc[mi][ni][cc], res, ldres, bias, gm, gn);
            }
        }
    }
}

// ---------------- embed + positional ----------------
__global__ void embed_kernel(float* __restrict__ x, const int* __restrict__ ids,
                             const float* __restrict__ emb, const float* __restrict__ pos)
{
    int row = blockIdx.x;
    int t   = row & (TSEQ - 1);
    int id  = ids[row];
    int tid = threadIdx.x;
    #pragma unroll
    for (int i = 0; i < 4; i++) {
        int d = tid + i * 256;
        x[(size_t)row * DM + d] = emb[(size_t)id * DM + d] + pos[(size_t)t * DM + d];
    }
}

// ---------------- rmsnorm ----------------
__global__ void rms_kernel(float* __restrict__ y, const float* __restrict__ x,
                           const float* __restrict__ w)
{
    __shared__ float red[8];
    int row = blockIdx.x, tid = threadIdx.x;
    const float* xr = x + (size_t)row * DM;
    float s = 0.f;
    #pragma unroll
    for (int i = 0; i < 4; i++) { float v = xr[tid + i * 256]; s = fmaf(v, v, s); }
    s = blockSum(s, red);
    float r = rsqrtf(s * (1.f / DM) + 1e-6f);
    #pragma unroll
    for (int i = 0; i < 4; i++) {
        int d = tid + i * 256;
        y[(size_t)row * DM + d] = xr[d] * r * w[d];
    }
}

// ---------------- flash attention ----------------
#define FA_STRIDE 68
#define FA_SMEM   (4 * 64 * FA_STRIDE * 4)

__global__ __launch_bounds__(256)
void fattn_kernel(const float* __restrict__ qkv, float* __restrict__ out, int S)
{
    extern __shared__ float fsm[];
    float* Qs = fsm;
    float* Ks = fsm + 64 * FA_STRIDE;
    float* Vs = fsm + 2 * 64 * FA_STRIDE;
    float* Ps = fsm + 3 * 64 * FA_STRIDE;
    const int qc = blockIdx.x, h = blockIdx.y, b = blockIdx.z;
    const int tid = threadIdx.x, w = tid >> 5, lane = tid & 31;
    const int pair = lane & 3, g = lane >> 2;
    const int r0 = w * 8 + pair * 2;
    const float* base = qkv + (size_t)b * S * 3072;

    {
        int row = tid >> 2, c0 = (tid & 3) * 16;
        const float* src = base + (size_t)(qc * 64 + row) * 3072 + h * 64 + c0;
        #pragma unroll
        for (int q = 0; q < 4; q++)
            *(float4*)&Qs[row * FA_STRIDE + c0 + q * 4] = *(const float4*)(src + q * 4);
    }

    float o0[8], o1[8];
    #pragma unroll
    for (int j = 0; j < 8; j++) { o0[j] = 0.f; o1[j] = 0.f; }
    float m0 = -1e30f, m1 = -1e30f, l0 = 0.f, l1 = 0.f;

    for (int kt = 0; kt <= qc; kt++) {
        __syncthreads();
        {
            int row = tid >> 2, c0 = (tid & 3) * 16;
            const float* ksrc = base + (size_t)(kt * 64 + row) * 3072 + 1024 + h * 64 + c0;
            const float* vsrc = ksrc + 1024;
            int sw = (row >> 3) & 7;
            #pragma unroll
            for (int q = 0; q < 4; q++) {
                int d4 = (c0 >> 2) + q;
                int cc = d4 ^ sw;
                *(float4*)&Ks[row * FA_STRIDE + cc * 4] = *(const float4*)(ksrc + q * 4);
                *(float4*)&Vs[row * FA_STRIDE + cc * 4] = *(const float4*)(vsrc + q * 4);
            }
        }
        __syncthreads();

        float s0[8], s1[8];
        #pragma unroll
        for (int j = 0; j < 8; j++) { s0[j] = 0.f; s1[j] = 0.f; }
        #pragma unroll 4
        for (int d4 = 0; d4 < 16; d4++) {
            float4 q0 = *(float4*)&Qs[r0 * FA_STRIDE + d4 * 4];
            float4 q1 = *(float4*)&Qs[(r0 + 1) * FA_STRIDE + d4 * 4];
            #pragma unroll
            for (int j = 0; j < 8; j++) {
                float4 kv = *(float4*)&Ks[(g * 8 + j) * FA_STRIDE + (d4 ^ g) * 4];
                s0[j] += q0.x*kv.x + q0.y*kv.y + q0.z*kv.z + q0.w*kv.w;
                s1[j] += q1.x*kv.x + q1.y*kv.y + q1.z*kv.z + q1.w*kv.w;
            }
        }
        int qg0 = qc * 64 + r0;
        #pragma unroll
        for (int j = 0; j < 8; j++) {
            s0[j] *= 0.125f; s1[j] *= 0.125f;
            if (kt == qc) {
                int kg = kt * 64 + g * 8 + j;
                if (kg > qg0)     s0[j] = -1e30f;
                if (kg > qg0 + 1) s1[j] = -1e30f;
            }
        }
        float mx0 = s0[0], mx1 = s1[0];
        #pragma unroll
        for (int j = 1; j < 8; j++) { mx0 = fmaxf(mx0, s0[j]); mx1 = fmaxf(mx1, s1[j]); }
        #pragma unroll
        for (int off = 4; off <= 16; off <<= 1) {
            mx0 = fmaxf(mx0, __shfl_xor_sync(0xffffffffu, mx0, off));
            mx1 = fmaxf(mx1, __shfl_xor_sync(0xffffffffu, mx1, off));
        }
        float mn0 = fmaxf(m0, mx0), mn1 = fmaxf(m1, mx1);
        float cor0 = __expf(m0 - mn0), cor1 = __expf(m1 - mn1);
        m0 = mn0; m1 = mn1;
        float ls0 = 0.f, ls1 = 0.f;
        #pragma unroll
        for (int j = 0; j < 8; j++) {
            s0[j] = __expf(s0[j] - mn0);
            s1[j] = __expf(s1[j] - mn1);
            ls0 += s0[j]; ls1 += s1[j];
        }
        #pragma unroll
        for (int off = 4; off <= 16; off <<= 1) {
            ls0 += __shfl_xor_sync(0xffffffffu, ls0, off);
            ls1 += __shfl_xor_sync(0xffffffffu, ls1, off);
        }
        l0 = l0 * cor0 + ls0;
        l1 = l1 * cor1 + ls1;
        #pragma unroll
        for (int j = 0; j < 8; j++) { o0[j] *= cor0; o1[j] *= cor1; }
        *(float4*)&Ps[r0 * FA_STRIDE + g * 8]           = make_float4(s0[0], s0[1], s0[2], s0[3]);
        *(float4*)&Ps[r0 * FA_STRIDE + g * 8 + 4]       = make_float4(s0[4], s0[5], s0[6], s0[7]);
        *(float4*)&Ps[(r0 + 1) * FA_STRIDE + g * 8]     = make_float4(s1[0], s1[1], s1[2], s1[3]);
        *(float4*)&Ps[(r0 + 1) * FA_STRIDE + g * 8 + 4] = make_float4(s1[4], s1[5], s1[6], s1[7]);
        __syncwarp();
        #pragma unroll 4
        for (int kk = 0; kk < 64; kk++) {
            float pa = Ps[r0 * FA_STRIDE + kk];
            float pb = Ps[(r0 + 1) * FA_STRIDE + kk];
            int sw = kk >> 3;
            float4 va = *(float4*)&Vs[kk * FA_STRIDE + ((2 * g) ^ sw) * 4];
            float4 vb = *(float4*)&Vs[kk * FA_STRIDE + ((2 * g + 1) ^ sw) * 4];
            o0[0] += pa * va.x; o0[1] += pa * va.y; o0[2] += pa * va.z; o0[3] += pa * va.w;
            o0[4] += pa * vb.x; o0[5] += pa * vb.y; o0[6] += pa * vb.z; o0[7] += pa * vb.w;
            o1[0] += pb * va.x; o1[1] += pb * va.y; o1[2] += pb * va.z; o1[3] += pb * va.w;
            o1[4] += pb * vb.x; o1[5] += pb * vb.y; o1[6] += pb * vb.z; o1[7] += pb * vb.w;
        }
        __syncwarp();
    }

    float inv0 = 1.f / l0, inv1 = 1.f / l1;
    size_t row0g = (size_t)(b * S + qc * 64 + r0);
    float* d0 = out + row0g * DM + h * 64 + g * 8;
    float* d1 = d0 + DM;
    *(float4*)d0       = make_float4(o0[0]*inv0, o0[1]*inv0, o0[2]*inv0, o0[3]*inv0);
    *(float4*)(d0 + 4) = make_float4(o0[4]*inv0, o0[5]*inv0, o0[6]*inv0, o0[7]*inv0);
    *(float4*)d1       = make_float4(o1[0]*inv1, o1[1]*inv1, o1[2]*inv1, o1[3]*inv1);
    *(float4*)(d1 + 4) = make_float4(o1[4]*inv1, o1[5]*inv1, o1[6]*inv1, o1[7]*inv1);
}

// ---------------- MoD: router scores ----------------
__global__ void score_kernel(float* __restrict__ scores, const float* __restrict__ x,
                             const float* __restrict__ r)
{
    __shared__ float red[8];
    int row = blockIdx.x, tid = threadIdx.x;
    const float* xr = x + (size_t)row * DM;
    float s = 0.f;
    #pragma unroll
    for (int i = 0; i < 4; i++) { int d = tid + i * 256; s = fmaf(xr[d], r[d], s); }
    s = blockSum(s, red);
    if (tid == 0) scores[row] = s;
}

// ---------------- MoD: exact top-128 descending (bitonic, tie = smaller idx) ----------------
__global__ void topk_sort_kernel(int* __restrict__ idx, const float* __restrict__ scores)
{
    int b = blockIdx.x, tid = threadIdx.x;
    __shared__ float s[TSEQ];
    __shared__ int   si[TSEQ];
    s[tid]  = scores[b * TSEQ + tid];
    si[tid] = tid;
    __syncthreads();
    for (int k = 2; k <= TSEQ; k <<= 1) {
        for (int j = k >> 1; j > 0; j >>= 1) {
            int ixj = tid ^ j;
            if (ixj > tid) {
                bool desc = ((tid & k) == 0);
                float s1 = s[tid], s2 = s[ixj];
                int   i1 = si[tid], i2 = si[ixj];
                bool firstBetter = (s1 > s2) || (s1 == s2 && i1 < i2);
                if (desc != firstBetter) {
                    s[tid] = s2; s[ixj] = s1;
                    si[tid] = i2; si[ixj] = i1;
                }
            }
            __syncthreads();
        }
    }
    if (tid < CAP) idx[b * CAP + tid] = si[tid];
}

__global__ void gather_kernel(float* __restrict__ xs, const float* __restrict__ x,
                              const int* __restrict__ idx)
{
    int row = blockIdx.x;
    int b = row >> 7;
    int src = b * TSEQ + idx[row];
    int tid = threadIdx.x;
    #pragma unroll
    for (int i = 0; i < 4; i++) {
        int d = tid + i * 256;
        xs[(size_t)row * DM + d] = x[(size_t)src * DM + d];
    }
}
__global__ void scatter_kernel(float* __restrict__ x, const float* __restrict__ xs,
                               const int* __restrict__ idx)
{
    int row = blockIdx.x;
    int b = row >> 7;
    int dst = b * TSEQ + idx[row];
    int tid = threadIdx.x;
    #pragma unroll
    for (int i = 0; i < 4; i++) {
        int d = tid + i * 256;
        x[(size_t)dst * DM + d] = xs[(size_t)row * DM + d];
    }
}

// ---------------- memory: top-8 + softmax + weighted value gather ----------------
__global__ void memtopk_kernel(float* __restrict__ outp, const float* __restrict__ sim,
                               const float* __restrict__ mem_values)
{
    int row = blockIdx.x, tid = threadIdx.x;
    __shared__ float sv[NSLOTS];
    __shared__ float av[NSLOTS];
    __shared__ int   ai[NSLOTS];
    __shared__ float wk[TOPK];
    __shared__ int   ik[TOPK];
    sv[tid] = sim[(size_t)row * NSLOTS + tid] * 0.03125f;
    __syncthreads();
    for (int k = 0; k < TOPK; k++) {
        av[tid] = sv[tid]; ai[tid] = tid;
        __syncthreads();
        for (int s = 64; s > 0; s >>= 1) {
            if (tid < s) {
                float v2 = av[tid + s]; int i2 = ai[tid + s];
                if (v2 > av[tid] || (v2 == av[tid] && i2 < ai[tid])) { av[tid] = v2; ai[tid] = i2; }
            }
            __syncthreads();
        }
        if (tid == 0) { wk[k] = av[0]; ik[k] = ai[0]; sv[ai[0]] = -INFINITY; }
        __syncthreads();
    }
    if (tid == 0) {
        float mx = wk[0], ssum = 0.f, e[TOPK];
        #pragma unroll
        for (int k = 0; k < TOPK; k++) { e[k] = expf(wk[k] - mx); ssum += e[k]; }
        #pragma unroll
        for (int k = 0; k < TOPK; k++) wk[k] = e[k] / ssum;
    }
    __syncthreads();
    #pragma unroll
    for (int i = 0; i < 8; i++) {
        int d = tid + i * 128;
        float o = 0.f;
        #pragma unroll
        for (int k = 0; k < TOPK; k++)
            o = fmaf(wk[k], mem_values[(size_t)ik[k] * DM + d], o);
        outp[(size_t)row * DM + d] = o;
    }
}

// ---------------- gate ----------------
__global__ void gate_kernel(float* __restrict__ x, const float* __restrict__ g1,
                            const float* __restrict__ gw2, const float* __restrict__ gb2,
                            const float* __restrict__ retr)
{
    __shared__ float red[8];
    int row = blockIdx.x, tid = threadIdx.x;
    float s = 0.f;
    for (int j = tid; j < 512; j += 256) {
        float v = g1[(size_t)row * 512 + j];
        s = fmaf(gelu_f(v), gw2[j], s);
    }
    s = blockSum(s, red);
    float gate = 1.f / (1.f + expf(-(s + gb2[0])));
    #pragma unroll
    for (int i = 0; i < 4; i++) {
        int d = tid + i * 256;
        size_t p = (size_t)row * DM + d;
        x[p] += gate * retr[p];
    }
}

// ---------------- host-side gemm dispatch ----------------
static void gemm(int ep, int terms, float* C, const float* A, const float* B,
                 int M, int N, int K, int lda, int ldb, int ldc,
                 const float* res = nullptr, int ldres = 0,
                 const float* bias = nullptr)
{
    int gx = (N + 127) / 128;
    int gy128 = (M + 127) / 128;
    #define EP_SWITCH(KER, T, GRID) \
        switch (ep) { \
        case EP_STORE:    KER<EP_STORE,T>   <<<GRID,256>>>(C,A,B,M,N,K,lda,ldb,ldc,res,ldres,bias); break; \
        case EP_ADD:      KER<EP_ADD,T>     <<<GRID,256>>>(C,A,B,M,N,K,lda,ldb,ldc,res,ldres,bias); break; \
        case EP_GELU:     KER<EP_GELU,T>    <<<GRID,256>>>(C,A,B,M,N,K,lda,ldb,ldc,res,ldres,bias); break; \
        case EP_ADD_BIAS: KER<EP_ADD_BIAS,T><<<GRID,256>>>(C,A,B,M,N,K,lda,ldb,ldc,res,ldres,bias); break; \
        case EP_SILU_MUL: KER<EP_SILU_MUL,T><<<GRID,256>>>(C,A,B,M,N,K,lda,ldb,ldc,res,ldres,bias); break; }
    if (gx * gy128 < 200) {
        dim3 grid(gx, (M + 63) / 64);
        if (terms == 3) { EP_SWITCH(tgemm64_abt, 3, grid) } else { EP_SWITCH(tgemm64_abt, 2, grid) }
    } else {
        dim3 grid(gx, gy128);
        if (terms == 3) { EP_SWITCH(tgemm_abt, 3, grid) } else { EP_SWITCH(tgemm_abt, 2, grid) }
    }
    #undef EP_SWITCH
}

extern "C" void kernel_launch(void* const* d_in, const int* in_sizes, int n_in,
                              void* d_out, int out_size)
{
    const int*   ids       = (const int*)  d_in[0];
    const float* embed     = (const float*)d_in[1];
    const float* pos       = (const float*)d_in[2];
    const float* n1        = (const float*)d_in[3];
    const float* qkvw      = (const float*)d_in[4];
    const float* outw      = (const float*)d_in[5];
    const float* n2        = (const float*)d_in[6];
    const float* w1        = (const float*)d_in[7];
    const float* w2        = (const float*)d_in[8];
    const float* w3        = (const float*)d_in[9];
    const float* router    = (const float*)d_in[10];
    const float* mem_keys  = (const float*)d_in[11];
    const float* mem_vals  = (const float*)d_in[12];
    const float* mem_q     = (const float*)d_in[13];
    const float* mem_out   = (const float*)d_in[14];
    const float* gate_w1   = (const float*)d_in[15];
    const float* gate_b1   = (const float*)d_in[16];
    const float* gate_w2   = (const float*)d_in[17];
    const float* gate_b2   = (const float*)d_in[18];
    const float* lat_norm  = (const float*)d_in[19];
    const float* lat_w1    = (const float*)d_in[20];
    const float* lat_w2    = (const float*)d_in[21];
    const float* fin_norm  = (const float*)d_in[22];
    const float* lm_head   = (const float*)d_in[23];
    float* out = (float*)d_out;

    float *x,*xn,*qkvb,*attnb,*ff1,*ff2,*retr,*retrp,*sim,*g1,*h1,*xs,*scores;
    int *idxb;
    cudaGetSymbolAddress((void**)&x,     g_x);
    cudaGetSymbolAddress((void**)&xn,    g_xn);
    cudaGetSymbolAddress((void**)&qkvb,  g_qkv);
    cudaGetSymbolAddress((void**)&attnb, g_attn);
    cudaGetSymbolAddress((void**)&ff1,   g_ff1);
    cudaGetSymbolAddress((void**)&ff2,   g_ff2);
    cudaGetSymbolAddress((void**)&retr,  g_retr);
    cudaGetSymbolAddress((void**)&retrp, g_retrp);
    cudaGetSymbolAddress((void**)&sim,   g_sim);
    cudaGetSymbolAddress((void**)&g1,    g_g1);
    cudaGetSymbolAddress((void**)&h1,    g_h1);
    cudaGetSymbolAddress((void**)&xs,    g_xs);
    cudaGetSymbolAddress((void**)&scores,g_scores);
    cudaGetSymbolAddress((void**)&idxb,  g_idx);

    cudaFuncSetAttribute(fattn_kernel, cudaFuncAttributeMaxDynamicSharedMemorySize, FA_SMEM);

    embed_kernel<<<NTOK, 256>>>(x, ids, embed, pos);

    // 3-term everywhere a discrete selection (MoD routing / memory top-8) is downstream.
    auto run_block = [&](float* buf, int M, int S, int l) {
        const float* Wqkv = qkvw + (size_t)l * 3 * DM * DM;
        const float* Wout = outw + (size_t)l * DM * DM;
        const float* W1   = w1   + (size_t)l * DFF * DM;
        const float* W2   = w2   + (size_t)l * DFF * DM;
        const float* W3   = w3   + (size_t)l * DM * DFF;
        rms_kernel<<<M, 256>>>(xn, buf, n1 + (size_t)l * DM);
        gemm(EP_STORE, 3, qkvb, xn, Wqkv, M, 3 * DM, DM, DM, DM, 3 * DM);
        fattn_kernel<<<dim3(S / 64, NHEAD, BATCH), 256, FA_SMEM>>>(qkvb, attnb, S);
        gemm(EP_ADD, 3, buf, attnb, Wout, M, DM, DM, DM, DM, DM, buf, DM);
        rms_kernel<<<M, 256>>>(xn, buf, n2 + (size_t)l * DM);
        gemm(EP_STORE,    3, ff1, xn, W1, M, DFF, DM, DM, DM, DFF);
        gemm(EP_SILU_MUL, 3, ff2, xn, W2, M, DFF, DM, DM, DM, DFF, ff1, DFF);
        gemm(EP_ADD,      3, buf, ff2, W3, M, DM, DFF, DFF, DFF, DM, buf, DM);
    };

    for (int l = 0; l < NLAYER; l++) {
        if (l & 1) {
            score_kernel<<<NTOK, 256>>>(scores, x, router + (size_t)l * DM);
            topk_sort_kernel<<<BATCH, TSEQ>>>(idxb, scores);
            gather_kernel<<<BATCH * CAP, 256>>>(xs, x, idxb);
            run_block(xs, BATCH * CAP, CAP, l);
            scatter_kernel<<<BATCH * CAP, 256>>>(x, xs, idxb);
        } else {
            run_block(x, NTOK, TSEQ, l);
        }
    }

    // kNN memory retrieval (q and sim feed the top-8 selection: 3-term)
    gemm(EP_STORE, 3, xn,  x,  mem_q,    NTOK, DM,     DM, DM, DM, DM);
    gemm(EP_STORE, 3, sim, xn, mem_keys, NTOK, NSLOTS, DM, DM, DM, NSLOTS);
    memtopk_kernel<<<NTOK, 128>>>(retrp, sim, mem_vals);
    // all selections done -> 2-term from here on
    gemm(EP_STORE, 2, retr, retrp, mem_out, NTOK, DM, DM, DM, DM, DM);
    gemm(EP_STORE,    2, g1, x,    gate_w1,      NTOK, 512, DM, DM, 2 * DM, 512);
    gemm(EP_ADD_BIAS, 2, g1, retr, gate_w1 + DM, NTOK, 512, DM, DM, 2 * DM, 512, g1, 512, gate_b1);
    gate_kernel<<<NTOK, 256>>>(x, g1, gate_w2, gate_b2, retr);

    // latent reasoning iterations (2-term)
    for (int it = 0; it < 4; it++) {
        rms_kernel<<<NTOK, 256>>>(xn, x, lat_norm);
        gemm(EP_GELU, 2, h1, xn, lat_w1, NTOK, 2 * DM, DM, DM, DM, 2 * DM);
        gemm(EP_ADD,  2, x,  h1, lat_w2, NTOK, DM, 2 * DM, 2 * DM, 2 * DM, DM, x, DM);
    }

    // final norm + LM head (2-term)
    rms_kernel<<<NTOK, 256>>>(xn, x, fin_norm);
    gemm(EP_STORE, 2, out, xn, lm_head, NTOK, 50257, DM, DM, DM, 50257);
}